// round 1
// baseline (speedup 1.0000x reference)
#include <cuda_runtime.h>
#include <math.h>

// Problem constants
#define L_ 2
#define B_ 2
#define T_ 2048
#define C_ 1024
#define H_ 16
#define D_ 64
#define F_ 4096
#define WIN_ 256
#define M_ (B_*T_)   // 4096 tokens
#define NEG_ (-1e9f)

// ---------------------------------------------------------------------------
// Scratch (static device globals; no allocation allowed)
// ---------------------------------------------------------------------------
__device__ float g_h  [M_*C_];
__device__ float g_h2 [M_*C_];
__device__ float g_qkv[M_*3*C_];
__device__ float g_o  [M_*C_];
__device__ float g_attn[M_*C_];
__device__ float g_f1 [M_*F_];
__device__ float g_f2 [M_*F_];
__device__ float g_ret[B_*C_];

// ---------------------------------------------------------------------------
// RMSNorm: out[token][c] = x*rsqrt(mean(x^2)+eps)*g[c]
// ---------------------------------------------------------------------------
__global__ __launch_bounds__(128) void rmsnorm_kernel(
    const float* __restrict__ x, const float* __restrict__ g, float* __restrict__ out)
{
    __shared__ float red[128];
    __shared__ float rinv;
    const int tkn = blockIdx.x, tid = threadIdx.x;
    const float* row = x + (size_t)tkn * C_;
    float ss = 0.f;
    #pragma unroll
    for (int c = tid; c < C_; c += 128) { float v = row[c]; ss += v * v; }
    red[tid] = ss; __syncthreads();
    for (int s = 64; s; s >>= 1) { if (tid < s) red[tid] += red[tid + s]; __syncthreads(); }
    if (tid == 0) rinv = rsqrtf(red[0] * (1.0f / C_) + 1e-6f);
    __syncthreads();
    const float r = rinv;
    float* orow = out + (size_t)tkn * C_;
    #pragma unroll
    for (int c = tid; c < C_; c += 128) orow[c] = row[c] * r * g[c];
}

// ---------------------------------------------------------------------------
// Generic SGEMM: C[M,N] (+)= A[M,K] @ B[K,N], all row-major fp32.
// 128x128 block tile, BK=8, 256 threads, 8x8 per-thread micro tile.
// M,N multiples of 128; K multiple of 8.
// ---------------------------------------------------------------------------
__global__ __launch_bounds__(256) void gemm128(
    const float* __restrict__ A, const float* __restrict__ Bm, float* __restrict__ Cm,
    int Md, int Nd, int Kd, int addTo)
{
    __shared__ float As[8][128];
    __shared__ float Bs[8][128];
    const int t  = threadIdx.x;
    const int tx = t & 15, ty = t >> 4;
    const float* Ab = A  + (size_t)blockIdx.y * 128 * Kd;
    const float* Bb = Bm + (size_t)blockIdx.x * 128;
    float acc[8][8];
    #pragma unroll
    for (int i = 0; i < 8; i++)
        #pragma unroll
        for (int j = 0; j < 8; j++) acc[i][j] = 0.f;

    const int arow = t >> 1, ac4 = (t & 1) * 4;
    const int brow = t >> 5, bc4 = (t & 31) * 4;

    for (int k0 = 0; k0 < Kd; k0 += 8) {
        const float4 av = *(const float4*)(Ab + (size_t)arow * Kd + k0 + ac4);
        As[ac4 + 0][arow] = av.x;
        As[ac4 + 1][arow] = av.y;
        As[ac4 + 2][arow] = av.z;
        As[ac4 + 3][arow] = av.w;
        const float4 bv = *(const float4*)(Bb + (size_t)(k0 + brow) * Nd + bc4);
        *(float4*)&Bs[brow][bc4] = bv;
        __syncthreads();
        #pragma unroll
        for (int kk = 0; kk < 8; kk++) {
            float a[8], b[8];
            *(float4*)&a[0] = *(const float4*)&As[kk][ty * 8];
            *(float4*)&a[4] = *(const float4*)&As[kk][ty * 8 + 4];
            *(float4*)&b[0] = *(const float4*)&Bs[kk][tx * 8];
            *(float4*)&b[4] = *(const float4*)&Bs[kk][tx * 8 + 4];
            #pragma unroll
            for (int i = 0; i < 8; i++)
                #pragma unroll
                for (int j = 0; j < 8; j++) acc[i][j] = fmaf(a[i], b[j], acc[i][j]);
        }
        __syncthreads();
    }

    const size_t cbase = ((size_t)blockIdx.y * 128 + ty * 8) * Nd + blockIdx.x * 128 + tx * 8;
    #pragma unroll
    for (int i = 0; i < 8; i++) {
        float* crow = Cm + cbase + (size_t)i * Nd;
        if (addTo) {
            #pragma unroll
            for (int j = 0; j < 8; j++) crow[j] += acc[i][j];
        } else {
            float4 c0 = make_float4(acc[i][0], acc[i][1], acc[i][2], acc[i][3]);
            float4 c1 = make_float4(acc[i][4], acc[i][5], acc[i][6], acc[i][7]);
            *(float4*)(crow)     = c0;
            *(float4*)(crow + 4) = c1;
        }
    }
}

// ---------------------------------------------------------------------------
// Sliding-window attention.
// One block per (b, h, 64-query tile). Window W=256 -> key range of a q-tile
// is exactly 5 aligned 64-key tiles [q0-256, q0+63]. Full score slab kept in
// SMEM (64 x 320), then softmax, then P@V.
// qkv layout: [B*T, 3C] with q at [.., h*64+d], k at [.., C + ..], v at [.., 2C + ..]
// ---------------------------------------------------------------------------
#define ATT_SP 324
#define ATT_SMEM ((2*64*65 + 64*ATT_SP) * 4)

__global__ __launch_bounds__(256) void attn_kernel(
    const float* __restrict__ qkv, float* __restrict__ o)
{
    extern __shared__ float sm[];
    float* Qs = sm;              // [64][65]
    float* KV = sm + 64 * 65;    // [64][65]
    float* S  = sm + 2 * 64 * 65;// [64][ATT_SP], 320 cols used

    const int q0 = blockIdx.x * 64;
    const int h  = blockIdx.y;
    const int b  = blockIdx.z;
    const int t  = threadIdx.x;
    const int tx = t & 15, ty = t >> 4;
    const int r0 = ty * 4, c0 = tx * 4;
    const float scale = 0.125f;   // 1/sqrt(64)

    // Load Q tile (64 queries x 64 dims)
    for (int e = t; e < 64 * 16; e += 256) {
        const int q = e >> 4, dg = (e & 15) * 4;
        const float4 v = *(const float4*)(qkv + ((size_t)(b * T_ + q0 + q)) * (3 * C_) + h * D_ + dg);
        Qs[q * 65 + dg + 0] = v.x; Qs[q * 65 + dg + 1] = v.y;
        Qs[q * 65 + dg + 2] = v.z; Qs[q * 65 + dg + 3] = v.w;
    }

    // Phase 1: scores into S
    for (int it = 0; it < 5; it++) {
        const int kb = q0 + (it - 4) * 64;   // key tile base (multiple of 64, may be <0)
        if (kb < 0) {
            #pragma unroll
            for (int i = 0; i < 4; i++)
                #pragma unroll
                for (int j = 0; j < 4; j++)
                    S[(r0 + i) * ATT_SP + it * 64 + c0 + j] = -1e30f;
            continue;
        }
        __syncthreads();   // previous KV users done (also orders Qs load before compute)
        for (int e = t; e < 64 * 16; e += 256) {
            const int r = e >> 4, dg = (e & 15) * 4;
            const float4 v = *(const float4*)(qkv + ((size_t)(b * T_ + kb + r)) * (3 * C_) + C_ + h * D_ + dg);
            KV[r * 65 + dg + 0] = v.x; KV[r * 65 + dg + 1] = v.y;
            KV[r * 65 + dg + 2] = v.z; KV[r * 65 + dg + 3] = v.w;
        }
        __syncthreads();
        float acc[4][4];
        #pragma unroll
        for (int i = 0; i < 4; i++)
            #pragma unroll
            for (int j = 0; j < 4; j++) acc[i][j] = 0.f;
        #pragma unroll 4
        for (int kk = 0; kk < 64; kk++) {
            float a[4], bb[4];
            #pragma unroll
            for (int i = 0; i < 4; i++) a[i]  = Qs[(r0 + i) * 65 + kk];
            #pragma unroll
            for (int j = 0; j < 4; j++) bb[j] = KV[(c0 + j) * 65 + kk];
            #pragma unroll
            for (int i = 0; i < 4; i++)
                #pragma unroll
                for (int j = 0; j < 4; j++) acc[i][j] = fmaf(a[i], bb[j], acc[i][j]);
        }
        #pragma unroll
        for (int i = 0; i < 4; i++) {
            const int ig = q0 + r0 + i;
            #pragma unroll
            for (int j = 0; j < 4; j++) {
                const int jg = kb + c0 + j;
                const bool ok = (jg <= ig) && (jg >= ig - (WIN_ - 1));
                S[(r0 + i) * ATT_SP + it * 64 + c0 + j] = ok ? acc[i][j] * scale : -1e30f;
            }
        }
    }
    __syncthreads();

    // Phase 2: row softmax over 320 cols. 8 warps x 8 rows each.
    {
        const int wid = t >> 5, lane = t & 31;
        for (int rr = 0; rr < 8; rr++) {
            const int r = wid * 8 + rr;
            float m = -1e30f;
            for (int c = lane; c < 320; c += 32) m = fmaxf(m, S[r * ATT_SP + c]);
            #pragma unroll
            for (int off = 16; off; off >>= 1) m = fmaxf(m, __shfl_xor_sync(0xffffffffu, m, off));
            float sum = 0.f;
            for (int c = lane; c < 320; c += 32) {
                const float p = expf(S[r * ATT_SP + c] - m);
                S[r * ATT_SP + c] = p;
                sum += p;
            }
            #pragma unroll
            for (int off = 16; off; off >>= 1) sum += __shfl_xor_sync(0xffffffffu, sum, off);
            const float inv = 1.f / sum;
            for (int c = lane; c < 320; c += 32) S[r * ATT_SP + c] *= inv;
        }
    }

    // Phase 3: O = P @ V
    float oacc[4][4];
    #pragma unroll
    for (int i = 0; i < 4; i++)
        #pragma unroll
        for (int j = 0; j < 4; j++) oacc[i][j] = 0.f;

    for (int it = 0; it < 5; it++) {
        const int kb = q0 + (it - 4) * 64;
        if (kb < 0) continue;    // P is exactly 0 there
        __syncthreads();
        for (int e = t; e < 64 * 16; e += 256) {
            const int r = e >> 4, dg = (e & 15) * 4;
            const float4 v = *(const float4*)(qkv + ((size_t)(b * T_ + kb + r)) * (3 * C_) + 2 * C_ + h * D_ + dg);
            KV[r * 65 + dg + 0] = v.x; KV[r * 65 + dg + 1] = v.y;
            KV[r * 65 + dg + 2] = v.z; KV[r * 65 + dg + 3] = v.w;
        }
        __syncthreads();
        #pragma unroll 4
        for (int kk = 0; kk < 64; kk++) {
            float a[4], bb[4];
            #pragma unroll
            for (int i = 0; i < 4; i++) a[i]  = S[(r0 + i) * ATT_SP + it * 64 + kk];
            #pragma unroll
            for (int j = 0; j < 4; j++) bb[j] = KV[kk * 65 + c0 + j];
            #pragma unroll
            for (int i = 0; i < 4; i++)
                #pragma unroll
                for (int j = 0; j < 4; j++) oacc[i][j] = fmaf(a[i], bb[j], oacc[i][j]);
        }
    }
    #pragma unroll
    for (int i = 0; i < 4; i++)
        #pragma unroll
        for (int j = 0; j < 4; j++)
            o[((size_t)(b * T_ + q0 + r0 + i)) * C_ + h * D_ + c0 + j] = oacc[i][j];
}

// ---------------------------------------------------------------------------
// Retrieval projection: ret[b][c] = sum_k rc[b][k] * retW[k][c]   (tiny GEMM)
// ---------------------------------------------------------------------------
__global__ __launch_bounds__(256) void ret_kernel(
    const float* __restrict__ rc, const float* __restrict__ retW, float* __restrict__ ret)
{
    const int c = blockIdx.x * 256 + threadIdx.x;
    const int b = blockIdx.y;
    float acc = 0.f;
    for (int k = 0; k < C_; k++) acc = fmaf(rc[b * C_ + k], retW[(size_t)k * C_ + c], acc);
    ret[b * C_ + c] = acc;
}

// ---------------------------------------------------------------------------
// Gate logits + softmax (channel 1 pinned to -1e9) + residual mix:
//   x += g0 * attn_out + g2 * ret_out
// ---------------------------------------------------------------------------
__global__ __launch_bounds__(128) void gate_mix_kernel(
    const float* __restrict__ hmat, const float* __restrict__ gW, const float* __restrict__ gb,
    const float* __restrict__ attn, const float* __restrict__ ret, float* __restrict__ x)
{
    __shared__ float red0[128], red2[128];
    __shared__ float gg0, gg2;
    const int tkn = blockIdx.x, tid = threadIdx.x;
    const float* hrow = hmat + (size_t)tkn * C_;
    float p0 = 0.f, p2 = 0.f;
    for (int c = tid; c < C_; c += 128) {
        const float hv = hrow[c];
        p0 = fmaf(hv, gW[c * 3 + 0], p0);
        p2 = fmaf(hv, gW[c * 3 + 2], p2);
    }
    red0[tid] = p0; red2[tid] = p2; __syncthreads();
    for (int s = 64; s; s >>= 1) {
        if (tid < s) { red0[tid] += red0[tid + s]; red2[tid] += red2[tid + s]; }
        __syncthreads();
    }
    if (tid == 0) {
        const float l0 = red0[0] + gb[0];
        const float l2 = red2[0] + gb[2];
        const float m  = fmaxf(l0, l2);
        const float e0 = expf(l0 - m);
        const float e1 = expf(NEG_ - m);   // underflows to 0, matches reference
        const float e2 = expf(l2 - m);
        const float inv = 1.f / (e0 + e1 + e2);
        gg0 = e0 * inv; gg2 = e2 * inv;
    }
    __syncthreads();
    const float a0 = gg0, a2 = gg2;
    const int b = tkn / T_;
    float* xrow = x + (size_t)tkn * C_;
    const float* arow = attn + (size_t)tkn * C_;
    for (int c = tid; c < C_; c += 128)
        xrow[c] += a0 * arow[c] + a2 * ret[b * C_ + c];
}

// ---------------------------------------------------------------------------
// SwiGLU elementwise: f1 = silu(f1) * f2
// ---------------------------------------------------------------------------
__global__ __launch_bounds__(256) void silu_mul_kernel(
    float* __restrict__ f1, const float* __restrict__ f2, int n)
{
    for (int i = blockIdx.x * blockDim.x + threadIdx.x; i < n; i += gridDim.x * blockDim.x) {
        const float a = f1[i];
        const float s = a / (1.f + expf(-a));
        f1[i] = s * f2[i];
    }
}

// ---------------------------------------------------------------------------
// Launcher
// ---------------------------------------------------------------------------
extern "C" void kernel_launch(void* const* d_in, const int* in_sizes, int n_in,
                              void* d_out, int out_size)
{
    (void)in_sizes; (void)n_in; (void)out_size;
    const float* x    = (const float*)d_in[0];
    const float* rc   = (const float*)d_in[1];
    const float* n1g  = (const float*)d_in[2];
    const float* Wqkv = (const float*)d_in[3];
    const float* Wpro = (const float*)d_in[4];
    const float* gW   = (const float*)d_in[5];
    const float* gb   = (const float*)d_in[6];
    const float* retW = (const float*)d_in[7];
    const float* n2g  = (const float*)d_in[8];
    const float* fgW  = (const float*)d_in[9];
    const float* fuW  = (const float*)d_in[10];
    const float* fdW  = (const float*)d_in[11];
    float* xo = (float*)d_out;

    float *pH, *pH2, *pQKV, *pO, *pA, *pF1, *pF2, *pR;
    cudaGetSymbolAddress((void**)&pH,   g_h);
    cudaGetSymbolAddress((void**)&pH2,  g_h2);
    cudaGetSymbolAddress((void**)&pQKV, g_qkv);
    cudaGetSymbolAddress((void**)&pO,   g_o);
    cudaGetSymbolAddress((void**)&pA,   g_attn);
    cudaGetSymbolAddress((void**)&pF1,  g_f1);
    cudaGetSymbolAddress((void**)&pF2,  g_f2);
    cudaGetSymbolAddress((void**)&pR,   g_ret);

    cudaFuncSetAttribute(attn_kernel, cudaFuncAttributeMaxDynamicSharedMemorySize, ATT_SMEM);

    // x -> output buffer (updated in place)
    cudaMemcpyAsync(xo, x, sizeof(float) * (size_t)M_ * C_, cudaMemcpyDeviceToDevice);

    for (int l = 0; l < L_; l++) {
        rmsnorm_kernel<<<M_, 128>>>(xo, n1g + l * C_, pH);

        gemm128<<<dim3(3 * C_ / 128, M_ / 128), 256>>>(
            pH, Wqkv + (size_t)l * C_ * 3 * C_, pQKV, M_, 3 * C_, C_, 0);

        attn_kernel<<<dim3(T_ / 64, H_, B_), 256, ATT_SMEM>>>(pQKV, pO);

        gemm128<<<dim3(C_ / 128, M_ / 128), 256>>>(
            pO, Wpro + (size_t)l * C_ * C_, pA, M_, C_, C_, 0);

        ret_kernel<<<dim3(C_ / 256, B_), 256>>>(rc, retW + (size_t)l * C_ * C_, pR);

        gate_mix_kernel<<<M_, 128>>>(pH, gW + (size_t)l * C_ * 3, gb + l * 3, pA, pR, xo);

        rmsnorm_kernel<<<M_, 128>>>(xo, n2g + l * C_, pH2);

        gemm128<<<dim3(F_ / 128, M_ / 128), 256>>>(
            pH2, fgW + (size_t)l * C_ * F_, pF1, M_, F_, C_, 0);
        gemm128<<<dim3(F_ / 128, M_ / 128), 256>>>(
            pH2, fuW + (size_t)l * C_ * F_, pF2, M_, F_, C_, 0);

        silu_mul_kernel<<<4096, 256>>>(pF1, pF2, M_ * F_);

        gemm128<<<dim3(C_ / 128, M_ / 128), 256>>>(
            pF1, fdW + (size_t)l * F_ * C_, xo, M_, C_, F_, 1 /*accumulate into x*/);
    }
}

// round 2
// speedup vs baseline: 2.2148x; 2.2148x over previous
#include <cuda_runtime.h>
#include <math.h>
#include <stdint.h>

// Problem constants
#define L_ 2
#define B_ 2
#define T_ 2048
#define C_ 1024
#define H_ 16
#define D_ 64
#define F_ 4096
#define WIN_ 256
#define M_ (B_*T_)   // 4096 tokens
#define NEG_ (-1e9f)

// ---------------------------------------------------------------------------
// Scratch (static device globals; no allocation allowed)
// ---------------------------------------------------------------------------
__device__ float g_h  [M_*C_];
__device__ float g_h2 [M_*C_];
__device__ float g_qkv[M_*3*C_];
__device__ float g_o  [M_*C_];
__device__ float g_attn[M_*C_];
__device__ float g_f1 [M_*F_];
__device__ float g_f2 [M_*F_];
__device__ float g_ret[B_*C_];

// ---------------------------------------------------------------------------
// RMSNorm
// ---------------------------------------------------------------------------
__global__ __launch_bounds__(128) void rmsnorm_kernel(
    const float* __restrict__ x, const float* __restrict__ g, float* __restrict__ out)
{
    __shared__ float red[128];
    __shared__ float rinv;
    const int tkn = blockIdx.x, tid = threadIdx.x;
    const float* row = x + (size_t)tkn * C_;
    float ss = 0.f;
    #pragma unroll
    for (int c = tid; c < C_; c += 128) { float v = row[c]; ss += v * v; }
    red[tid] = ss; __syncthreads();
    for (int s = 64; s; s >>= 1) { if (tid < s) red[tid] += red[tid + s]; __syncthreads(); }
    if (tid == 0) rinv = rsqrtf(red[0] * (1.0f / C_) + 1e-6f);
    __syncthreads();
    const float r = rinv;
    float* orow = out + (size_t)tkn * C_;
    #pragma unroll
    for (int c = tid; c < C_; c += 128) orow[c] = row[c] * r * g[c];
}

// ---------------------------------------------------------------------------
// TF32 tensor-core GEMM: C[M,N] (+)= A[M,K] @ B[K,N], row-major fp32 in/out.
// 128x128x16 block tile, 256 threads, 8 warps of 64x32, mma.m16n8k8 tf32.
// Double-buffered SMEM; fp32 -> tf32 (cvt.rna) in producer.
// M,N multiples of 128; K multiple of 16.
// ---------------------------------------------------------------------------
__device__ __forceinline__ uint32_t f2tf32(float f) {
    uint32_t u;
    asm("cvt.rna.tf32.f32 %0, %1;" : "=r"(u) : "f"(f));
    return u;
}

__device__ __forceinline__ void mma_tf32(float c[4], const uint32_t a[4], const uint32_t b[2]) {
    asm volatile(
        "mma.sync.aligned.m16n8k8.row.col.f32.tf32.tf32.f32 "
        "{%0,%1,%2,%3}, {%4,%5,%6,%7}, {%8,%9}, {%0,%1,%2,%3};\n"
        : "+f"(c[0]), "+f"(c[1]), "+f"(c[2]), "+f"(c[3])
        : "r"(a[0]), "r"(a[1]), "r"(a[2]), "r"(a[3]), "r"(b[0]), "r"(b[1]));
}

#define APAD 20   // 16 + 4  -> conflict-free A-fragment LDS
#define BPAD 136  // 128 + 8 -> conflict-free B-fragment LDS

__global__ __launch_bounds__(256) void gemm_tf32(
    const float* __restrict__ A, const float* __restrict__ Bm, float* __restrict__ Cm,
    int Nd, int Kd, int addTo)
{
    __shared__ uint32_t As[2][128][APAD];
    __shared__ uint32_t Bs[2][16][BPAD];

    const int t = threadIdx.x;
    const int lane = t & 31, w = t >> 5;
    const int mb = (w >> 2) * 64;      // warp m offset (0 or 64)
    const int nb = (w & 3) * 32;       // warp n offset (0,32,64,96)
    const int r = lane >> 2, c = lane & 3;

    // Producer addressing
    const int arow = t >> 1, ac = (t & 1) * 8;     // A: row 0..127, k-offset 0 or 8
    const int brow = t >> 4, bc = (t & 15) * 8;    // B: k-row 0..15, n-offset
    const float* Ag = A + (size_t)(blockIdx.y * 128 + arow) * Kd + ac;
    const float* Bg = Bm + (size_t)brow * Nd + (size_t)blockIdx.x * 128 + bc;

    float acc[16][4];
    #pragma unroll
    for (int i = 0; i < 16; i++)
        #pragma unroll
        for (int j = 0; j < 4; j++) acc[i][j] = 0.f;

    const int niter = Kd >> 4;

    float4 av0, av1, bv0, bv1;
    // prologue load (k0 = 0)
    av0 = *(const float4*)(Ag);
    av1 = *(const float4*)(Ag + 4);
    bv0 = *(const float4*)(Bg);
    bv1 = *(const float4*)(Bg + 4);
    {
        uint32_t* ap = &As[0][arow][ac];
        ap[0]=f2tf32(av0.x); ap[1]=f2tf32(av0.y); ap[2]=f2tf32(av0.z); ap[3]=f2tf32(av0.w);
        ap[4]=f2tf32(av1.x); ap[5]=f2tf32(av1.y); ap[6]=f2tf32(av1.z); ap[7]=f2tf32(av1.w);
        uint32_t* bp = &Bs[0][brow][bc];
        bp[0]=f2tf32(bv0.x); bp[1]=f2tf32(bv0.y); bp[2]=f2tf32(bv0.z); bp[3]=f2tf32(bv0.w);
        bp[4]=f2tf32(bv1.x); bp[5]=f2tf32(bv1.y); bp[6]=f2tf32(bv1.z); bp[7]=f2tf32(bv1.w);
    }
    __syncthreads();

    int st = 0;
    for (int it = 0; it < niter; it++) {
        const bool more = (it + 1) < niter;
        if (more) {
            const int k0 = (it + 1) << 4;
            av0 = *(const float4*)(Ag + k0);
            av1 = *(const float4*)(Ag + k0 + 4);
            const float* bp = Bg + (size_t)k0 * Nd;
            bv0 = *(const float4*)(bp);
            bv1 = *(const float4*)(bp + 4);
        }

        // compute on stage st
        #pragma unroll
        for (int kk = 0; kk < 16; kk += 8) {
            uint32_t af[4][4], bf[4][2];
            #pragma unroll
            for (int mt = 0; mt < 4; mt++) {
                const int m0 = mb + mt * 16;
                af[mt][0] = As[st][m0 + r    ][kk + c];
                af[mt][1] = As[st][m0 + r + 8][kk + c];
                af[mt][2] = As[st][m0 + r    ][kk + c + 4];
                af[mt][3] = As[st][m0 + r + 8][kk + c + 4];
            }
            #pragma unroll
            for (int nt = 0; nt < 4; nt++) {
                const int n0 = nb + nt * 8;
                bf[nt][0] = Bs[st][kk + c    ][n0 + r];
                bf[nt][1] = Bs[st][kk + c + 4][n0 + r];
            }
            #pragma unroll
            for (int mt = 0; mt < 4; mt++)
                #pragma unroll
                for (int nt = 0; nt < 4; nt++)
                    mma_tf32(acc[mt * 4 + nt], af[mt], bf[nt]);
        }

        if (more) {
            const int ns = st ^ 1;
            uint32_t* ap = &As[ns][arow][ac];
            ap[0]=f2tf32(av0.x); ap[1]=f2tf32(av0.y); ap[2]=f2tf32(av0.z); ap[3]=f2tf32(av0.w);
            ap[4]=f2tf32(av1.x); ap[5]=f2tf32(av1.y); ap[6]=f2tf32(av1.z); ap[7]=f2tf32(av1.w);
            uint32_t* bp = &Bs[ns][brow][bc];
            bp[0]=f2tf32(bv0.x); bp[1]=f2tf32(bv0.y); bp[2]=f2tf32(bv0.z); bp[3]=f2tf32(bv0.w);
            bp[4]=f2tf32(bv1.x); bp[5]=f2tf32(bv1.y); bp[6]=f2tf32(bv1.z); bp[7]=f2tf32(bv1.w);
        }
        __syncthreads();
        st ^= 1;
    }

    // Epilogue: c0 (r, 2c), c1 (r, 2c+1), c2 (r+8, 2c), c3 (r+8, 2c+1)
    const size_t crow0 = (size_t)blockIdx.y * 128;
    const size_t ccol0 = (size_t)blockIdx.x * 128;
    #pragma unroll
    for (int mt = 0; mt < 4; mt++) {
        #pragma unroll
        for (int nt = 0; nt < 4; nt++) {
            const float* a4 = acc[mt * 4 + nt];
            float* p0 = Cm + (crow0 + mb + mt * 16 + r) * Nd + ccol0 + nb + nt * 8 + c * 2;
            float* p1 = p0 + 8 * (size_t)Nd;
            if (addTo) {
                p0[0] += a4[0]; p0[1] += a4[1];
                p1[0] += a4[2]; p1[1] += a4[3];
            } else {
                *(float2*)p0 = make_float2(a4[0], a4[1]);
                *(float2*)p1 = make_float2(a4[2], a4[3]);
            }
        }
    }
}

// ---------------------------------------------------------------------------
// Sliding-window attention (unchanged from R1)
// ---------------------------------------------------------------------------
#define ATT_SP 324
#define ATT_SMEM ((2*64*65 + 64*ATT_SP) * 4)

__global__ __launch_bounds__(256) void attn_kernel(
    const float* __restrict__ qkv, float* __restrict__ o)
{
    extern __shared__ float sm[];
    float* Qs = sm;
    float* KV = sm + 64 * 65;
    float* S  = sm + 2 * 64 * 65;

    const int q0 = blockIdx.x * 64;
    const int h  = blockIdx.y;
    const int b  = blockIdx.z;
    const int t  = threadIdx.x;
    const int tx = t & 15, ty = t >> 4;
    const int r0 = ty * 4, c0 = tx * 4;
    const float scale = 0.125f;

    for (int e = t; e < 64 * 16; e += 256) {
        const int q = e >> 4, dg = (e & 15) * 4;
        const float4 v = *(const float4*)(qkv + ((size_t)(b * T_ + q0 + q)) * (3 * C_) + h * D_ + dg);
        Qs[q * 65 + dg + 0] = v.x; Qs[q * 65 + dg + 1] = v.y;
        Qs[q * 65 + dg + 2] = v.z; Qs[q * 65 + dg + 3] = v.w;
    }

    for (int it = 0; it < 5; it++) {
        const int kb = q0 + (it - 4) * 64;
        if (kb < 0) {
            #pragma unroll
            for (int i = 0; i < 4; i++)
                #pragma unroll
                for (int j = 0; j < 4; j++)
                    S[(r0 + i) * ATT_SP + it * 64 + c0 + j] = -1e30f;
            continue;
        }
        __syncthreads();
        for (int e = t; e < 64 * 16; e += 256) {
            const int r = e >> 4, dg = (e & 15) * 4;
            const float4 v = *(const float4*)(qkv + ((size_t)(b * T_ + kb + r)) * (3 * C_) + C_ + h * D_ + dg);
            KV[r * 65 + dg + 0] = v.x; KV[r * 65 + dg + 1] = v.y;
            KV[r * 65 + dg + 2] = v.z; KV[r * 65 + dg + 3] = v.w;
        }
        __syncthreads();
        float acc[4][4];
        #pragma unroll
        for (int i = 0; i < 4; i++)
            #pragma unroll
            for (int j = 0; j < 4; j++) acc[i][j] = 0.f;
        #pragma unroll 4
        for (int kk = 0; kk < 64; kk++) {
            float a[4], bb[4];
            #pragma unroll
            for (int i = 0; i < 4; i++) a[i]  = Qs[(r0 + i) * 65 + kk];
            #pragma unroll
            for (int j = 0; j < 4; j++) bb[j] = KV[(c0 + j) * 65 + kk];
            #pragma unroll
            for (int i = 0; i < 4; i++)
                #pragma unroll
                for (int j = 0; j < 4; j++) acc[i][j] = fmaf(a[i], bb[j], acc[i][j]);
        }
        #pragma unroll
        for (int i = 0; i < 4; i++) {
            const int ig = q0 + r0 + i;
            #pragma unroll
            for (int j = 0; j < 4; j++) {
                const int jg = kb + c0 + j;
                const bool ok = (jg <= ig) && (jg >= ig - (WIN_ - 1));
                S[(r0 + i) * ATT_SP + it * 64 + c0 + j] = ok ? acc[i][j] * scale : -1e30f;
            }
        }
    }
    __syncthreads();

    {
        const int wid = t >> 5, lane = t & 31;
        for (int rr = 0; rr < 8; rr++) {
            const int r = wid * 8 + rr;
            float m = -1e30f;
            for (int c = lane; c < 320; c += 32) m = fmaxf(m, S[r * ATT_SP + c]);
            #pragma unroll
            for (int off = 16; off; off >>= 1) m = fmaxf(m, __shfl_xor_sync(0xffffffffu, m, off));
            float sum = 0.f;
            for (int c = lane; c < 320; c += 32) {
                const float p = expf(S[r * ATT_SP + c] - m);
                S[r * ATT_SP + c] = p;
                sum += p;
            }
            #pragma unroll
            for (int off = 16; off; off >>= 1) sum += __shfl_xor_sync(0xffffffffu, sum, off);
            const float inv = 1.f / sum;
            for (int c = lane; c < 320; c += 32) S[r * ATT_SP + c] *= inv;
        }
    }

    float oacc[4][4];
    #pragma unroll
    for (int i = 0; i < 4; i++)
        #pragma unroll
        for (int j = 0; j < 4; j++) oacc[i][j] = 0.f;

    for (int it = 0; it < 5; it++) {
        const int kb = q0 + (it - 4) * 64;
        if (kb < 0) continue;
        __syncthreads();
        for (int e = t; e < 64 * 16; e += 256) {
            const int r = e >> 4, dg = (e & 15) * 4;
            const float4 v = *(const float4*)(qkv + ((size_t)(b * T_ + kb + r)) * (3 * C_) + 2 * C_ + h * D_ + dg);
            KV[r * 65 + dg + 0] = v.x; KV[r * 65 + dg + 1] = v.y;
            KV[r * 65 + dg + 2] = v.z; KV[r * 65 + dg + 3] = v.w;
        }
        __syncthreads();
        #pragma unroll 4
        for (int kk = 0; kk < 64; kk++) {
            float a[4], bb[4];
            #pragma unroll
            for (int i = 0; i < 4; i++) a[i]  = S[(r0 + i) * ATT_SP + it * 64 + kk];
            #pragma unroll
            for (int j = 0; j < 4; j++) bb[j] = KV[kk * 65 + c0 + j];
            #pragma unroll
            for (int i = 0; i < 4; i++)
                #pragma unroll
                for (int j = 0; j < 4; j++) oacc[i][j] = fmaf(a[i], bb[j], oacc[i][j]);
        }
    }
    #pragma unroll
    for (int i = 0; i < 4; i++)
        #pragma unroll
        for (int j = 0; j < 4; j++)
            o[((size_t)(b * T_ + q0 + r0 + i)) * C_ + h * D_ + c0 + j] = oacc[i][j];
}

// ---------------------------------------------------------------------------
// Retrieval projection
// ---------------------------------------------------------------------------
__global__ __launch_bounds__(256) void ret_kernel(
    const float* __restrict__ rc, const float* __restrict__ retW, float* __restrict__ ret)
{
    const int c = blockIdx.x * 256 + threadIdx.x;
    const int b = blockIdx.y;
    float acc = 0.f;
    for (int k = 0; k < C_; k++) acc = fmaf(rc[b * C_ + k], retW[(size_t)k * C_ + c], acc);
    ret[b * C_ + c] = acc;
}

// ---------------------------------------------------------------------------
// Gate + mix
// ---------------------------------------------------------------------------
__global__ __launch_bounds__(128) void gate_mix_kernel(
    const float* __restrict__ hmat, const float* __restrict__ gW, const float* __restrict__ gb,
    const float* __restrict__ attn, const float* __restrict__ ret, float* __restrict__ x)
{
    __shared__ float red0[128], red2[128];
    __shared__ float gg0, gg2;
    const int tkn = blockIdx.x, tid = threadIdx.x;
    const float* hrow = hmat + (size_t)tkn * C_;
    float p0 = 0.f, p2 = 0.f;
    for (int c = tid; c < C_; c += 128) {
        const float hv = hrow[c];
        p0 = fmaf(hv, gW[c * 3 + 0], p0);
        p2 = fmaf(hv, gW[c * 3 + 2], p2);
    }
    red0[tid] = p0; red2[tid] = p2; __syncthreads();
    for (int s = 64; s; s >>= 1) {
        if (tid < s) { red0[tid] += red0[tid + s]; red2[tid] += red2[tid + s]; }
        __syncthreads();
    }
    if (tid == 0) {
        const float l0 = red0[0] + gb[0];
        const float l2 = red2[0] + gb[2];
        const float m  = fmaxf(l0, l2);
        const float e0 = expf(l0 - m);
        const float e1 = expf(NEG_ - m);
        const float e2 = expf(l2 - m);
        const float inv = 1.f / (e0 + e1 + e2);
        gg0 = e0 * inv; gg2 = e2 * inv;
    }
    __syncthreads();
    const float a0 = gg0, a2 = gg2;
    const int b = tkn / T_;
    float* xrow = x + (size_t)tkn * C_;
    const float* arow = attn + (size_t)tkn * C_;
    for (int c = tid; c < C_; c += 128)
        xrow[c] += a0 * arow[c] + a2 * ret[b * C_ + c];
}

// ---------------------------------------------------------------------------
// SwiGLU elementwise
// ---------------------------------------------------------------------------
__global__ __launch_bounds__(256) void silu_mul_kernel(
    float* __restrict__ f1, const float* __restrict__ f2, int n)
{
    for (int i = blockIdx.x * blockDim.x + threadIdx.x; i < n; i += gridDim.x * blockDim.x) {
        const float a = f1[i];
        const float s = a / (1.f + expf(-a));
        f1[i] = s * f2[i];
    }
}

// ---------------------------------------------------------------------------
// Launcher
// ---------------------------------------------------------------------------
extern "C" void kernel_launch(void* const* d_in, const int* in_sizes, int n_in,
                              void* d_out, int out_size)
{
    (void)in_sizes; (void)n_in; (void)out_size;
    const float* x    = (const float*)d_in[0];
    const float* rc   = (const float*)d_in[1];
    const float* n1g  = (const float*)d_in[2];
    const float* Wqkv = (const float*)d_in[3];
    const float* Wpro = (const float*)d_in[4];
    const float* gW   = (const float*)d_in[5];
    const float* gb   = (const float*)d_in[6];
    const float* retW = (const float*)d_in[7];
    const float* n2g  = (const float*)d_in[8];
    const float* fgW  = (const float*)d_in[9];
    const float* fuW  = (const float*)d_in[10];
    const float* fdW  = (const float*)d_in[11];
    float* xo = (float*)d_out;

    float *pH, *pH2, *pQKV, *pO, *pA, *pF1, *pF2, *pR;
    cudaGetSymbolAddress((void**)&pH,   g_h);
    cudaGetSymbolAddress((void**)&pH2,  g_h2);
    cudaGetSymbolAddress((void**)&pQKV, g_qkv);
    cudaGetSymbolAddress((void**)&pO,   g_o);
    cudaGetSymbolAddress((void**)&pA,   g_attn);
    cudaGetSymbolAddress((void**)&pF1,  g_f1);
    cudaGetSymbolAddress((void**)&pF2,  g_f2);
    cudaGetSymbolAddress((void**)&pR,   g_ret);

    cudaFuncSetAttribute(attn_kernel, cudaFuncAttributeMaxDynamicSharedMemorySize, ATT_SMEM);

    cudaMemcpyAsync(xo, x, sizeof(float) * (size_t)M_ * C_, cudaMemcpyDeviceToDevice);

    for (int l = 0; l < L_; l++) {
        rmsnorm_kernel<<<M_, 128>>>(xo, n1g + l * C_, pH);

        gemm_tf32<<<dim3(3 * C_ / 128, M_ / 128), 256>>>(
            pH, Wqkv + (size_t)l * C_ * 3 * C_, pQKV, 3 * C_, C_, 0);

        attn_kernel<<<dim3(T_ / 64, H_, B_), 256, ATT_SMEM>>>(pQKV, pO);

        gemm_tf32<<<dim3(C_ / 128, M_ / 128), 256>>>(
            pO, Wpro + (size_t)l * C_ * C_, pA, C_, C_, 0);

        ret_kernel<<<dim3(C_ / 256, B_), 256>>>(rc, retW + (size_t)l * C_ * C_, pR);

        gate_mix_kernel<<<M_, 128>>>(pH, gW + (size_t)l * C_ * 3, gb + l * 3, pA, pR, xo);

        rmsnorm_kernel<<<M_, 128>>>(xo, n2g + l * C_, pH2);

        gemm_tf32<<<dim3(F_ / 128, M_ / 128), 256>>>(
            pH2, fgW + (size_t)l * C_ * F_, pF1, F_, C_, 0);
        gemm_tf32<<<dim3(F_ / 128, M_ / 128), 256>>>(
            pH2, fuW + (size_t)l * C_ * F_, pF2, F_, C_, 0);

        silu_mul_kernel<<<4096, 256>>>(pF1, pF2, M_ * F_);

        gemm_tf32<<<dim3(C_ / 128, M_ / 128), 256>>>(
            pF1, fdW + (size_t)l * F_ * C_, xo, C_, F_, 1 /*accumulate*/);
    }
}

// round 3
// speedup vs baseline: 2.6113x; 1.1790x over previous
#include <cuda_runtime.h>
#include <math.h>
#include <stdint.h>

// Problem constants
#define L_ 2
#define B_ 2
#define T_ 2048
#define C_ 1024
#define H_ 16
#define D_ 64
#define F_ 4096
#define WIN_ 256
#define M_ (B_*T_)   // 4096 tokens
#define NEG_ (-1e9f)

// ---------------------------------------------------------------------------
// Scratch
// ---------------------------------------------------------------------------
__device__ float g_h  [M_*C_];
__device__ float g_h2 [M_*C_];
__device__ float g_qkv[M_*3*C_];
__device__ float g_o  [M_*C_];
__device__ float g_attn[M_*C_];
__device__ float g_f1 [M_*F_];
__device__ float g_f2 [M_*F_];
__device__ float g_ret[B_*C_];

// ---------------------------------------------------------------------------
// RMSNorm
// ---------------------------------------------------------------------------
__global__ __launch_bounds__(128) void rmsnorm_kernel(
    const float* __restrict__ x, const float* __restrict__ g, float* __restrict__ out)
{
    __shared__ float red[128];
    __shared__ float rinv;
    const int tkn = blockIdx.x, tid = threadIdx.x;
    const float* row = x + (size_t)tkn * C_;
    float ss = 0.f;
    #pragma unroll
    for (int c = tid; c < C_; c += 128) { float v = row[c]; ss += v * v; }
    red[tid] = ss; __syncthreads();
    for (int s = 64; s; s >>= 1) { if (tid < s) red[tid] += red[tid + s]; __syncthreads(); }
    if (tid == 0) rinv = rsqrtf(red[0] * (1.0f / C_) + 1e-6f);
    __syncthreads();
    const float r = rinv;
    float* orow = out + (size_t)tkn * C_;
    #pragma unroll
    for (int c = tid; c < C_; c += 128) orow[c] = row[c] * r * g[c];
}

// ---------------------------------------------------------------------------
// TF32 tensor-core GEMM v2.
// 128(M)x256(N)x16(K) block tile, 256 threads, 8 warps of 64x64.
// cp.async 3-stage pipeline; MMA consumes raw fp32 bits (HW tf32 truncation).
// N multiple of 256, M multiple of 128, K multiple of 16 (and >= 32).
// ---------------------------------------------------------------------------
__device__ __forceinline__ void mma_tf32(float c[4], const uint32_t a[4], const uint32_t b[2]) {
    asm volatile(
        "mma.sync.aligned.m16n8k8.row.col.f32.tf32.tf32.f32 "
        "{%0,%1,%2,%3}, {%4,%5,%6,%7}, {%8,%9}, {%0,%1,%2,%3};\n"
        : "+f"(c[0]), "+f"(c[1]), "+f"(c[2]), "+f"(c[3])
        : "r"(a[0]), "r"(a[1]), "r"(a[2]), "r"(a[3]), "r"(b[0]), "r"(b[1]));
}

#define APADV 20     // A row: 16 + 4 floats pad (80 bytes, 16B aligned)
#define BPADV 264    // B row: 256 + 8 floats pad (1056 bytes, 16B aligned)
#define STG_F 6784   // floats per stage: 128*20 + 16*264
#define GEMM_SMEM (3 * STG_F * 4)

__device__ __forceinline__ void cp16(void* dst, const void* src) {
    uint32_t d = (uint32_t)__cvta_generic_to_shared(dst);
    asm volatile("cp.async.cg.shared.global [%0], [%1], 16;\n" :: "r"(d), "l"(src));
}

__global__ __launch_bounds__(256, 1) void gemm_tf32_v2(
    const float* __restrict__ A, const float* __restrict__ Bm, float* __restrict__ Cm,
    int Nd, int Kd, int addTo)
{
    extern __shared__ float smv[];
    #define ASM_(s,m,k)  smv[(s)*STG_F + (m)*APADV + (k)]
    #define BSM_(s,kr,n) smv[(s)*STG_F + 128*APADV + (kr)*BPADV + (n)]

    const int t = threadIdx.x;
    const int w = t >> 5, lane = t & 31;
    const int r = lane >> 2, c = lane & 3;
    const int mb = (w & 1) * 64, nb = (w >> 1) * 64;
    const int bm = blockIdx.y * 128, bn = blockIdx.x * 256;

    // producer indices
    const int am = t >> 2, ak = (t & 3) * 4;    // A rows am, am+64 (16B each)
    const int bk = t >> 6, bn0 = (t & 63) * 4;  // B rows bk+4i        (16B each)
    const float* Ag = A  + (size_t)(bm + am) * Kd + ak;
    const float* Bg = Bm + (size_t)bn + bn0;

    float acc[32][4];
    #pragma unroll
    for (int i = 0; i < 32; i++)
        #pragma unroll
        for (int j = 0; j < 4; j++) acc[i][j] = 0.f;

    const int niter = Kd >> 4;

    // prologue: stages 0,1
    #pragma unroll
    for (int p = 0; p < 2; p++) {
        const int kt = p << 4;
        cp16(&ASM_(p, am, ak),      Ag + kt);
        cp16(&ASM_(p, am + 64, ak), Ag + (size_t)64 * Kd + kt);
        #pragma unroll
        for (int i = 0; i < 4; i++) {
            const int kr = bk + i * 4;
            cp16(&BSM_(p, kr, bn0), Bg + (size_t)(kt + kr) * Nd);
        }
        asm volatile("cp.async.commit_group;\n");
    }

    int st = 0;
    for (int it = 0; it < niter; it++) {
        asm volatile("cp.async.wait_group 1;\n");
        __syncthreads();

        if (it + 2 < niter) {
            const int ps = (st + 2) % 3;
            const int kt = (it + 2) << 4;
            cp16(&ASM_(ps, am, ak),      Ag + kt);
            cp16(&ASM_(ps, am + 64, ak), Ag + (size_t)64 * Kd + kt);
            #pragma unroll
            for (int i = 0; i < 4; i++) {
                const int kr = bk + i * 4;
                cp16(&BSM_(ps, kr, bn0), Bg + (size_t)(kt + kr) * Nd);
            }
        }
        asm volatile("cp.async.commit_group;\n");

        // compute on stage st
        #pragma unroll
        for (int kh = 0; kh < 16; kh += 8) {
            uint32_t af[4][4], bf[8][2];
            #pragma unroll
            for (int mt = 0; mt < 4; mt++) {
                const int m0 = mb + mt * 16 + r;
                af[mt][0] = __float_as_uint(ASM_(st, m0,     kh + c));
                af[mt][1] = __float_as_uint(ASM_(st, m0 + 8, kh + c));
                af[mt][2] = __float_as_uint(ASM_(st, m0,     kh + c + 4));
                af[mt][3] = __float_as_uint(ASM_(st, m0 + 8, kh + c + 4));
            }
            #pragma unroll
            for (int nt = 0; nt < 8; nt++) {
                const int n0 = nb + nt * 8 + r;
                bf[nt][0] = __float_as_uint(BSM_(st, kh + c,     n0));
                bf[nt][1] = __float_as_uint(BSM_(st, kh + c + 4, n0));
            }
            #pragma unroll
            for (int mt = 0; mt < 4; mt++)
                #pragma unroll
                for (int nt = 0; nt < 8; nt++)
                    mma_tf32(acc[mt * 8 + nt], af[mt], bf[nt]);
        }

        __syncthreads();
        st = (st + 1) % 3;
    }

    // Epilogue
    #pragma unroll
    for (int mt = 0; mt < 4; mt++) {
        #pragma unroll
        for (int nt = 0; nt < 8; nt++) {
            const float* a4 = acc[mt * 8 + nt];
            float* p0 = Cm + (size_t)(bm + mb + mt * 16 + r) * Nd + bn + nb + nt * 8 + c * 2;
            float* p1 = p0 + 8 * (size_t)Nd;
            if (addTo) {
                p0[0] += a4[0]; p0[1] += a4[1];
                p1[0] += a4[2]; p1[1] += a4[3];
            } else {
                *(float2*)p0 = make_float2(a4[0], a4[1]);
                *(float2*)p1 = make_float2(a4[2], a4[3]);
            }
        }
    }
    #undef ASM_
    #undef BSM_
}

// ---------------------------------------------------------------------------
// Sliding-window attention (unchanged)
// ---------------------------------------------------------------------------
#define ATT_SP 324
#define ATT_SMEM ((2*64*65 + 64*ATT_SP) * 4)

__global__ __launch_bounds__(256) void attn_kernel(
    const float* __restrict__ qkv, float* __restrict__ o)
{
    extern __shared__ float sm[];
    float* Qs = sm;
    float* KV = sm + 64 * 65;
    float* S  = sm + 2 * 64 * 65;

    const int q0 = blockIdx.x * 64;
    const int h  = blockIdx.y;
    const int b  = blockIdx.z;
    const int t  = threadIdx.x;
    const int tx = t & 15, ty = t >> 4;
    const int r0 = ty * 4, c0 = tx * 4;
    const float scale = 0.125f;

    for (int e = t; e < 64 * 16; e += 256) {
        const int q = e >> 4, dg = (e & 15) * 4;
        const float4 v = *(const float4*)(qkv + ((size_t)(b * T_ + q0 + q)) * (3 * C_) + h * D_ + dg);
        Qs[q * 65 + dg + 0] = v.x; Qs[q * 65 + dg + 1] = v.y;
        Qs[q * 65 + dg + 2] = v.z; Qs[q * 65 + dg + 3] = v.w;
    }

    for (int it = 0; it < 5; it++) {
        const int kb = q0 + (it - 4) * 64;
        if (kb < 0) {
            #pragma unroll
            for (int i = 0; i < 4; i++)
                #pragma unroll
                for (int j = 0; j < 4; j++)
                    S[(r0 + i) * ATT_SP + it * 64 + c0 + j] = -1e30f;
            continue;
        }
        __syncthreads();
        for (int e = t; e < 64 * 16; e += 256) {
            const int r = e >> 4, dg = (e & 15) * 4;
            const float4 v = *(const float4*)(qkv + ((size_t)(b * T_ + kb + r)) * (3 * C_) + C_ + h * D_ + dg);
            KV[r * 65 + dg + 0] = v.x; KV[r * 65 + dg + 1] = v.y;
            KV[r * 65 + dg + 2] = v.z; KV[r * 65 + dg + 3] = v.w;
        }
        __syncthreads();
        float acc[4][4];
        #pragma unroll
        for (int i = 0; i < 4; i++)
            #pragma unroll
            for (int j = 0; j < 4; j++) acc[i][j] = 0.f;
        #pragma unroll 4
        for (int kk = 0; kk < 64; kk++) {
            float a[4], bb[4];
            #pragma unroll
            for (int i = 0; i < 4; i++) a[i]  = Qs[(r0 + i) * 65 + kk];
            #pragma unroll
            for (int j = 0; j < 4; j++) bb[j] = KV[(c0 + j) * 65 + kk];
            #pragma unroll
            for (int i = 0; i < 4; i++)
                #pragma unroll
                for (int j = 0; j < 4; j++) acc[i][j] = fmaf(a[i], bb[j], acc[i][j]);
        }
        #pragma unroll
        for (int i = 0; i < 4; i++) {
            const int ig = q0 + r0 + i;
            #pragma unroll
            for (int j = 0; j < 4; j++) {
                const int jg = kb + c0 + j;
                const bool ok = (jg <= ig) && (jg >= ig - (WIN_ - 1));
                S[(r0 + i) * ATT_SP + it * 64 + c0 + j] = ok ? acc[i][j] * scale : -1e30f;
            }
        }
    }
    __syncthreads();

    {
        const int wid = t >> 5, lane = t & 31;
        for (int rr = 0; rr < 8; rr++) {
            const int r = wid * 8 + rr;
            float m = -1e30f;
            for (int c = lane; c < 320; c += 32) m = fmaxf(m, S[r * ATT_SP + c]);
            #pragma unroll
            for (int off = 16; off; off >>= 1) m = fmaxf(m, __shfl_xor_sync(0xffffffffu, m, off));
            float sum = 0.f;
            for (int c = lane; c < 320; c += 32) {
                const float p = expf(S[r * ATT_SP + c] - m);
                S[r * ATT_SP + c] = p;
                sum += p;
            }
            #pragma unroll
            for (int off = 16; off; off >>= 1) sum += __shfl_xor_sync(0xffffffffu, sum, off);
            const float inv = 1.f / sum;
            for (int c = lane; c < 320; c += 32) S[r * ATT_SP + c] *= inv;
        }
    }

    float oacc[4][4];
    #pragma unroll
    for (int i = 0; i < 4; i++)
        #pragma unroll
        for (int j = 0; j < 4; j++) oacc[i][j] = 0.f;

    for (int it = 0; it < 5; it++) {
        const int kb = q0 + (it - 4) * 64;
        if (kb < 0) continue;
        __syncthreads();
        for (int e = t; e < 64 * 16; e += 256) {
            const int r = e >> 4, dg = (e & 15) * 4;
            const float4 v = *(const float4*)(qkv + ((size_t)(b * T_ + kb + r)) * (3 * C_) + 2 * C_ + h * D_ + dg);
            KV[r * 65 + dg + 0] = v.x; KV[r * 65 + dg + 1] = v.y;
            KV[r * 65 + dg + 2] = v.z; KV[r * 65 + dg + 3] = v.w;
        }
        __syncthreads();
        #pragma unroll 4
        for (int kk = 0; kk < 64; kk++) {
            float a[4], bb[4];
            #pragma unroll
            for (int i = 0; i < 4; i++) a[i]  = S[(r0 + i) * ATT_SP + it * 64 + kk];
            #pragma unroll
            for (int j = 0; j < 4; j++) bb[j] = KV[kk * 65 + c0 + j];
            #pragma unroll
            for (int i = 0; i < 4; i++)
                #pragma unroll
                for (int j = 0; j < 4; j++) oacc[i][j] = fmaf(a[i], bb[j], oacc[i][j]);
        }
    }
    #pragma unroll
    for (int i = 0; i < 4; i++)
        #pragma unroll
        for (int j = 0; j < 4; j++)
            o[((size_t)(b * T_ + q0 + r0 + i)) * C_ + h * D_ + c0 + j] = oacc[i][j];
}

// ---------------------------------------------------------------------------
// Retrieval projection
// ---------------------------------------------------------------------------
__global__ __launch_bounds__(256) void ret_kernel(
    const float* __restrict__ rc, const float* __restrict__ retW, float* __restrict__ ret)
{
    const int c = blockIdx.x * 256 + threadIdx.x;
    const int b = blockIdx.y;
    float acc = 0.f;
    for (int k = 0; k < C_; k++) acc = fmaf(rc[b * C_ + k], retW[(size_t)k * C_ + c], acc);
    ret[b * C_ + c] = acc;
}

// ---------------------------------------------------------------------------
// Gate + mix
// ---------------------------------------------------------------------------
__global__ __launch_bounds__(128) void gate_mix_kernel(
    const float* __restrict__ hmat, const float* __restrict__ gW, const float* __restrict__ gb,
    const float* __restrict__ attn, const float* __restrict__ ret, float* __restrict__ x)
{
    __shared__ float red0[128], red2[128];
    __shared__ float gg0, gg2;
    const int tkn = blockIdx.x, tid = threadIdx.x;
    const float* hrow = hmat + (size_t)tkn * C_;
    float p0 = 0.f, p2 = 0.f;
    for (int c = tid; c < C_; c += 128) {
        const float hv = hrow[c];
        p0 = fmaf(hv, gW[c * 3 + 0], p0);
        p2 = fmaf(hv, gW[c * 3 + 2], p2);
    }
    red0[tid] = p0; red2[tid] = p2; __syncthreads();
    for (int s = 64; s; s >>= 1) {
        if (tid < s) { red0[tid] += red0[tid + s]; red2[tid] += red2[tid + s]; }
        __syncthreads();
    }
    if (tid == 0) {
        const float l0 = red0[0] + gb[0];
        const float l2 = red2[0] + gb[2];
        const float m  = fmaxf(l0, l2);
        const float e0 = expf(l0 - m);
        const float e1 = expf(NEG_ - m);
        const float e2 = expf(l2 - m);
        const float inv = 1.f / (e0 + e1 + e2);
        gg0 = e0 * inv; gg2 = e2 * inv;
    }
    __syncthreads();
    const float a0 = gg0, a2 = gg2;
    const int b = tkn / T_;
    float* xrow = x + (size_t)tkn * C_;
    const float* arow = attn + (size_t)tkn * C_;
    for (int c = tid; c < C_; c += 128)
        xrow[c] += a0 * arow[c] + a2 * ret[b * C_ + c];
}

// ---------------------------------------------------------------------------
// SwiGLU elementwise
// ---------------------------------------------------------------------------
__global__ __launch_bounds__(256) void silu_mul_kernel(
    float* __restrict__ f1, const float* __restrict__ f2, int n)
{
    for (int i = blockIdx.x * blockDim.x + threadIdx.x; i < n; i += gridDim.x * blockDim.x) {
        const float a = f1[i];
        const float s = a / (1.f + expf(-a));
        f1[i] = s * f2[i];
    }
}

// ---------------------------------------------------------------------------
// Launcher
// ---------------------------------------------------------------------------
extern "C" void kernel_launch(void* const* d_in, const int* in_sizes, int n_in,
                              void* d_out, int out_size)
{
    (void)in_sizes; (void)n_in; (void)out_size;
    const float* x    = (const float*)d_in[0];
    const float* rc   = (const float*)d_in[1];
    const float* n1g  = (const float*)d_in[2];
    const float* Wqkv = (const float*)d_in[3];
    const float* Wpro = (const float*)d_in[4];
    const float* gW   = (const float*)d_in[5];
    const float* gb   = (const float*)d_in[6];
    const float* retW = (const float*)d_in[7];
    const float* n2g  = (const float*)d_in[8];
    const float* fgW  = (const float*)d_in[9];
    const float* fuW  = (const float*)d_in[10];
    const float* fdW  = (const float*)d_in[11];
    float* xo = (float*)d_out;

    float *pH, *pH2, *pQKV, *pO, *pA, *pF1, *pF2, *pR;
    cudaGetSymbolAddress((void**)&pH,   g_h);
    cudaGetSymbolAddress((void**)&pH2,  g_h2);
    cudaGetSymbolAddress((void**)&pQKV, g_qkv);
    cudaGetSymbolAddress((void**)&pO,   g_o);
    cudaGetSymbolAddress((void**)&pA,   g_attn);
    cudaGetSymbolAddress((void**)&pF1,  g_f1);
    cudaGetSymbolAddress((void**)&pF2,  g_f2);
    cudaGetSymbolAddress((void**)&pR,   g_ret);

    cudaFuncSetAttribute(attn_kernel, cudaFuncAttributeMaxDynamicSharedMemorySize, ATT_SMEM);
    cudaFuncSetAttribute(gemm_tf32_v2, cudaFuncAttributeMaxDynamicSharedMemorySize, GEMM_SMEM);

    cudaMemcpyAsync(xo, x, sizeof(float) * (size_t)M_ * C_, cudaMemcpyDeviceToDevice);

    for (int l = 0; l < L_; l++) {
        rmsnorm_kernel<<<M_, 128>>>(xo, n1g + l * C_, pH);

        gemm_tf32_v2<<<dim3(3 * C_ / 256, M_ / 128), 256, GEMM_SMEM>>>(
            pH, Wqkv + (size_t)l * C_ * 3 * C_, pQKV, 3 * C_, C_, 0);

        attn_kernel<<<dim3(T_ / 64, H_, B_), 256, ATT_SMEM>>>(pQKV, pO);

        gemm_tf32_v2<<<dim3(C_ / 256, M_ / 128), 256, GEMM_SMEM>>>(
            pO, Wpro + (size_t)l * C_ * C_, pA, C_, C_, 0);

        ret_kernel<<<dim3(C_ / 256, B_), 256>>>(rc, retW + (size_t)l * C_ * C_, pR);

        gate_mix_kernel<<<M_, 128>>>(pH, gW + (size_t)l * C_ * 3, gb + l * 3, pA, pR, xo);

        rmsnorm_kernel<<<M_, 128>>>(xo, n2g + l * C_, pH2);

        gemm_tf32_v2<<<dim3(F_ / 256, M_ / 128), 256, GEMM_SMEM>>>(
            pH2, fgW + (size_t)l * C_ * F_, pF1, F_, C_, 0);
        gemm_tf32_v2<<<dim3(F_ / 256, M_ / 128), 256, GEMM_SMEM>>>(
            pH2, fuW + (size_t)l * C_ * F_, pF2, F_, C_, 0);

        silu_mul_kernel<<<4096, 256>>>(pF1, pF2, M_ * F_);

        gemm_tf32_v2<<<dim3(C_ / 256, M_ / 128), 256, GEMM_SMEM>>>(
            pF1, fdW + (size_t)l * F_ * C_, xo, C_, F_, 1 /*accumulate*/);
    }
}

// round 4
// speedup vs baseline: 2.6577x; 1.0178x over previous
#include <cuda_runtime.h>
#include <math.h>
#include <stdint.h>

// Problem constants
#define L_ 2
#define B_ 2
#define T_ 2048
#define C_ 1024
#define H_ 16
#define D_ 64
#define F_ 4096
#define WIN_ 256
#define M_ (B_*T_)   // 4096 tokens
#define NEG_ (-1e9f)

// ---------------------------------------------------------------------------
// Scratch
// ---------------------------------------------------------------------------
__device__ float g_h  [M_*C_];
__device__ float g_h2 [M_*C_];
__device__ float g_qkv[M_*3*C_];
__device__ float g_o  [M_*C_];
__device__ float g_attn[M_*C_];
__device__ float g_f1 [M_*F_];
__device__ float g_f2 [M_*F_];
__device__ float g_ret[B_*C_];

// ---------------------------------------------------------------------------
// RMSNorm
// ---------------------------------------------------------------------------
__global__ __launch_bounds__(128) void rmsnorm_kernel(
    const float* __restrict__ x, const float* __restrict__ g, float* __restrict__ out)
{
    __shared__ float red[128];
    __shared__ float rinv;
    const int tkn = blockIdx.x, tid = threadIdx.x;
    const float* row = x + (size_t)tkn * C_;
    float ss = 0.f;
    #pragma unroll
    for (int c = tid; c < C_; c += 128) { float v = row[c]; ss += v * v; }
    red[tid] = ss; __syncthreads();
    for (int s = 64; s; s >>= 1) { if (tid < s) red[tid] += red[tid + s]; __syncthreads(); }
    if (tid == 0) rinv = rsqrtf(red[0] * (1.0f / C_) + 1e-6f);
    __syncthreads();
    const float r = rinv;
    float* orow = out + (size_t)tkn * C_;
    #pragma unroll
    for (int c = tid; c < C_; c += 128) orow[c] = row[c] * r * g[c];
}

// ---------------------------------------------------------------------------
// TF32 tensor-core GEMM v3.
// 128x128x32 block tile, 256 threads (8 warps of 64x32), 2 blocks/SM.
// 3-stage cp.async pipeline, ONE __syncthreads per k-iter.
// Fragments rounded with cvt.rna.tf32 before MMA (restores precision).
// M,N multiples of 128; K multiple of 32.
// ---------------------------------------------------------------------------
__device__ __forceinline__ uint32_t f2tf32r(float f) {
    uint32_t u;
    asm("cvt.rna.tf32.f32 %0, %1;" : "=r"(u) : "f"(f));
    return u;
}

__device__ __forceinline__ void mma_tf32(float c[4], const uint32_t a[4], const uint32_t b[2]) {
    asm volatile(
        "mma.sync.aligned.m16n8k8.row.col.f32.tf32.tf32.f32 "
        "{%0,%1,%2,%3}, {%4,%5,%6,%7}, {%8,%9}, {%0,%1,%2,%3};\n"
        : "+f"(c[0]), "+f"(c[1]), "+f"(c[2]), "+f"(c[3])
        : "r"(a[0]), "r"(a[1]), "r"(a[2]), "r"(a[3]), "r"(b[0]), "r"(b[1]));
}

#define APAD3 36     // 32 + 4 floats pad
#define BPAD3 136    // 128 + 8 floats pad
#define ASTG3 (128*APAD3)          // 4608 floats
#define BSTG3 (32*BPAD3)           // 4352 floats
#define STG3  (ASTG3 + BSTG3)      // 8960 floats per stage
#define GEMM3_SMEM (3 * STG3 * 4)  // 107520 bytes

__device__ __forceinline__ void cp16(void* dst, const void* src) {
    uint32_t d = (uint32_t)__cvta_generic_to_shared(dst);
    asm volatile("cp.async.cg.shared.global [%0], [%1], 16;\n" :: "r"(d), "l"(src));
}

__global__ void __launch_bounds__(256, 2) gemm_tf32_v3(
    const float* __restrict__ A, const float* __restrict__ Bm, float* __restrict__ Cm,
    int Nd, int Kd, int addTo)
{
    extern __shared__ float smv[];
    #define ASM_(s,m,k)  smv[(s)*STG3 + (m)*APAD3 + (k)]
    #define BSM_(s,kr,n) smv[(s)*STG3 + ASTG3 + (kr)*BPAD3 + (n)]

    const int t = threadIdx.x;
    const int w = t >> 5, lane = t & 31;
    const int r = lane >> 2, c = lane & 3;
    const int mb = (w >> 2) * 64;   // 0 or 64
    const int nb = (w & 3) * 32;    // 0,32,64,96
    const int bm = blockIdx.y * 128, bn = blockIdx.x * 128;

    // producer indices
    const int ar = t >> 3, ak = (t & 7) * 4;     // A rows ar+32i, 16B chunks
    const int br = t >> 5, bn0 = (t & 31) * 4;   // B rows br+8i, 16B chunks
    const float* Ag = A  + (size_t)(bm + ar) * Kd + ak;
    const float* Bg = Bm + (size_t)bn + bn0;

    float acc[16][4];
    #pragma unroll
    for (int i = 0; i < 16; i++)
        #pragma unroll
        for (int j = 0; j < 4; j++) acc[i][j] = 0.f;

    const int niter = Kd >> 5;

    // prologue: stages 0,1
    #pragma unroll
    for (int p = 0; p < 2; p++) {
        const int kt = p << 5;
        #pragma unroll
        for (int i = 0; i < 4; i++)
            cp16(&ASM_(p, ar + 32 * i, ak), Ag + (size_t)(32 * i) * Kd + kt);
        #pragma unroll
        for (int i = 0; i < 4; i++)
            cp16(&BSM_(p, br + 8 * i, bn0), Bg + (size_t)(kt + br + 8 * i) * Nd);
        asm volatile("cp.async.commit_group;\n");
    }

    int st = 0;
    for (int it = 0; it < niter; it++) {
        asm volatile("cp.async.wait_group 1;\n");
        __syncthreads();

        // prefetch stage st+2 (never the stage being read this iter)
        if (it + 2 < niter) {
            const int ps = (st + 2) % 3;
            const int kt = (it + 2) << 5;
            #pragma unroll
            for (int i = 0; i < 4; i++)
                cp16(&ASM_(ps, ar + 32 * i, ak), Ag + (size_t)(32 * i) * Kd + kt);
            #pragma unroll
            for (int i = 0; i < 4; i++)
                cp16(&BSM_(ps, br + 8 * i, bn0), Bg + (size_t)(kt + br + 8 * i) * Nd);
        }
        asm volatile("cp.async.commit_group;\n");

        // compute on stage st: 4 k-halves of 8
        #pragma unroll
        for (int kh = 0; kh < 32; kh += 8) {
            uint32_t af[4][4], bf[4][2];
            #pragma unroll
            for (int mt = 0; mt < 4; mt++) {
                const int m0 = mb + mt * 16 + r;
                af[mt][0] = f2tf32r(ASM_(st, m0,     kh + c));
                af[mt][1] = f2tf32r(ASM_(st, m0 + 8, kh + c));
                af[mt][2] = f2tf32r(ASM_(st, m0,     kh + c + 4));
                af[mt][3] = f2tf32r(ASM_(st, m0 + 8, kh + c + 4));
            }
            #pragma unroll
            for (int nt = 0; nt < 4; nt++) {
                const int n0 = nb + nt * 8 + r;
                bf[nt][0] = f2tf32r(BSM_(st, kh + c,     n0));
                bf[nt][1] = f2tf32r(BSM_(st, kh + c + 4, n0));
            }
            #pragma unroll
            for (int mt = 0; mt < 4; mt++)
                #pragma unroll
                for (int nt = 0; nt < 4; nt++)
                    mma_tf32(acc[mt * 4 + nt], af[mt], bf[nt]);
        }

        st = (st + 1) % 3;
    }

    // Epilogue
    #pragma unroll
    for (int mt = 0; mt < 4; mt++) {
        #pragma unroll
        for (int nt = 0; nt < 4; nt++) {
            const float* a4 = acc[mt * 4 + nt];
            float* p0 = Cm + (size_t)(bm + mb + mt * 16 + r) * Nd + bn + nb + nt * 8 + c * 2;
            float* p1 = p0 + 8 * (size_t)Nd;
            if (addTo) {
                p0[0] += a4[0]; p0[1] += a4[1];
                p1[0] += a4[2]; p1[1] += a4[3];
            } else {
                *(float2*)p0 = make_float2(a4[0], a4[1]);
                *(float2*)p1 = make_float2(a4[2], a4[3]);
            }
        }
    }
    #undef ASM_
    #undef BSM_
}

// ---------------------------------------------------------------------------
// Sliding-window attention (unchanged)
// ---------------------------------------------------------------------------
#define ATT_SP 324
#define ATT_SMEM ((2*64*65 + 64*ATT_SP) * 4)

__global__ __launch_bounds__(256) void attn_kernel(
    const float* __restrict__ qkv, float* __restrict__ o)
{
    extern __shared__ float sm[];
    float* Qs = sm;
    float* KV = sm + 64 * 65;
    float* S  = sm + 2 * 64 * 65;

    const int q0 = blockIdx.x * 64;
    const int h  = blockIdx.y;
    const int b  = blockIdx.z;
    const int t  = threadIdx.x;
    const int tx = t & 15, ty = t >> 4;
    const int r0 = ty * 4, c0 = tx * 4;
    const float scale = 0.125f;

    for (int e = t; e < 64 * 16; e += 256) {
        const int q = e >> 4, dg = (e & 15) * 4;
        const float4 v = *(const float4*)(qkv + ((size_t)(b * T_ + q0 + q)) * (3 * C_) + h * D_ + dg);
        Qs[q * 65 + dg + 0] = v.x; Qs[q * 65 + dg + 1] = v.y;
        Qs[q * 65 + dg + 2] = v.z; Qs[q * 65 + dg + 3] = v.w;
    }

    for (int it = 0; it < 5; it++) {
        const int kb = q0 + (it - 4) * 64;
        if (kb < 0) {
            #pragma unroll
            for (int i = 0; i < 4; i++)
                #pragma unroll
                for (int j = 0; j < 4; j++)
                    S[(r0 + i) * ATT_SP + it * 64 + c0 + j] = -1e30f;
            continue;
        }
        __syncthreads();
        for (int e = t; e < 64 * 16; e += 256) {
            const int r = e >> 4, dg = (e & 15) * 4;
            const float4 v = *(const float4*)(qkv + ((size_t)(b * T_ + kb + r)) * (3 * C_) + C_ + h * D_ + dg);
            KV[r * 65 + dg + 0] = v.x; KV[r * 65 + dg + 1] = v.y;
            KV[r * 65 + dg + 2] = v.z; KV[r * 65 + dg + 3] = v.w;
        }
        __syncthreads();
        float acc[4][4];
        #pragma unroll
        for (int i = 0; i < 4; i++)
            #pragma unroll
            for (int j = 0; j < 4; j++) acc[i][j] = 0.f;
        #pragma unroll 4
        for (int kk = 0; kk < 64; kk++) {
            float a[4], bb[4];
            #pragma unroll
            for (int i = 0; i < 4; i++) a[i]  = Qs[(r0 + i) * 65 + kk];
            #pragma unroll
            for (int j = 0; j < 4; j++) bb[j] = KV[(c0 + j) * 65 + kk];
            #pragma unroll
            for (int i = 0; i < 4; i++)
                #pragma unroll
                for (int j = 0; j < 4; j++) acc[i][j] = fmaf(a[i], bb[j], acc[i][j]);
        }
        #pragma unroll
        for (int i = 0; i < 4; i++) {
            const int ig = q0 + r0 + i;
            #pragma unroll
            for (int j = 0; j < 4; j++) {
                const int jg = kb + c0 + j;
                const bool ok = (jg <= ig) && (jg >= ig - (WIN_ - 1));
                S[(r0 + i) * ATT_SP + it * 64 + c0 + j] = ok ? acc[i][j] * scale : -1e30f;
            }
        }
    }
    __syncthreads();

    {
        const int wid = t >> 5, lane = t & 31;
        for (int rr = 0; rr < 8; rr++) {
            const int r = wid * 8 + rr;
            float m = -1e30f;
            for (int c = lane; c < 320; c += 32) m = fmaxf(m, S[r * ATT_SP + c]);
            #pragma unroll
            for (int off = 16; off; off >>= 1) m = fmaxf(m, __shfl_xor_sync(0xffffffffu, m, off));
            float sum = 0.f;
            for (int c = lane; c < 320; c += 32) {
                const float p = expf(S[r * ATT_SP + c] - m);
                S[r * ATT_SP + c] = p;
                sum += p;
            }
            #pragma unroll
            for (int off = 16; off; off >>= 1) sum += __shfl_xor_sync(0xffffffffu, sum, off);
            const float inv = 1.f / sum;
            for (int c = lane; c < 320; c += 32) S[r * ATT_SP + c] *= inv;
        }
    }

    float oacc[4][4];
    #pragma unroll
    for (int i = 0; i < 4; i++)
        #pragma unroll
        for (int j = 0; j < 4; j++) oacc[i][j] = 0.f;

    for (int it = 0; it < 5; it++) {
        const int kb = q0 + (it - 4) * 64;
        if (kb < 0) continue;
        __syncthreads();
        for (int e = t; e < 64 * 16; e += 256) {
            const int r = e >> 4, dg = (e & 15) * 4;
            const float4 v = *(const float4*)(qkv + ((size_t)(b * T_ + kb + r)) * (3 * C_) + 2 * C_ + h * D_ + dg);
            KV[r * 65 + dg + 0] = v.x; KV[r * 65 + dg + 1] = v.y;
            KV[r * 65 + dg + 2] = v.z; KV[r * 65 + dg + 3] = v.w;
        }
        __syncthreads();
        #pragma unroll 4
        for (int kk = 0; kk < 64; kk++) {
            float a[4], bb[4];
            #pragma unroll
            for (int i = 0; i < 4; i++) a[i]  = S[(r0 + i) * ATT_SP + it * 64 + kk];
            #pragma unroll
            for (int j = 0; j < 4; j++) bb[j] = KV[kk * 65 + c0 + j];
            #pragma unroll
            for (int i = 0; i < 4; i++)
                #pragma unroll
                for (int j = 0; j < 4; j++) oacc[i][j] = fmaf(a[i], bb[j], oacc[i][j]);
        }
    }
    #pragma unroll
    for (int i = 0; i < 4; i++)
        #pragma unroll
        for (int j = 0; j < 4; j++)
            o[((size_t)(b * T_ + q0 + r0 + i)) * C_ + h * D_ + c0 + j] = oacc[i][j];
}

// ---------------------------------------------------------------------------
// Retrieval projection
// ---------------------------------------------------------------------------
__global__ __launch_bounds__(256) void ret_kernel(
    const float* __restrict__ rc, const float* __restrict__ retW, float* __restrict__ ret)
{
    const int c = blockIdx.x * 256 + threadIdx.x;
    const int b = blockIdx.y;
    float acc = 0.f;
    for (int k = 0; k < C_; k++) acc = fmaf(rc[b * C_ + k], retW[(size_t)k * C_ + c], acc);
    ret[b * C_ + c] = acc;
}

// ---------------------------------------------------------------------------
// Gate + mix
// ---------------------------------------------------------------------------
__global__ __launch_bounds__(128) void gate_mix_kernel(
    const float* __restrict__ hmat, const float* __restrict__ gW, const float* __restrict__ gb,
    const float* __restrict__ attn, const float* __restrict__ ret, float* __restrict__ x)
{
    __shared__ float red0[128], red2[128];
    __shared__ float gg0, gg2;
    const int tkn = blockIdx.x, tid = threadIdx.x;
    const float* hrow = hmat + (size_t)tkn * C_;
    float p0 = 0.f, p2 = 0.f;
    for (int c = tid; c < C_; c += 128) {
        const float hv = hrow[c];
        p0 = fmaf(hv, gW[c * 3 + 0], p0);
        p2 = fmaf(hv, gW[c * 3 + 2], p2);
    }
    red0[tid] = p0; red2[tid] = p2; __syncthreads();
    for (int s = 64; s; s >>= 1) {
        if (tid < s) { red0[tid] += red0[tid + s]; red2[tid] += red2[tid + s]; }
        __syncthreads();
    }
    if (tid == 0) {
        const float l0 = red0[0] + gb[0];
        const float l2 = red2[0] + gb[2];
        const float m  = fmaxf(l0, l2);
        const float e0 = expf(l0 - m);
        const float e1 = expf(NEG_ - m);
        const float e2 = expf(l2 - m);
        const float inv = 1.f / (e0 + e1 + e2);
        gg0 = e0 * inv; gg2 = e2 * inv;
    }
    __syncthreads();
    const float a0 = gg0, a2 = gg2;
    const int b = tkn / T_;
    float* xrow = x + (size_t)tkn * C_;
    const float* arow = attn + (size_t)tkn * C_;
    for (int c = tid; c < C_; c += 128)
        xrow[c] += a0 * arow[c] + a2 * ret[b * C_ + c];
}

// ---------------------------------------------------------------------------
// SwiGLU elementwise
// ---------------------------------------------------------------------------
__global__ __launch_bounds__(256) void silu_mul_kernel(
    float* __restrict__ f1, const float* __restrict__ f2, int n)
{
    for (int i = blockIdx.x * blockDim.x + threadIdx.x; i < n; i += gridDim.x * blockDim.x) {
        const float a = f1[i];
        const float s = a / (1.f + expf(-a));
        f1[i] = s * f2[i];
    }
}

// ---------------------------------------------------------------------------
// Launcher
// ---------------------------------------------------------------------------
extern "C" void kernel_launch(void* const* d_in, const int* in_sizes, int n_in,
                              void* d_out, int out_size)
{
    (void)in_sizes; (void)n_in; (void)out_size;
    const float* x    = (const float*)d_in[0];
    const float* rc   = (const float*)d_in[1];
    const float* n1g  = (const float*)d_in[2];
    const float* Wqkv = (const float*)d_in[3];
    const float* Wpro = (const float*)d_in[4];
    const float* gW   = (const float*)d_in[5];
    const float* gb   = (const float*)d_in[6];
    const float* retW = (const float*)d_in[7];
    const float* n2g  = (const float*)d_in[8];
    const float* fgW  = (const float*)d_in[9];
    const float* fuW  = (const float*)d_in[10];
    const float* fdW  = (const float*)d_in[11];
    float* xo = (float*)d_out;

    float *pH, *pH2, *pQKV, *pO, *pA, *pF1, *pF2, *pR;
    cudaGetSymbolAddress((void**)&pH,   g_h);
    cudaGetSymbolAddress((void**)&pH2,  g_h2);
    cudaGetSymbolAddress((void**)&pQKV, g_qkv);
    cudaGetSymbolAddress((void**)&pO,   g_o);
    cudaGetSymbolAddress((void**)&pA,   g_attn);
    cudaGetSymbolAddress((void**)&pF1,  g_f1);
    cudaGetSymbolAddress((void**)&pF2,  g_f2);
    cudaGetSymbolAddress((void**)&pR,   g_ret);

    cudaFuncSetAttribute(attn_kernel, cudaFuncAttributeMaxDynamicSharedMemorySize, ATT_SMEM);
    cudaFuncSetAttribute(gemm_tf32_v3, cudaFuncAttributeMaxDynamicSharedMemorySize, GEMM3_SMEM);

    cudaMemcpyAsync(xo, x, sizeof(float) * (size_t)M_ * C_, cudaMemcpyDeviceToDevice);

    for (int l = 0; l < L_; l++) {
        rmsnorm_kernel<<<M_, 128>>>(xo, n1g + l * C_, pH);

        gemm_tf32_v3<<<dim3(3 * C_ / 128, M_ / 128), 256, GEMM3_SMEM>>>(
            pH, Wqkv + (size_t)l * C_ * 3 * C_, pQKV, 3 * C_, C_, 0);

        attn_kernel<<<dim3(T_ / 64, H_, B_), 256, ATT_SMEM>>>(pQKV, pO);

        gemm_tf32_v3<<<dim3(C_ / 128, M_ / 128), 256, GEMM3_SMEM>>>(
            pO, Wpro + (size_t)l * C_ * C_, pA, C_, C_, 0);

        ret_kernel<<<dim3(C_ / 256, B_), 256>>>(rc, retW + (size_t)l * C_ * C_, pR);

        gate_mix_kernel<<<M_, 128>>>(pH, gW + (size_t)l * C_ * 3, gb + l * 3, pA, pR, xo);

        rmsnorm_kernel<<<M_, 128>>>(xo, n2g + l * C_, pH2);

        gemm_tf32_v3<<<dim3(F_ / 128, M_ / 128), 256, GEMM3_SMEM>>>(
            pH2, fgW + (size_t)l * C_ * F_, pF1, F_, C_, 0);
        gemm_tf32_v3<<<dim3(F_ / 128, M_ / 128), 256, GEMM3_SMEM>>>(
            pH2, fuW + (size_t)l * C_ * F_, pF2, F_, C_, 0);

        silu_mul_kernel<<<4096, 256>>>(pF1, pF2, M_ * F_);

        gemm_tf32_v3<<<dim3(C_ / 128, M_ / 128), 256, GEMM3_SMEM>>>(
            pF1, fdW + (size_t)l * F_ * C_, xo, C_, F_, 1 /*accumulate*/);
    }
}

// round 6
// speedup vs baseline: 2.8295x; 1.0646x over previous
#include <cuda_runtime.h>
#include <math.h>
#include <stdint.h>

// Problem constants
#define L_ 2
#define B_ 2
#define T_ 2048
#define C_ 1024
#define H_ 16
#define D_ 64
#define F_ 4096
#define WIN_ 256
#define M_ (B_*T_)   // 4096 tokens
#define NEG_ (-1e9f)

// ---------------------------------------------------------------------------
// Scratch
// ---------------------------------------------------------------------------
__device__ float g_h  [M_*C_];
__device__ float g_h2 [M_*C_];
__device__ float g_qkv[M_*3*C_];
__device__ float g_o  [M_*C_];
__device__ float g_attn[M_*C_];
__device__ float g_f1 [M_*F_];
__device__ float g_f2 [M_*F_];
__device__ float g_ret[B_*C_];
// tf32-pre-rounded weights (per layer: qkv | proj | gate | up | down)
#define WR_L   16777216           // floats per layer
#define WR_QKV 0
#define WR_PROJ 3145728
#define WR_GATE 4194304
#define WR_UP   8388608
#define WR_DOWN 12582912
__device__ float g_wr[L_ * WR_L];

__device__ __forceinline__ float rnd_tf32(float f) {
    uint32_t u;
    asm("cvt.rna.tf32.f32 %0, %1;" : "=r"(u) : "f"(f));
    return __uint_as_float(u);
}

// ---------------------------------------------------------------------------
// Weight pre-rounding (once per launch; graph-capturable, deterministic)
// ---------------------------------------------------------------------------
__global__ __launch_bounds__(256) void round_tf32_copy(
    const float* __restrict__ src, float* __restrict__ dst, int n)
{
    int i = blockIdx.x * 256 + threadIdx.x;
    const int stride = gridDim.x * 256;
    for (; i < n; i += stride) dst[i] = rnd_tf32(src[i]);
}

// ---------------------------------------------------------------------------
// RMSNorm (output pre-rounded to tf32 grid: it is always a GEMM A operand)
// ---------------------------------------------------------------------------
__global__ __launch_bounds__(128) void rmsnorm_kernel(
    const float* __restrict__ x, const float* __restrict__ g, float* __restrict__ out)
{
    __shared__ float red[128];
    __shared__ float rinv;
    const int tkn = blockIdx.x, tid = threadIdx.x;
    const float* row = x + (size_t)tkn * C_;
    float ss = 0.f;
    #pragma unroll
    for (int c = tid; c < C_; c += 128) { float v = row[c]; ss += v * v; }
    red[tid] = ss; __syncthreads();
    for (int s = 64; s; s >>= 1) { if (tid < s) red[tid] += red[tid + s]; __syncthreads(); }
    if (tid == 0) rinv = rsqrtf(red[0] * (1.0f / C_) + 1e-6f);
    __syncthreads();
    const float r = rinv;
    float* orow = out + (size_t)tkn * C_;
    #pragma unroll
    for (int c = tid; c < C_; c += 128) orow[c] = rnd_tf32(row[c] * r * g[c]);
}

// ---------------------------------------------------------------------------
// TF32 tensor-core GEMM v4.
// 128x128x32 / 256 threads / 2 blocks/SM / 3-stage cp.async.
// NO cvt in the hot loop: operands are pre-rounded by producers.
// ---------------------------------------------------------------------------
__device__ __forceinline__ void mma_tf32(float c[4], const uint32_t a[4], const uint32_t b[2]) {
    asm volatile(
        "mma.sync.aligned.m16n8k8.row.col.f32.tf32.tf32.f32 "
        "{%0,%1,%2,%3}, {%4,%5,%6,%7}, {%8,%9}, {%0,%1,%2,%3};\n"
        : "+f"(c[0]), "+f"(c[1]), "+f"(c[2]), "+f"(c[3])
        : "r"(a[0]), "r"(a[1]), "r"(a[2]), "r"(a[3]), "r"(b[0]), "r"(b[1]));
}

#define APAD3 36
#define BPAD3 136
#define ASTG3 (128*APAD3)
#define BSTG3 (32*BPAD3)
#define STG3  (ASTG3 + BSTG3)
#define GEMM3_SMEM (3 * STG3 * 4)

__device__ __forceinline__ void cp16(void* dst, const void* src) {
    uint32_t d = (uint32_t)__cvta_generic_to_shared(dst);
    asm volatile("cp.async.cg.shared.global [%0], [%1], 16;\n" :: "r"(d), "l"(src));
}

__global__ void __launch_bounds__(256, 2) gemm_tf32_v4(
    const float* __restrict__ A, const float* __restrict__ Bm, float* __restrict__ Cm,
    int Nd, int Kd, int addTo)
{
    extern __shared__ float smv[];
    #define ASM_(s,m,k)  smv[(s)*STG3 + (m)*APAD3 + (k)]
    #define BSM_(s,kr,n) smv[(s)*STG3 + ASTG3 + (kr)*BPAD3 + (n)]

    const int t = threadIdx.x;
    const int w = t >> 5, lane = t & 31;
    const int r = lane >> 2, c = lane & 3;
    const int mb = (w >> 2) * 64;
    const int nb = (w & 3) * 32;
    const int bm = blockIdx.y * 128, bn = blockIdx.x * 128;

    const int ar = t >> 3, ak = (t & 7) * 4;
    const int br = t >> 5, bn0 = (t & 31) * 4;
    const float* Ag = A  + (size_t)(bm + ar) * Kd + ak;
    const float* Bg = Bm + (size_t)bn + bn0;

    float acc[16][4];
    #pragma unroll
    for (int i = 0; i < 16; i++)
        #pragma unroll
        for (int j = 0; j < 4; j++) acc[i][j] = 0.f;

    const int niter = Kd >> 5;

    #pragma unroll
    for (int p = 0; p < 2; p++) {
        const int kt = p << 5;
        #pragma unroll
        for (int i = 0; i < 4; i++)
            cp16(&ASM_(p, ar + 32 * i, ak), Ag + (size_t)(32 * i) * Kd + kt);
        #pragma unroll
        for (int i = 0; i < 4; i++)
            cp16(&BSM_(p, br + 8 * i, bn0), Bg + (size_t)(kt + br + 8 * i) * Nd);
        asm volatile("cp.async.commit_group;\n");
    }

    int st = 0;
    for (int it = 0; it < niter; it++) {
        asm volatile("cp.async.wait_group 1;\n");
        __syncthreads();

        if (it + 2 < niter) {
            const int ps = (st + 2) % 3;
            const int kt = (it + 2) << 5;
            #pragma unroll
            for (int i = 0; i < 4; i++)
                cp16(&ASM_(ps, ar + 32 * i, ak), Ag + (size_t)(32 * i) * Kd + kt);
            #pragma unroll
            for (int i = 0; i < 4; i++)
                cp16(&BSM_(ps, br + 8 * i, bn0), Bg + (size_t)(kt + br + 8 * i) * Nd);
        }
        asm volatile("cp.async.commit_group;\n");

        #pragma unroll
        for (int kh = 0; kh < 32; kh += 8) {
            uint32_t af[4][4], bf[4][2];
            #pragma unroll
            for (int mt = 0; mt < 4; mt++) {
                const int m0 = mb + mt * 16 + r;
                af[mt][0] = __float_as_uint(ASM_(st, m0,     kh + c));
                af[mt][1] = __float_as_uint(ASM_(st, m0 + 8, kh + c));
                af[mt][2] = __float_as_uint(ASM_(st, m0,     kh + c + 4));
                af[mt][3] = __float_as_uint(ASM_(st, m0 + 8, kh + c + 4));
            }
            #pragma unroll
            for (int nt = 0; nt < 4; nt++) {
                const int n0 = nb + nt * 8 + r;
                bf[nt][0] = __float_as_uint(BSM_(st, kh + c,     n0));
                bf[nt][1] = __float_as_uint(BSM_(st, kh + c + 4, n0));
            }
            #pragma unroll
            for (int mt = 0; mt < 4; mt++)
                #pragma unroll
                for (int nt = 0; nt < 4; nt++)
                    mma_tf32(acc[mt * 4 + nt], af[mt], bf[nt]);
        }

        st = (st + 1) % 3;
    }

    #pragma unroll
    for (int mt = 0; mt < 4; mt++) {
        #pragma unroll
        for (int nt = 0; nt < 4; nt++) {
            const float* a4 = acc[mt * 4 + nt];
            float* p0 = Cm + (size_t)(bm + mb + mt * 16 + r) * Nd + bn + nb + nt * 8 + c * 2;
            float* p1 = p0 + 8 * (size_t)Nd;
            if (addTo) {
                float2 v0 = *(float2*)p0;
                float2 v1 = *(float2*)p1;
                v0.x += a4[0]; v0.y += a4[1];
                v1.x += a4[2]; v1.y += a4[3];
                *(float2*)p0 = v0;
                *(float2*)p1 = v1;
            } else {
                *(float2*)p0 = make_float2(a4[0], a4[1]);
                *(float2*)p1 = make_float2(a4[2], a4[3]);
            }
        }
    }
    #undef ASM_
    #undef BSM_
}

// ---------------------------------------------------------------------------
// Sliding-window attention (output pre-rounded: it is the proj GEMM A operand)
// ---------------------------------------------------------------------------
#define ATT_SP 324
#define ATT_SMEM ((2*64*65 + 64*ATT_SP) * 4)

__global__ __launch_bounds__(256) void attn_kernel(
    const float* __restrict__ qkv, float* __restrict__ o)
{
    extern __shared__ float sm[];
    float* Qs = sm;
    float* KV = sm + 64 * 65;
    float* S  = sm + 2 * 64 * 65;

    const int q0 = blockIdx.x * 64;
    const int h  = blockIdx.y;
    const int b  = blockIdx.z;
    const int t  = threadIdx.x;
    const int tx = t & 15, ty = t >> 4;
    const int r0 = ty * 4, c0 = tx * 4;
    const float scale = 0.125f;

    for (int e = t; e < 64 * 16; e += 256) {
        const int q = e >> 4, dg = (e & 15) * 4;
        const float4 v = *(const float4*)(qkv + ((size_t)(b * T_ + q0 + q)) * (3 * C_) + h * D_ + dg);
        Qs[q * 65 + dg + 0] = v.x; Qs[q * 65 + dg + 1] = v.y;
        Qs[q * 65 + dg + 2] = v.z; Qs[q * 65 + dg + 3] = v.w;
    }

    for (int it = 0; it < 5; it++) {
        const int kb = q0 + (it - 4) * 64;
        if (kb < 0) {
            #pragma unroll
            for (int i = 0; i < 4; i++)
                #pragma unroll
                for (int j = 0; j < 4; j++)
                    S[(r0 + i) * ATT_SP + it * 64 + c0 + j] = -1e30f;
            continue;
        }
        __syncthreads();
        for (int e = t; e < 64 * 16; e += 256) {
            const int r = e >> 4, dg = (e & 15) * 4;
            const float4 v = *(const float4*)(qkv + ((size_t)(b * T_ + kb + r)) * (3 * C_) + C_ + h * D_ + dg);
            KV[r * 65 + dg + 0] = v.x; KV[r * 65 + dg + 1] = v.y;
            KV[r * 65 + dg + 2] = v.z; KV[r * 65 + dg + 3] = v.w;
        }
        __syncthreads();
        float acc[4][4];
        #pragma unroll
        for (int i = 0; i < 4; i++)
            #pragma unroll
            for (int j = 0; j < 4; j++) acc[i][j] = 0.f;
        #pragma unroll 4
        for (int kk = 0; kk < 64; kk++) {
            float a[4], bb[4];
            #pragma unroll
            for (int i = 0; i < 4; i++) a[i]  = Qs[(r0 + i) * 65 + kk];
            #pragma unroll
            for (int j = 0; j < 4; j++) bb[j] = KV[(c0 + j) * 65 + kk];
            #pragma unroll
            for (int i = 0; i < 4; i++)
                #pragma unroll
                for (int j = 0; j < 4; j++) acc[i][j] = fmaf(a[i], bb[j], acc[i][j]);
        }
        #pragma unroll
        for (int i = 0; i < 4; i++) {
            const int ig = q0 + r0 + i;
            #pragma unroll
            for (int j = 0; j < 4; j++) {
                const int jg = kb + c0 + j;
                const bool ok = (jg <= ig) && (jg >= ig - (WIN_ - 1));
                S[(r0 + i) * ATT_SP + it * 64 + c0 + j] = ok ? acc[i][j] * scale : -1e30f;
            }
        }
    }
    __syncthreads();

    {
        const int wid = t >> 5, lane = t & 31;
        for (int rr = 0; rr < 8; rr++) {
            const int r = wid * 8 + rr;
            float m = -1e30f;
            for (int c = lane; c < 320; c += 32) m = fmaxf(m, S[r * ATT_SP + c]);
            #pragma unroll
            for (int off = 16; off; off >>= 1) m = fmaxf(m, __shfl_xor_sync(0xffffffffu, m, off));
            float sum = 0.f;
            for (int c = lane; c < 320; c += 32) {
                const float p = expf(S[r * ATT_SP + c] - m);
                S[r * ATT_SP + c] = p;
                sum += p;
            }
            #pragma unroll
            for (int off = 16; off; off >>= 1) sum += __shfl_xor_sync(0xffffffffu, sum, off);
            const float inv = 1.f / sum;
            for (int c = lane; c < 320; c += 32) S[r * ATT_SP + c] *= inv;
        }
    }

    float oacc[4][4];
    #pragma unroll
    for (int i = 0; i < 4; i++)
        #pragma unroll
        for (int j = 0; j < 4; j++) oacc[i][j] = 0.f;

    for (int it = 0; it < 5; it++) {
        const int kb = q0 + (it - 4) * 64;
        if (kb < 0) continue;
        __syncthreads();
        for (int e = t; e < 64 * 16; e += 256) {
            const int r = e >> 4, dg = (e & 15) * 4;
            const float4 v = *(const float4*)(qkv + ((size_t)(b * T_ + kb + r)) * (3 * C_) + 2 * C_ + h * D_ + dg);
            KV[r * 65 + dg + 0] = v.x; KV[r * 65 + dg + 1] = v.y;
            KV[r * 65 + dg + 2] = v.z; KV[r * 65 + dg + 3] = v.w;
        }
        __syncthreads();
        #pragma unroll 4
        for (int kk = 0; kk < 64; kk++) {
            float a[4], bb[4];
            #pragma unroll
            for (int i = 0; i < 4; i++) a[i]  = S[(r0 + i) * ATT_SP + it * 64 + kk];
            #pragma unroll
            for (int j = 0; j < 4; j++) bb[j] = KV[kk * 65 + c0 + j];
            #pragma unroll
            for (int i = 0; i < 4; i++)
                #pragma unroll
                for (int j = 0; j < 4; j++) oacc[i][j] = fmaf(a[i], bb[j], oacc[i][j]);
        }
    }
    #pragma unroll
    for (int i = 0; i < 4; i++)
        #pragma unroll
        for (int j = 0; j < 4; j++)
            o[((size_t)(b * T_ + q0 + r0 + i)) * C_ + h * D_ + c0 + j] = rnd_tf32(oacc[i][j]);
}

// ---------------------------------------------------------------------------
// Retrieval projection
// ---------------------------------------------------------------------------
__global__ __launch_bounds__(256) void ret_kernel(
    const float* __restrict__ rc, const float* __restrict__ retW, float* __restrict__ ret)
{
    const int c = blockIdx.x * 256 + threadIdx.x;
    const int b = blockIdx.y;
    float acc = 0.f;
    for (int k = 0; k < C_; k++) acc = fmaf(rc[b * C_ + k], retW[(size_t)k * C_ + c], acc);
    ret[b * C_ + c] = acc;
}

// ---------------------------------------------------------------------------
// Gate + mix
// ---------------------------------------------------------------------------
__global__ __launch_bounds__(128) void gate_mix_kernel(
    const float* __restrict__ hmat, const float* __restrict__ gW, const float* __restrict__ gb,
    const float* __restrict__ attn, const float* __restrict__ ret, float* __restrict__ x)
{
    __shared__ float red0[128], red2[128];
    __shared__ float gg0, gg2;
    const int tkn = blockIdx.x, tid = threadIdx.x;
    const float* hrow = hmat + (size_t)tkn * C_;
    float p0 = 0.f, p2 = 0.f;
    for (int c = tid; c < C_; c += 128) {
        const float hv = hrow[c];
        p0 = fmaf(hv, gW[c * 3 + 0], p0);
        p2 = fmaf(hv, gW[c * 3 + 2], p2);
    }
    red0[tid] = p0; red2[tid] = p2; __syncthreads();
    for (int s = 64; s; s >>= 1) {
        if (tid < s) { red0[tid] += red0[tid + s]; red2[tid] += red2[tid + s]; }
        __syncthreads();
    }
    if (tid == 0) {
        const float l0 = red0[0] + gb[0];
        const float l2 = red2[0] + gb[2];
        const float m  = fmaxf(l0, l2);
        const float e0 = expf(l0 - m);
        const float e1 = expf(NEG_ - m);
        const float e2 = expf(l2 - m);
        const float inv = 1.f / (e0 + e1 + e2);
        gg0 = e0 * inv; gg2 = e2 * inv;
    }
    __syncthreads();
    const float a0 = gg0, a2 = gg2;
    const int b = tkn / T_;
    float* xrow = x + (size_t)tkn * C_;
    const float* arow = attn + (size_t)tkn * C_;
    for (int c = tid; c < C_; c += 128)
        xrow[c] += a0 * arow[c] + a2 * ret[b * C_ + c];
}

// ---------------------------------------------------------------------------
// SwiGLU elementwise (output pre-rounded: it is the down-GEMM A operand)
// ---------------------------------------------------------------------------
__global__ __launch_bounds__(256) void silu_mul_kernel(
    float* __restrict__ f1, const float* __restrict__ f2, int n)
{
    for (int i = blockIdx.x * blockDim.x + threadIdx.x; i < n; i += gridDim.x * blockDim.x) {
        const float a = f1[i];
        const float s = a / (1.f + expf(-a));
        f1[i] = rnd_tf32(s * f2[i]);
    }
}

// ---------------------------------------------------------------------------
// Launcher
// ---------------------------------------------------------------------------
extern "C" void kernel_launch(void* const* d_in, const int* in_sizes, int n_in,
                              void* d_out, int out_size)
{
    (void)in_sizes; (void)n_in; (void)out_size;
    const float* x    = (const float*)d_in[0];
    const float* rc   = (const float*)d_in[1];
    const float* n1g  = (const float*)d_in[2];
    const float* Wqkv = (const float*)d_in[3];
    const float* Wpro = (const float*)d_in[4];
    const float* gW   = (const float*)d_in[5];
    const float* gb   = (const float*)d_in[6];
    const float* retW = (const float*)d_in[7];
    const float* n2g  = (const float*)d_in[8];
    const float* fgW  = (const float*)d_in[9];
    const float* fuW  = (const float*)d_in[10];
    const float* fdW  = (const float*)d_in[11];
    float* xo = (float*)d_out;

    float *pH, *pH2, *pQKV, *pO, *pA, *pF1, *pF2, *pR, *pWR;
    cudaGetSymbolAddress((void**)&pH,   g_h);
    cudaGetSymbolAddress((void**)&pH2,  g_h2);
    cudaGetSymbolAddress((void**)&pQKV, g_qkv);
    cudaGetSymbolAddress((void**)&pO,   g_o);
    cudaGetSymbolAddress((void**)&pA,   g_attn);
    cudaGetSymbolAddress((void**)&pF1,  g_f1);
    cudaGetSymbolAddress((void**)&pF2,  g_f2);
    cudaGetSymbolAddress((void**)&pR,   g_ret);
    cudaGetSymbolAddress((void**)&pWR,  g_wr);

    cudaFuncSetAttribute(attn_kernel, cudaFuncAttributeMaxDynamicSharedMemorySize, ATT_SMEM);
    cudaFuncSetAttribute(gemm_tf32_v4, cudaFuncAttributeMaxDynamicSharedMemorySize, GEMM3_SMEM);

    // One-time weight pre-rounding into scratch (tf32 grid)
    for (int l = 0; l < L_; l++) {
        float* base = pWR + (size_t)l * WR_L;
        round_tf32_copy<<<1184, 256>>>(Wqkv + (size_t)l * 3 * C_ * C_, base + WR_QKV, 3 * C_ * C_);
        round_tf32_copy<<<1184, 256>>>(Wpro + (size_t)l * C_ * C_,     base + WR_PROJ, C_ * C_);
        round_tf32_copy<<<1184, 256>>>(fgW  + (size_t)l * C_ * F_,     base + WR_GATE, C_ * F_);
        round_tf32_copy<<<1184, 256>>>(fuW  + (size_t)l * C_ * F_,     base + WR_UP,   C_ * F_);
        round_tf32_copy<<<1184, 256>>>(fdW  + (size_t)l * F_ * C_,     base + WR_DOWN, F_ * C_);
    }

    cudaMemcpyAsync(xo, x, sizeof(float) * (size_t)M_ * C_, cudaMemcpyDeviceToDevice);

    for (int l = 0; l < L_; l++) {
        float* base = pWR + (size_t)l * WR_L;

        rmsnorm_kernel<<<M_, 128>>>(xo, n1g + l * C_, pH);

        gemm_tf32_v4<<<dim3(3 * C_ / 128, M_ / 128), 256, GEMM3_SMEM>>>(
            pH, base + WR_QKV, pQKV, 3 * C_, C_, 0);

        attn_kernel<<<dim3(T_ / 64, H_, B_), 256, ATT_SMEM>>>(pQKV, pO);

        gemm_tf32_v4<<<dim3(C_ / 128, M_ / 128), 256, GEMM3_SMEM>>>(
            pO, base + WR_PROJ, pA, C_, C_, 0);

        ret_kernel<<<dim3(C_ / 256, B_), 256>>>(rc, retW + (size_t)l * C_ * C_, pR);

        gate_mix_kernel<<<M_, 128>>>(pH, gW + (size_t)l * C_ * 3, gb + l * 3, pA, pR, xo);

        rmsnorm_kernel<<<M_, 128>>>(xo, n2g + l * C_, pH2);

        gemm_tf32_v4<<<dim3(F_ / 128, M_ / 128), 256, GEMM3_SMEM>>>(
            pH2, base + WR_GATE, pF1, F_, C_, 0);
        gemm_tf32_v4<<<dim3(F_ / 128, M_ / 128), 256, GEMM3_SMEM>>>(
            pH2, base + WR_UP, pF2, F_, C_, 0);

        silu_mul_kernel<<<4096, 256>>>(pF1, pF2, M_ * F_);

        gemm_tf32_v4<<<dim3(C_ / 128, M_ / 128), 256, GEMM3_SMEM>>>(
            pF1, base + WR_DOWN, xo, C_, F_, 1 /*accumulate*/);
    }
}

// round 7
// speedup vs baseline: 2.8915x; 1.0219x over previous
#include <cuda_runtime.h>
#include <math.h>
#include <stdint.h>

// Problem constants
#define L_ 2
#define B_ 2
#define T_ 2048
#define C_ 1024
#define H_ 16
#define D_ 64
#define F_ 4096
#define WIN_ 256
#define M_ (B_*T_)   // 4096 tokens
#define NEG_ (-1e9f)

// ---------------------------------------------------------------------------
// Scratch
// ---------------------------------------------------------------------------
__device__ float g_h  [M_*C_];
__device__ float g_h2 [M_*C_];
__device__ float g_qkv[M_*3*C_];
__device__ float g_o  [M_*C_];
__device__ float g_attn[M_*C_];
__device__ float g_f1 [M_*F_];
__device__ float g_f2 [M_*F_];
__device__ float g_ret[B_*C_];
// tf32-pre-rounded weights (per layer: qkv | proj | gate | up | down)
#define WR_L   16777216           // floats per layer
#define WR_QKV 0
#define WR_PROJ 3145728
#define WR_GATE 4194304
#define WR_UP   8388608
#define WR_DOWN 12582912
__device__ float g_wr[L_ * WR_L];

__device__ __forceinline__ float rnd_tf32(float f) {
    uint32_t u;
    asm("cvt.rna.tf32.f32 %0, %1;" : "=r"(u) : "f"(f));
    return __uint_as_float(u);
}

// ---------------------------------------------------------------------------
// Weight pre-rounding (runs every launch; deterministic)
// ---------------------------------------------------------------------------
__global__ __launch_bounds__(256) void round_tf32_copy(
    const float* __restrict__ src, float* __restrict__ dst, int n)
{
    int i = blockIdx.x * 256 + threadIdx.x;
    const int stride = gridDim.x * 256;
    for (; i < n; i += stride) dst[i] = rnd_tf32(src[i]);
}

// ---------------------------------------------------------------------------
// RMSNorm (output pre-rounded to tf32 grid)
// ---------------------------------------------------------------------------
__global__ __launch_bounds__(128) void rmsnorm_kernel(
    const float* __restrict__ x, const float* __restrict__ g, float* __restrict__ out)
{
    __shared__ float red[128];
    __shared__ float rinv;
    const int tkn = blockIdx.x, tid = threadIdx.x;
    const float* row = x + (size_t)tkn * C_;
    float ss = 0.f;
    #pragma unroll
    for (int c = tid; c < C_; c += 128) { float v = row[c]; ss += v * v; }
    red[tid] = ss; __syncthreads();
    for (int s = 64; s; s >>= 1) { if (tid < s) red[tid] += red[tid + s]; __syncthreads(); }
    if (tid == 0) rinv = rsqrtf(red[0] * (1.0f / C_) + 1e-6f);
    __syncthreads();
    const float r = rinv;
    float* orow = out + (size_t)tkn * C_;
    #pragma unroll
    for (int c = tid; c < C_; c += 128) orow[c] = rnd_tf32(row[c] * r * g[c]);
}

// ---------------------------------------------------------------------------
// TF32 tensor-core GEMM v5: A fragments via ldmatrix.x4 (4x fewer A-side LDS).
// 128x128x32 block tile / 256 threads / 2 blocks/SM / 3-stage cp.async.
// Operands pre-rounded by producers; no cvt in hot loop.
// ---------------------------------------------------------------------------
__device__ __forceinline__ void mma_tf32(float c[4], const uint32_t a[4], const uint32_t b[2]) {
    asm volatile(
        "mma.sync.aligned.m16n8k8.row.col.f32.tf32.tf32.f32 "
        "{%0,%1,%2,%3}, {%4,%5,%6,%7}, {%8,%9}, {%0,%1,%2,%3};\n"
        : "+f"(c[0]), "+f"(c[1]), "+f"(c[2]), "+f"(c[3])
        : "r"(a[0]), "r"(a[1]), "r"(a[2]), "r"(a[3]), "r"(b[0]), "r"(b[1]));
}

__device__ __forceinline__ void ldsm_x4(uint32_t f[4], uint32_t addr) {
    asm volatile(
        "ldmatrix.sync.aligned.m8n8.x4.shared.b16 {%0,%1,%2,%3}, [%4];\n"
        : "=r"(f[0]), "=r"(f[1]), "=r"(f[2]), "=r"(f[3]) : "r"(addr));
}

#define APAD3 36
#define BPAD3 136
#define ASTG3 (128*APAD3)
#define BSTG3 (32*BPAD3)
#define STG3  (ASTG3 + BSTG3)
#define GEMM3_SMEM (3 * STG3 * 4)

__device__ __forceinline__ void cp16(void* dst, const void* src) {
    uint32_t d = (uint32_t)__cvta_generic_to_shared(dst);
    asm volatile("cp.async.cg.shared.global [%0], [%1], 16;\n" :: "r"(d), "l"(src));
}

__global__ void __launch_bounds__(256, 2) gemm_tf32_v5(
    const float* __restrict__ A, const float* __restrict__ Bm, float* __restrict__ Cm,
    int Nd, int Kd, int addTo)
{
    extern __shared__ float smv[];
    #define ASM_(s,m,k)  smv[(s)*STG3 + (m)*APAD3 + (k)]
    #define BSM_(s,kr,n) smv[(s)*STG3 + ASTG3 + (kr)*BPAD3 + (n)]

    const int t = threadIdx.x;
    const int w = t >> 5, lane = t & 31;
    const int r = lane >> 2, c = lane & 3;
    const int mb = (w >> 2) * 64;
    const int nb = (w & 3) * 32;
    const int bm = blockIdx.y * 128, bn = blockIdx.x * 128;

    // ldmatrix per-thread tile offsets: tiles (m0,k),(m0+8,k),(m0,k+4),(m0+8,k+4)
    const int offm = (lane & 7) + ((lane >> 3) & 1) * 8;
    const int offk = (lane >> 4) * 4;

    const int ar = t >> 3, ak = (t & 7) * 4;
    const int br = t >> 5, bn0 = (t & 31) * 4;
    const float* Ag = A  + (size_t)(bm + ar) * Kd + ak;
    const float* Bg = Bm + (size_t)bn + bn0;

    float acc[16][4];
    #pragma unroll
    for (int i = 0; i < 16; i++)
        #pragma unroll
        for (int j = 0; j < 4; j++) acc[i][j] = 0.f;

    const int niter = Kd >> 5;

    #pragma unroll
    for (int p = 0; p < 2; p++) {
        const int kt = p << 5;
        #pragma unroll
        for (int i = 0; i < 4; i++)
            cp16(&ASM_(p, ar + 32 * i, ak), Ag + (size_t)(32 * i) * Kd + kt);
        #pragma unroll
        for (int i = 0; i < 4; i++)
            cp16(&BSM_(p, br + 8 * i, bn0), Bg + (size_t)(kt + br + 8 * i) * Nd);
        asm volatile("cp.async.commit_group;\n");
    }

    int st = 0;
    for (int it = 0; it < niter; it++) {
        asm volatile("cp.async.wait_group 1;\n");
        __syncthreads();

        if (it + 2 < niter) {
            const int ps = (st + 2) % 3;
            const int kt = (it + 2) << 5;
            #pragma unroll
            for (int i = 0; i < 4; i++)
                cp16(&ASM_(ps, ar + 32 * i, ak), Ag + (size_t)(32 * i) * Kd + kt);
            #pragma unroll
            for (int i = 0; i < 4; i++)
                cp16(&BSM_(ps, br + 8 * i, bn0), Bg + (size_t)(kt + br + 8 * i) * Nd);
        }
        asm volatile("cp.async.commit_group;\n");

        // shared-space base address of this stage's A region (for ldmatrix)
        const uint32_t abase =
            (uint32_t)__cvta_generic_to_shared(&smv[st * STG3]);

        #pragma unroll
        for (int kh = 0; kh < 32; kh += 8) {
            uint32_t af[4][4], bf[4][2];
            #pragma unroll
            for (int mt = 0; mt < 4; mt++) {
                const uint32_t aaddr = abase +
                    (((mb + mt * 16 + offm) * APAD3 + kh + offk) << 2);
                ldsm_x4(af[mt], aaddr);
            }
            #pragma unroll
            for (int nt = 0; nt < 4; nt++) {
                const int n0 = nb + nt * 8 + r;
                bf[nt][0] = __float_as_uint(BSM_(st, kh + c,     n0));
                bf[nt][1] = __float_as_uint(BSM_(st, kh + c + 4, n0));
            }
            #pragma unroll
            for (int mt = 0; mt < 4; mt++)
                #pragma unroll
                for (int nt = 0; nt < 4; nt++)
                    mma_tf32(acc[mt * 4 + nt], af[mt], bf[nt]);
        }

        st = (st + 1) % 3;
    }

    #pragma unroll
    for (int mt = 0; mt < 4; mt++) {
        #pragma unroll
        for (int nt = 0; nt < 4; nt++) {
            const float* a4 = acc[mt * 4 + nt];
            float* p0 = Cm + (size_t)(bm + mb + mt * 16 + r) * Nd + bn + nb + nt * 8 + c * 2;
            float* p1 = p0 + 8 * (size_t)Nd;
            if (addTo) {
                float2 v0 = *(float2*)p0;
                float2 v1 = *(float2*)p1;
                v0.x += a4[0]; v0.y += a4[1];
                v1.x += a4[2]; v1.y += a4[3];
                *(float2*)p0 = v0;
                *(float2*)p1 = v1;
            } else {
                *(float2*)p0 = make_float2(a4[0], a4[1]);
                *(float2*)p1 = make_float2(a4[2], a4[3]);
            }
        }
    }
    #undef ASM_
    #undef BSM_
}

// ---------------------------------------------------------------------------
// Sliding-window attention (output pre-rounded)
// ---------------------------------------------------------------------------
#define ATT_SP 324
#define ATT_SMEM ((2*64*65 + 64*ATT_SP) * 4)

__global__ __launch_bounds__(256) void attn_kernel(
    const float* __restrict__ qkv, float* __restrict__ o)
{
    extern __shared__ float sm[];
    float* Qs = sm;
    float* KV = sm + 64 * 65;
    float* S  = sm + 2 * 64 * 65;

    const int q0 = blockIdx.x * 64;
    const int h  = blockIdx.y;
    const int b  = blockIdx.z;
    const int t  = threadIdx.x;
    const int tx = t & 15, ty = t >> 4;
    const int r0 = ty * 4, c0 = tx * 4;
    const float scale = 0.125f;

    for (int e = t; e < 64 * 16; e += 256) {
        const int q = e >> 4, dg = (e & 15) * 4;
        const float4 v = *(const float4*)(qkv + ((size_t)(b * T_ + q0 + q)) * (3 * C_) + h * D_ + dg);
        Qs[q * 65 + dg + 0] = v.x; Qs[q * 65 + dg + 1] = v.y;
        Qs[q * 65 + dg + 2] = v.z; Qs[q * 65 + dg + 3] = v.w;
    }

    for (int it = 0; it < 5; it++) {
        const int kb = q0 + (it - 4) * 64;
        if (kb < 0) {
            #pragma unroll
            for (int i = 0; i < 4; i++)
                #pragma unroll
                for (int j = 0; j < 4; j++)
                    S[(r0 + i) * ATT_SP + it * 64 + c0 + j] = -1e30f;
            continue;
        }
        __syncthreads();
        for (int e = t; e < 64 * 16; e += 256) {
            const int r = e >> 4, dg = (e & 15) * 4;
            const float4 v = *(const float4*)(qkv + ((size_t)(b * T_ + kb + r)) * (3 * C_) + C_ + h * D_ + dg);
            KV[r * 65 + dg + 0] = v.x; KV[r * 65 + dg + 1] = v.y;
            KV[r * 65 + dg + 2] = v.z; KV[r * 65 + dg + 3] = v.w;
        }
        __syncthreads();
        float acc[4][4];
        #pragma unroll
        for (int i = 0; i < 4; i++)
            #pragma unroll
            for (int j = 0; j < 4; j++) acc[i][j] = 0.f;
        #pragma unroll 4
        for (int kk = 0; kk < 64; kk++) {
            float a[4], bb[4];
            #pragma unroll
            for (int i = 0; i < 4; i++) a[i]  = Qs[(r0 + i) * 65 + kk];
            #pragma unroll
            for (int j = 0; j < 4; j++) bb[j] = KV[(c0 + j) * 65 + kk];
            #pragma unroll
            for (int i = 0; i < 4; i++)
                #pragma unroll
                for (int j = 0; j < 4; j++) acc[i][j] = fmaf(a[i], bb[j], acc[i][j]);
        }
        #pragma unroll
        for (int i = 0; i < 4; i++) {
            const int ig = q0 + r0 + i;
            #pragma unroll
            for (int j = 0; j < 4; j++) {
                const int jg = kb + c0 + j;
                const bool ok = (jg <= ig) && (jg >= ig - (WIN_ - 1));
                S[(r0 + i) * ATT_SP + it * 64 + c0 + j] = ok ? acc[i][j] * scale : -1e30f;
            }
        }
    }
    __syncthreads();

    {
        const int wid = t >> 5, lane = t & 31;
        for (int rr = 0; rr < 8; rr++) {
            const int r = wid * 8 + rr;
            float m = -1e30f;
            for (int c = lane; c < 320; c += 32) m = fmaxf(m, S[r * ATT_SP + c]);
            #pragma unroll
            for (int off = 16; off; off >>= 1) m = fmaxf(m, __shfl_xor_sync(0xffffffffu, m, off));
            float sum = 0.f;
            for (int c = lane; c < 320; c += 32) {
                const float p = expf(S[r * ATT_SP + c] - m);
                S[r * ATT_SP + c] = p;
                sum += p;
            }
            #pragma unroll
            for (int off = 16; off; off >>= 1) sum += __shfl_xor_sync(0xffffffffu, sum, off);
            const float inv = 1.f / sum;
            for (int c = lane; c < 320; c += 32) S[r * ATT_SP + c] *= inv;
        }
    }

    float oacc[4][4];
    #pragma unroll
    for (int i = 0; i < 4; i++)
        #pragma unroll
        for (int j = 0; j < 4; j++) oacc[i][j] = 0.f;

    for (int it = 0; it < 5; it++) {
        const int kb = q0 + (it - 4) * 64;
        if (kb < 0) continue;
        __syncthreads();
        for (int e = t; e < 64 * 16; e += 256) {
            const int r = e >> 4, dg = (e & 15) * 4;
            const float4 v = *(const float4*)(qkv + ((size_t)(b * T_ + kb + r)) * (3 * C_) + 2 * C_ + h * D_ + dg);
            KV[r * 65 + dg + 0] = v.x; KV[r * 65 + dg + 1] = v.y;
            KV[r * 65 + dg + 2] = v.z; KV[r * 65 + dg + 3] = v.w;
        }
        __syncthreads();
        #pragma unroll 4
        for (int kk = 0; kk < 64; kk++) {
            float a[4], bb[4];
            #pragma unroll
            for (int i = 0; i < 4; i++) a[i]  = S[(r0 + i) * ATT_SP + it * 64 + kk];
            #pragma unroll
            for (int j = 0; j < 4; j++) bb[j] = KV[kk * 65 + c0 + j];
            #pragma unroll
            for (int i = 0; i < 4; i++)
                #pragma unroll
                for (int j = 0; j < 4; j++) oacc[i][j] = fmaf(a[i], bb[j], oacc[i][j]);
        }
    }
    #pragma unroll
    for (int i = 0; i < 4; i++)
        #pragma unroll
        for (int j = 0; j < 4; j++)
            o[((size_t)(b * T_ + q0 + r0 + i)) * C_ + h * D_ + c0 + j] = rnd_tf32(oacc[i][j]);
}

// ---------------------------------------------------------------------------
// Retrieval projection
// ---------------------------------------------------------------------------
__global__ __launch_bounds__(256) void ret_kernel(
    const float* __restrict__ rc, const float* __restrict__ retW, float* __restrict__ ret)
{
    const int c = blockIdx.x * 256 + threadIdx.x;
    const int b = blockIdx.y;
    float acc = 0.f;
    for (int k = 0; k < C_; k++) acc = fmaf(rc[b * C_ + k], retW[(size_t)k * C_ + c], acc);
    ret[b * C_ + c] = acc;
}

// ---------------------------------------------------------------------------
// Gate + mix
// ---------------------------------------------------------------------------
__global__ __launch_bounds__(128) void gate_mix_kernel(
    const float* __restrict__ hmat, const float* __restrict__ gW, const float* __restrict__ gb,
    const float* __restrict__ attn, const float* __restrict__ ret, float* __restrict__ x)
{
    __shared__ float red0[128], red2[128];
    __shared__ float gg0, gg2;
    const int tkn = blockIdx.x, tid = threadIdx.x;
    const float* hrow = hmat + (size_t)tkn * C_;
    float p0 = 0.f, p2 = 0.f;
    for (int c = tid; c < C_; c += 128) {
        const float hv = hrow[c];
        p0 = fmaf(hv, gW[c * 3 + 0], p0);
        p2 = fmaf(hv, gW[c * 3 + 2], p2);
    }
    red0[tid] = p0; red2[tid] = p2; __syncthreads();
    for (int s = 64; s; s >>= 1) {
        if (tid < s) { red0[tid] += red0[tid + s]; red2[tid] += red2[tid + s]; }
        __syncthreads();
    }
    if (tid == 0) {
        const float l0 = red0[0] + gb[0];
        const float l2 = red2[0] + gb[2];
        const float m  = fmaxf(l0, l2);
        const float e0 = expf(l0 - m);
        const float e1 = expf(NEG_ - m);
        const float e2 = expf(l2 - m);
        const float inv = 1.f / (e0 + e1 + e2);
        gg0 = e0 * inv; gg2 = e2 * inv;
    }
    __syncthreads();
    const float a0 = gg0, a2 = gg2;
    const int b = tkn / T_;
    float* xrow = x + (size_t)tkn * C_;
    const float* arow = attn + (size_t)tkn * C_;
    for (int c = tid; c < C_; c += 128)
        xrow[c] += a0 * arow[c] + a2 * ret[b * C_ + c];
}

// ---------------------------------------------------------------------------
// SwiGLU elementwise (output pre-rounded)
// ---------------------------------------------------------------------------
__global__ __launch_bounds__(256) void silu_mul_kernel(
    float* __restrict__ f1, const float* __restrict__ f2, int n)
{
    for (int i = blockIdx.x * blockDim.x + threadIdx.x; i < n; i += gridDim.x * blockDim.x) {
        const float a = f1[i];
        const float s = a / (1.f + expf(-a));
        f1[i] = rnd_tf32(s * f2[i]);
    }
}

// ---------------------------------------------------------------------------
// Launcher
// ---------------------------------------------------------------------------
extern "C" void kernel_launch(void* const* d_in, const int* in_sizes, int n_in,
                              void* d_out, int out_size)
{
    (void)in_sizes; (void)n_in; (void)out_size;
    const float* x    = (const float*)d_in[0];
    const float* rc   = (const float*)d_in[1];
    const float* n1g  = (const float*)d_in[2];
    const float* Wqkv = (const float*)d_in[3];
    const float* Wpro = (const float*)d_in[4];
    const float* gW   = (const float*)d_in[5];
    const float* gb   = (const float*)d_in[6];
    const float* retW = (const float*)d_in[7];
    const float* n2g  = (const float*)d_in[8];
    const float* fgW  = (const float*)d_in[9];
    const float* fuW  = (const float*)d_in[10];
    const float* fdW  = (const float*)d_in[11];
    float* xo = (float*)d_out;

    float *pH, *pH2, *pQKV, *pO, *pA, *pF1, *pF2, *pR, *pWR;
    cudaGetSymbolAddress((void**)&pH,   g_h);
    cudaGetSymbolAddress((void**)&pH2,  g_h2);
    cudaGetSymbolAddress((void**)&pQKV, g_qkv);
    cudaGetSymbolAddress((void**)&pO,   g_o);
    cudaGetSymbolAddress((void**)&pA,   g_attn);
    cudaGetSymbolAddress((void**)&pF1,  g_f1);
    cudaGetSymbolAddress((void**)&pF2,  g_f2);
    cudaGetSymbolAddress((void**)&pR,   g_ret);
    cudaGetSymbolAddress((void**)&pWR,  g_wr);

    cudaFuncSetAttribute(attn_kernel, cudaFuncAttributeMaxDynamicSharedMemorySize, ATT_SMEM);
    cudaFuncSetAttribute(gemm_tf32_v5, cudaFuncAttributeMaxDynamicSharedMemorySize, GEMM3_SMEM);

    // One-time weight pre-rounding into scratch (tf32 grid)
    for (int l = 0; l < L_; l++) {
        float* base = pWR + (size_t)l * WR_L;
        round_tf32_copy<<<1184, 256>>>(Wqkv + (size_t)l * 3 * C_ * C_, base + WR_QKV, 3 * C_ * C_);
        round_tf32_copy<<<1184, 256>>>(Wpro + (size_t)l * C_ * C_,     base + WR_PROJ, C_ * C_);
        round_tf32_copy<<<1184, 256>>>(fgW  + (size_t)l * C_ * F_,     base + WR_GATE, C_ * F_);
        round_tf32_copy<<<1184, 256>>>(fuW  + (size_t)l * C_ * F_,     base + WR_UP,   C_ * F_);
        round_tf32_copy<<<1184, 256>>>(fdW  + (size_t)l * F_ * C_,     base + WR_DOWN, F_ * C_);
    }

    cudaMemcpyAsync(xo, x, sizeof(float) * (size_t)M_ * C_, cudaMemcpyDeviceToDevice);

    for (int l = 0; l < L_; l++) {
        float* base = pWR + (size_t)l * WR_L;

        rmsnorm_kernel<<<M_, 128>>>(xo, n1g + l * C_, pH);

        gemm_tf32_v5<<<dim3(3 * C_ / 128, M_ / 128), 256, GEMM3_SMEM>>>(
            pH, base + WR_QKV, pQKV, 3 * C_, C_, 0);

        attn_kernel<<<dim3(T_ / 64, H_, B_), 256, ATT_SMEM>>>(pQKV, pO);

        gemm_tf32_v5<<<dim3(C_ / 128, M_ / 128), 256, GEMM3_SMEM>>>(
            pO, base + WR_PROJ, pA, C_, C_, 0);

        ret_kernel<<<dim3(C_ / 256, B_), 256>>>(rc, retW + (size_t)l * C_ * C_, pR);

        gate_mix_kernel<<<M_, 128>>>(pH, gW + (size_t)l * C_ * 3, gb + l * 3, pA, pR, xo);

        rmsnorm_kernel<<<M_, 128>>>(xo, n2g + l * C_, pH2);

        gemm_tf32_v5<<<dim3(F_ / 128, M_ / 128), 256, GEMM3_SMEM>>>(
            pH2, base + WR_GATE, pF1, F_, C_, 0);
        gemm_tf32_v5<<<dim3(F_ / 128, M_ / 128), 256, GEMM3_SMEM>>>(
            pH2, base + WR_UP, pF2, F_, C_, 0);

        silu_mul_kernel<<<4096, 256>>>(pF1, pF2, M_ * F_);

        gemm_tf32_v5<<<dim3(C_ / 128, M_ / 128), 256, GEMM3_SMEM>>>(
            pF1, base + WR_DOWN, xo, C_, F_, 1 /*accumulate*/);
    }
}

// round 8
// speedup vs baseline: 3.6352x; 1.2572x over previous
#include <cuda_runtime.h>
#include <cuda_fp16.h>
#include <math.h>
#include <stdint.h>

// Problem constants
#define L_ 2
#define B_ 2
#define T_ 2048
#define C_ 1024
#define H_ 16
#define D_ 64
#define F_ 4096
#define WIN_ 256
#define M_ (B_*T_)   // 4096 tokens
#define NEG_ (-1e9f)

// ---------------------------------------------------------------------------
// Scratch
// ---------------------------------------------------------------------------
__device__ __align__(16) __half g_h  [M_*C_];   // rmsnorm1 out (fp16)
__device__ __align__(16) __half g_h2 [M_*C_];   // rmsnorm2 out (fp16)
__device__ __align__(16) float  g_qkv[M_*3*C_];
__device__ __align__(16) __half g_o  [M_*C_];   // attn out (fp16)
__device__ __align__(16) float  g_attn[M_*C_];
__device__ __align__(16) float  g_f1 [M_*F_];
__device__ __align__(16) float  g_f2 [M_*F_];
__device__ __align__(16) __half g_f1h[M_*F_];   // silu-mul out (fp16)
__device__ __align__(16) float  g_ret[B_*C_];
// fp16 weights (per layer: qkv | proj | gate | up | down)
#define WH_L   16777216           // halfs per layer
#define WH_QKV 0
#define WH_PROJ 3145728
#define WH_GATE 4194304
#define WH_UP   8388608
#define WH_DOWN 12582912
__device__ __align__(16) __half g_wh[L_ * WH_L];

// ---------------------------------------------------------------------------
// Weight fp32 -> fp16 conversion (every launch; deterministic)
// ---------------------------------------------------------------------------
__global__ __launch_bounds__(256) void cvt_half_copy(
    const float* __restrict__ src, __half* __restrict__ dst, int n4)
{
    int i = blockIdx.x * 256 + threadIdx.x;
    const int stride = gridDim.x * 256;
    for (; i < n4; i += stride) {
        const float4 v = *(const float4*)(src + 4 * (size_t)i);
        __half2 h0 = __floats2half2_rn(v.x, v.y);
        __half2 h1 = __floats2half2_rn(v.z, v.w);
        *(__half2*)(dst + 4 * (size_t)i)     = h0;
        *(__half2*)(dst + 4 * (size_t)i + 2) = h1;
    }
}

// ---------------------------------------------------------------------------
// RMSNorm (fp32 in, fp16 out)
// ---------------------------------------------------------------------------
__global__ __launch_bounds__(128) void rmsnorm_kernel(
    const float* __restrict__ x, const float* __restrict__ g, __half* __restrict__ out)
{
    __shared__ float red[128];
    __shared__ float rinv;
    const int tkn = blockIdx.x, tid = threadIdx.x;
    const float* row = x + (size_t)tkn * C_;
    float ss = 0.f;
    #pragma unroll
    for (int c = tid; c < C_; c += 128) { float v = row[c]; ss += v * v; }
    red[tid] = ss; __syncthreads();
    for (int s = 64; s; s >>= 1) { if (tid < s) red[tid] += red[tid + s]; __syncthreads(); }
    if (tid == 0) rinv = rsqrtf(red[0] * (1.0f / C_) + 1e-6f);
    __syncthreads();
    const float r = rinv;
    __half* orow = out + (size_t)tkn * C_;
    #pragma unroll
    for (int c = tid; c < C_; c += 128) orow[c] = __float2half_rn(row[c] * r * g[c]);
}

// ---------------------------------------------------------------------------
// FP16 tensor-core GEMM: C[M,N](fp32) (+)= A[M,K](fp16) @ B[K,N](fp16).
// 128x128x64 block tile, 256 threads (8 warps, 64x32 warp tiles), 2 blocks/SM,
// 3-stage cp.async. A frags: ldmatrix.x4; B frags: ldmatrix.x4.trans.
// mma.m16n8k16.f32.f16.f16.f32 (fp32 accumulate).
// M,N multiples of 128; K multiple of 64.
// ---------------------------------------------------------------------------
__device__ __forceinline__ void mma_f16(float c[4], const uint32_t a[4], const uint32_t b[2]) {
    asm volatile(
        "mma.sync.aligned.m16n8k16.row.col.f32.f16.f16.f32 "
        "{%0,%1,%2,%3}, {%4,%5,%6,%7}, {%8,%9}, {%0,%1,%2,%3};\n"
        : "+f"(c[0]), "+f"(c[1]), "+f"(c[2]), "+f"(c[3])
        : "r"(a[0]), "r"(a[1]), "r"(a[2]), "r"(a[3]), "r"(b[0]), "r"(b[1]));
}

__device__ __forceinline__ void ldsm_x4(uint32_t f[4], uint32_t addr) {
    asm volatile(
        "ldmatrix.sync.aligned.m8n8.x4.shared.b16 {%0,%1,%2,%3}, [%4];\n"
        : "=r"(f[0]), "=r"(f[1]), "=r"(f[2]), "=r"(f[3]) : "r"(addr));
}
__device__ __forceinline__ void ldsm_x4_t(uint32_t f[4], uint32_t addr) {
    asm volatile(
        "ldmatrix.sync.aligned.m8n8.x4.trans.shared.b16 {%0,%1,%2,%3}, [%4];\n"
        : "=r"(f[0]), "=r"(f[1]), "=r"(f[2]), "=r"(f[3]) : "r"(addr));
}

#define BKH 64
#define APH 72     // A pitch in fp16 (64 + 8 pad)  -> 144 B
#define BPH 136    // B pitch in fp16 (128 + 8 pad) -> 272 B
#define ASTGH (128*APH)       // 9216 halfs
#define BSTGH (BKH*BPH)       // 8704 halfs
#define STGH  (ASTGH+BSTGH)   // 17920 halfs = 35840 B
#define GEMMH_SMEM (3 * STGH * 2)   // 107520 B

__device__ __forceinline__ void cp16(void* dst, const void* src) {
    uint32_t d = (uint32_t)__cvta_generic_to_shared(dst);
    asm volatile("cp.async.cg.shared.global [%0], [%1], 16;\n" :: "r"(d), "l"(src));
}

__global__ void __launch_bounds__(256, 2) gemm_f16(
    const __half* __restrict__ A, const __half* __restrict__ Bm, float* __restrict__ Cm,
    int Nd, int Kd, int addTo)
{
    extern __shared__ __half smh[];
    #define ASH_(s,m,k)  smh[(s)*STGH + (m)*APH + (k)]
    #define BSH_(s,kr,n) smh[(s)*STGH + ASTGH + (kr)*BPH + (n)]

    const int t = threadIdx.x;
    const int w = t >> 5, lane = t & 31;
    const int r = lane >> 2, c = lane & 3;
    const int mb = (w >> 2) * 64;
    const int nb = (w & 3) * 32;
    const int bm = blockIdx.y * 128, bn = blockIdx.x * 128;

    // ldmatrix A offsets: tiles (m0,k),(m0+8,k),(m0,k+8),(m0+8,k+8)
    const int offm = (lane & 7) + ((lane >> 3) & 1) * 8;
    const int offk = (lane >> 4) * 8;        // fp16 cols
    // ldmatrix B (trans) offsets: row kb + (lane&15), col nb + nt2*16 + (lane>>4)*8
    const int bfr = lane & 15;
    const int bfc = (lane >> 4) * 8;

    // producers: A row t>>1, 4 chunks of 16B at (t&1)*32 fp16
    const int ar = t >> 1, ac0 = (t & 1) * 32;
    // B row t>>2, 4 chunks of 16B at (t&3)*32 fp16
    const int br = t >> 2, bc0 = (t & 3) * 32;
    const __half* Ag = A  + (size_t)(bm + ar) * Kd + ac0;
    const __half* Bg = Bm + (size_t)br * Nd + bn + bc0;

    float acc[16][4];
    #pragma unroll
    for (int i = 0; i < 16; i++)
        #pragma unroll
        for (int j = 0; j < 4; j++) acc[i][j] = 0.f;

    const int niter = Kd / BKH;

    #pragma unroll
    for (int p = 0; p < 2; p++) {
        const int kt = p * BKH;
        #pragma unroll
        for (int i = 0; i < 4; i++)
            cp16(&ASH_(p, ar, ac0 + i * 8), Ag + kt + i * 8);
        #pragma unroll
        for (int i = 0; i < 4; i++)
            cp16(&BSH_(p, br, bc0 + i * 8), Bg + (size_t)kt * Nd + i * 8);
        asm volatile("cp.async.commit_group;\n");
    }

    int st = 0;
    for (int it = 0; it < niter; it++) {
        asm volatile("cp.async.wait_group 1;\n");
        __syncthreads();

        if (it + 2 < niter) {
            const int ps = (st + 2) % 3;
            const int kt = (it + 2) * BKH;
            #pragma unroll
            for (int i = 0; i < 4; i++)
                cp16(&ASH_(ps, ar, ac0 + i * 8), Ag + kt + i * 8);
            #pragma unroll
            for (int i = 0; i < 4; i++)
                cp16(&BSH_(ps, br, bc0 + i * 8), Bg + (size_t)kt * Nd + i * 8);
        }
        asm volatile("cp.async.commit_group;\n");

        const uint32_t sbase = (uint32_t)__cvta_generic_to_shared(&smh[st * STGH]);

        #pragma unroll
        for (int ks = 0; ks < 4; ks++) {
            const int kb = ks * 16;
            uint32_t af[4][4], bf[2][4];
            #pragma unroll
            for (int mt = 0; mt < 4; mt++) {
                const uint32_t aaddr = sbase +
                    (uint32_t)(((mb + mt * 16 + offm) * APH + kb + offk) * 2);
                ldsm_x4(af[mt], aaddr);
            }
            #pragma unroll
            for (int nt2 = 0; nt2 < 2; nt2++) {
                const uint32_t baddr = sbase + (uint32_t)(ASTGH * 2) +
                    (uint32_t)(((kb + bfr) * BPH + nb + nt2 * 16 + bfc) * 2);
                ldsm_x4_t(bf[nt2], baddr);
            }
            #pragma unroll
            for (int mt = 0; mt < 4; mt++)
                #pragma unroll
                for (int nt = 0; nt < 4; nt++)
                    mma_f16(acc[mt * 4 + nt], af[mt], &bf[nt >> 1][(nt & 1) * 2]);
        }

        st = (st + 1) % 3;
    }

    #pragma unroll
    for (int mt = 0; mt < 4; mt++) {
        #pragma unroll
        for (int nt = 0; nt < 4; nt++) {
            const float* a4 = acc[mt * 4 + nt];
            float* p0 = Cm + (size_t)(bm + mb + mt * 16 + r) * Nd + bn + nb + nt * 8 + c * 2;
            float* p1 = p0 + 8 * (size_t)Nd;
            if (addTo) {
                float2 v0 = *(float2*)p0;
                float2 v1 = *(float2*)p1;
                v0.x += a4[0]; v0.y += a4[1];
                v1.x += a4[2]; v1.y += a4[3];
                *(float2*)p0 = v0;
                *(float2*)p1 = v1;
            } else {
                *(float2*)p0 = make_float2(a4[0], a4[1]);
                *(float2*)p1 = make_float2(a4[2], a4[3]);
            }
        }
    }
    #undef ASH_
    #undef BSH_
}

// ---------------------------------------------------------------------------
// Sliding-window attention (fp32 qkv in, fp16 out)
// ---------------------------------------------------------------------------
#define ATT_SP 324
#define ATT_SMEM ((2*64*65 + 64*ATT_SP) * 4)

__global__ __launch_bounds__(256) void attn_kernel(
    const float* __restrict__ qkv, __half* __restrict__ o)
{
    extern __shared__ float sm[];
    float* Qs = sm;
    float* KV = sm + 64 * 65;
    float* S  = sm + 2 * 64 * 65;

    const int q0 = blockIdx.x * 64;
    const int h  = blockIdx.y;
    const int b  = blockIdx.z;
    const int t  = threadIdx.x;
    const int tx = t & 15, ty = t >> 4;
    const int r0 = ty * 4, c0 = tx * 4;
    const float scale = 0.125f;

    for (int e = t; e < 64 * 16; e += 256) {
        const int q = e >> 4, dg = (e & 15) * 4;
        const float4 v = *(const float4*)(qkv + ((size_t)(b * T_ + q0 + q)) * (3 * C_) + h * D_ + dg);
        Qs[q * 65 + dg + 0] = v.x; Qs[q * 65 + dg + 1] = v.y;
        Qs[q * 65 + dg + 2] = v.z; Qs[q * 65 + dg + 3] = v.w;
    }

    for (int it = 0; it < 5; it++) {
        const int kb = q0 + (it - 4) * 64;
        if (kb < 0) {
            #pragma unroll
            for (int i = 0; i < 4; i++)
                #pragma unroll
                for (int j = 0; j < 4; j++)
                    S[(r0 + i) * ATT_SP + it * 64 + c0 + j] = -1e30f;
            continue;
        }
        __syncthreads();
        for (int e = t; e < 64 * 16; e += 256) {
            const int r = e >> 4, dg = (e & 15) * 4;
            const float4 v = *(const float4*)(qkv + ((size_t)(b * T_ + kb + r)) * (3 * C_) + C_ + h * D_ + dg);
            KV[r * 65 + dg + 0] = v.x; KV[r * 65 + dg + 1] = v.y;
            KV[r * 65 + dg + 2] = v.z; KV[r * 65 + dg + 3] = v.w;
        }
        __syncthreads();
        float acc[4][4];
        #pragma unroll
        for (int i = 0; i < 4; i++)
            #pragma unroll
            for (int j = 0; j < 4; j++) acc[i][j] = 0.f;
        #pragma unroll 4
        for (int kk = 0; kk < 64; kk++) {
            float a[4], bb[4];
            #pragma unroll
            for (int i = 0; i < 4; i++) a[i]  = Qs[(r0 + i) * 65 + kk];
            #pragma unroll
            for (int j = 0; j < 4; j++) bb[j] = KV[(c0 + j) * 65 + kk];
            #pragma unroll
            for (int i = 0; i < 4; i++)
                #pragma unroll
                for (int j = 0; j < 4; j++) acc[i][j] = fmaf(a[i], bb[j], acc[i][j]);
        }
        #pragma unroll
        for (int i = 0; i < 4; i++) {
            const int ig = q0 + r0 + i;
            #pragma unroll
            for (int j = 0; j < 4; j++) {
                const int jg = kb + c0 + j;
                const bool ok = (jg <= ig) && (jg >= ig - (WIN_ - 1));
                S[(r0 + i) * ATT_SP + it * 64 + c0 + j] = ok ? acc[i][j] * scale : -1e30f;
            }
        }
    }
    __syncthreads();

    {
        const int wid = t >> 5, lane = t & 31;
        for (int rr = 0; rr < 8; rr++) {
            const int r = wid * 8 + rr;
            float m = -1e30f;
            for (int c = lane; c < 320; c += 32) m = fmaxf(m, S[r * ATT_SP + c]);
            #pragma unroll
            for (int off = 16; off; off >>= 1) m = fmaxf(m, __shfl_xor_sync(0xffffffffu, m, off));
            float sum = 0.f;
            for (int c = lane; c < 320; c += 32) {
                const float p = expf(S[r * ATT_SP + c] - m);
                S[r * ATT_SP + c] = p;
                sum += p;
            }
            #pragma unroll
            for (int off = 16; off; off >>= 1) sum += __shfl_xor_sync(0xffffffffu, sum, off);
            const float inv = 1.f / sum;
            for (int c = lane; c < 320; c += 32) S[r * ATT_SP + c] *= inv;
        }
    }

    float oacc[4][4];
    #pragma unroll
    for (int i = 0; i < 4; i++)
        #pragma unroll
        for (int j = 0; j < 4; j++) oacc[i][j] = 0.f;

    for (int it = 0; it < 5; it++) {
        const int kb = q0 + (it - 4) * 64;
        if (kb < 0) continue;
        __syncthreads();
        for (int e = t; e < 64 * 16; e += 256) {
            const int r = e >> 4, dg = (e & 15) * 4;
            const float4 v = *(const float4*)(qkv + ((size_t)(b * T_ + kb + r)) * (3 * C_) + 2 * C_ + h * D_ + dg);
            KV[r * 65 + dg + 0] = v.x; KV[r * 65 + dg + 1] = v.y;
            KV[r * 65 + dg + 2] = v.z; KV[r * 65 + dg + 3] = v.w;
        }
        __syncthreads();
        #pragma unroll 4
        for (int kk = 0; kk < 64; kk++) {
            float a[4], bb[4];
            #pragma unroll
            for (int i = 0; i < 4; i++) a[i]  = S[(r0 + i) * ATT_SP + it * 64 + kk];
            #pragma unroll
            for (int j = 0; j < 4; j++) bb[j] = KV[kk * 65 + c0 + j];
            #pragma unroll
            for (int i = 0; i < 4; i++)
                #pragma unroll
                for (int j = 0; j < 4; j++) oacc[i][j] = fmaf(a[i], bb[j], oacc[i][j]);
        }
    }
    #pragma unroll
    for (int i = 0; i < 4; i++)
        #pragma unroll
        for (int j = 0; j < 4; j++)
            o[((size_t)(b * T_ + q0 + r0 + i)) * C_ + h * D_ + c0 + j] = __float2half_rn(oacc[i][j]);
}

// ---------------------------------------------------------------------------
// Retrieval projection (fp32, tiny)
// ---------------------------------------------------------------------------
__global__ __launch_bounds__(256) void ret_kernel(
    const float* __restrict__ rc, const float* __restrict__ retW, float* __restrict__ ret)
{
    const int c = blockIdx.x * 256 + threadIdx.x;
    const int b = blockIdx.y;
    float acc = 0.f;
    for (int k = 0; k < C_; k++) acc = fmaf(rc[b * C_ + k], retW[(size_t)k * C_ + c], acc);
    ret[b * C_ + c] = acc;
}

// ---------------------------------------------------------------------------
// Gate + mix (h now fp16)
// ---------------------------------------------------------------------------
__global__ __launch_bounds__(128) void gate_mix_kernel(
    const __half* __restrict__ hmat, const float* __restrict__ gW, const float* __restrict__ gb,
    const float* __restrict__ attn, const float* __restrict__ ret, float* __restrict__ x)
{
    __shared__ float red0[128], red2[128];
    __shared__ float gg0, gg2;
    const int tkn = blockIdx.x, tid = threadIdx.x;
    const __half* hrow = hmat + (size_t)tkn * C_;
    float p0 = 0.f, p2 = 0.f;
    for (int c = tid; c < C_; c += 128) {
        const float hv = __half2float(hrow[c]);
        p0 = fmaf(hv, gW[c * 3 + 0], p0);
        p2 = fmaf(hv, gW[c * 3 + 2], p2);
    }
    red0[tid] = p0; red2[tid] = p2; __syncthreads();
    for (int s = 64; s; s >>= 1) {
        if (tid < s) { red0[tid] += red0[tid + s]; red2[tid] += red2[tid + s]; }
        __syncthreads();
    }
    if (tid == 0) {
        const float l0 = red0[0] + gb[0];
        const float l2 = red2[0] + gb[2];
        const float m  = fmaxf(l0, l2);
        const float e0 = expf(l0 - m);
        const float e1 = expf(NEG_ - m);
        const float e2 = expf(l2 - m);
        const float inv = 1.f / (e0 + e1 + e2);
        gg0 = e0 * inv; gg2 = e2 * inv;
    }
    __syncthreads();
    const float a0 = gg0, a2 = gg2;
    const int b = tkn / T_;
    float* xrow = x + (size_t)tkn * C_;
    const float* arow = attn + (size_t)tkn * C_;
    for (int c = tid; c < C_; c += 128)
        xrow[c] += a0 * arow[c] + a2 * ret[b * C_ + c];
}

// ---------------------------------------------------------------------------
// SwiGLU elementwise (fp32 in, fp16 out)
// ---------------------------------------------------------------------------
__global__ __launch_bounds__(256) void silu_mul_kernel(
    const float* __restrict__ f1, const float* __restrict__ f2, __half* __restrict__ out, int n)
{
    for (int i = blockIdx.x * blockDim.x + threadIdx.x; i < n; i += gridDim.x * blockDim.x) {
        const float a = f1[i];
        const float s = a / (1.f + expf(-a));
        out[i] = __float2half_rn(s * f2[i]);
    }
}

// ---------------------------------------------------------------------------
// Launcher
// ---------------------------------------------------------------------------
extern "C" void kernel_launch(void* const* d_in, const int* in_sizes, int n_in,
                              void* d_out, int out_size)
{
    (void)in_sizes; (void)n_in; (void)out_size;
    const float* x    = (const float*)d_in[0];
    const float* rc   = (const float*)d_in[1];
    const float* n1g  = (const float*)d_in[2];
    const float* Wqkv = (const float*)d_in[3];
    const float* Wpro = (const float*)d_in[4];
    const float* gW   = (const float*)d_in[5];
    const float* gb   = (const float*)d_in[6];
    const float* retW = (const float*)d_in[7];
    const float* n2g  = (const float*)d_in[8];
    const float* fgW  = (const float*)d_in[9];
    const float* fuW  = (const float*)d_in[10];
    const float* fdW  = (const float*)d_in[11];
    float* xo = (float*)d_out;

    __half *pH, *pH2, *pO, *pF1h, *pWH;
    float *pQKV, *pA, *pF1, *pF2, *pR;
    cudaGetSymbolAddress((void**)&pH,   g_h);
    cudaGetSymbolAddress((void**)&pH2,  g_h2);
    cudaGetSymbolAddress((void**)&pQKV, g_qkv);
    cudaGetSymbolAddress((void**)&pO,   g_o);
    cudaGetSymbolAddress((void**)&pA,   g_attn);
    cudaGetSymbolAddress((void**)&pF1,  g_f1);
    cudaGetSymbolAddress((void**)&pF2,  g_f2);
    cudaGetSymbolAddress((void**)&pF1h, g_f1h);
    cudaGetSymbolAddress((void**)&pR,   g_ret);
    cudaGetSymbolAddress((void**)&pWH,  g_wh);

    cudaFuncSetAttribute(attn_kernel, cudaFuncAttributeMaxDynamicSharedMemorySize, ATT_SMEM);
    cudaFuncSetAttribute(gemm_f16, cudaFuncAttributeMaxDynamicSharedMemorySize, GEMMH_SMEM);

    // Weight fp32 -> fp16 conversion into scratch
    for (int l = 0; l < L_; l++) {
        __half* base = pWH + (size_t)l * WH_L;
        cvt_half_copy<<<1184, 256>>>(Wqkv + (size_t)l * 3 * C_ * C_, base + WH_QKV, 3 * C_ * C_ / 4);
        cvt_half_copy<<<1184, 256>>>(Wpro + (size_t)l * C_ * C_,     base + WH_PROJ, C_ * C_ / 4);
        cvt_half_copy<<<1184, 256>>>(fgW  + (size_t)l * C_ * F_,     base + WH_GATE, C_ * F_ / 4);
        cvt_half_copy<<<1184, 256>>>(fuW  + (size_t)l * C_ * F_,     base + WH_UP,   C_ * F_ / 4);
        cvt_half_copy<<<1184, 256>>>(fdW  + (size_t)l * F_ * C_,     base + WH_DOWN, F_ * C_ / 4);
    }

    cudaMemcpyAsync(xo, x, sizeof(float) * (size_t)M_ * C_, cudaMemcpyDeviceToDevice);

    for (int l = 0; l < L_; l++) {
        __half* base = pWH + (size_t)l * WH_L;

        rmsnorm_kernel<<<M_, 128>>>(xo, n1g + l * C_, pH);

        gemm_f16<<<dim3(3 * C_ / 128, M_ / 128), 256, GEMMH_SMEM>>>(
            pH, base + WH_QKV, pQKV, 3 * C_, C_, 0);

        attn_kernel<<<dim3(T_ / 64, H_, B_), 256, ATT_SMEM>>>(pQKV, pO);

        gemm_f16<<<dim3(C_ / 128, M_ / 128), 256, GEMMH_SMEM>>>(
            pO, base + WH_PROJ, pA, C_, C_, 0);

        ret_kernel<<<dim3(C_ / 256, B_), 256>>>(rc, retW + (size_t)l * C_ * C_, pR);

        gate_mix_kernel<<<M_, 128>>>(pH, gW + (size_t)l * C_ * 3, gb + l * 3, pA, pR, xo);

        rmsnorm_kernel<<<M_, 128>>>(xo, n2g + l * C_, pH2);

        gemm_f16<<<dim3(F_ / 128, M_ / 128), 256, GEMMH_SMEM>>>(
            pH2, base + WH_GATE, pF1, F_, C_, 0);
        gemm_f16<<<dim3(F_ / 128, M_ / 128), 256, GEMMH_SMEM>>>(
            pH2, base + WH_UP, pF2, F_, C_, 0);

        silu_mul_kernel<<<4096, 256>>>(pF1, pF2, pF1h, M_ * F_);

        gemm_f16<<<dim3(C_ / 128, M_ / 128), 256, GEMMH_SMEM>>>(
            pF1h, base + WH_DOWN, xo, C_, F_, 1 /*accumulate*/);
    }
}

// round 9
// speedup vs baseline: 3.9676x; 1.0915x over previous
#include <cuda_runtime.h>
#include <cuda_fp16.h>
#include <math.h>
#include <stdint.h>

// Problem constants
#define L_ 2
#define B_ 2
#define T_ 2048
#define C_ 1024
#define H_ 16
#define D_ 64
#define F_ 4096
#define WIN_ 256
#define M_ (B_*T_)   // 4096 tokens
#define NEG_ (-1e9f)

// ---------------------------------------------------------------------------
// Scratch
// ---------------------------------------------------------------------------
__device__ __align__(16) __half g_h  [M_*C_];    // rmsnorm1 out (fp16)
__device__ __align__(16) __half g_h2 [M_*C_];    // rmsnorm2 out (fp16)
__device__ __align__(16) __half g_qkv[M_*3*C_];  // qkv (fp16)
__device__ __align__(16) __half g_o  [M_*C_];    // attn out (fp16)
__device__ __align__(16) float  g_attn[M_*C_];
__device__ __align__(16) __half g_f1h[M_*F_];    // swiglu out (fp16)
__device__ __align__(16) float  g_ret[B_*C_];
// fp16 weights per layer: qkv | proj | gateup(interleaved, 2F cols) | down
#define WH_L    16777216          // halfs per layer
#define WH_QKV  0
#define WH_PROJ 3145728
#define WH_GU   4194304           // C x 2F interleaved
#define WH_DOWN 12582912
__device__ __align__(16) __half g_wh[L_ * WH_L];

// ---------------------------------------------------------------------------
// Weight conversion kernels
// ---------------------------------------------------------------------------
__global__ __launch_bounds__(256) void cvt_half_copy(
    const float* __restrict__ src, __half* __restrict__ dst, int n4)
{
    int i = blockIdx.x * 256 + threadIdx.x;
    const int stride = gridDim.x * 256;
    for (; i < n4; i += stride) {
        const float4 v = *(const float4*)(src + 4 * (size_t)i);
        *(__half2*)(dst + 4 * (size_t)i)     = __floats2half2_rn(v.x, v.y);
        *(__half2*)(dst + 4 * (size_t)i + 2) = __floats2half2_rn(v.z, v.w);
    }
}

// interleave gate/up: dst2[k*F + j] = (gate[k*F+j], up[k*F+j]) as half2
__global__ __launch_bounds__(256) void cvt_gateup(
    const float* __restrict__ gate, const float* __restrict__ up,
    __half2* __restrict__ dst2, int n)
{
    int i = blockIdx.x * 256 + threadIdx.x;
    const int stride = gridDim.x * 256;
    for (; i < n; i += stride)
        dst2[i] = __floats2half2_rn(gate[i], up[i]);
}

// ---------------------------------------------------------------------------
// RMSNorm (fp32 in, fp16 out)
// ---------------------------------------------------------------------------
__global__ __launch_bounds__(128) void rmsnorm_kernel(
    const float* __restrict__ x, const float* __restrict__ g, __half* __restrict__ out)
{
    __shared__ float red[128];
    __shared__ float rinv;
    const int tkn = blockIdx.x, tid = threadIdx.x;
    const float* row = x + (size_t)tkn * C_;
    float ss = 0.f;
    #pragma unroll
    for (int c = tid; c < C_; c += 128) { float v = row[c]; ss += v * v; }
    red[tid] = ss; __syncthreads();
    for (int s = 64; s; s >>= 1) { if (tid < s) red[tid] += red[tid + s]; __syncthreads(); }
    if (tid == 0) rinv = rsqrtf(red[0] * (1.0f / C_) + 1e-6f);
    __syncthreads();
    const float r = rinv;
    __half* orow = out + (size_t)tkn * C_;
    #pragma unroll
    for (int c = tid; c < C_; c += 128) orow[c] = __float2half_rn(row[c] * r * g[c]);
}

// ---------------------------------------------------------------------------
// FP16 tensor-core GEMM. Modes:
//   0: fp32 store   1: fp32 accumulate   2: fp16 store
//   3: swiglu — B columns interleaved (gate,up); writes silu(g)*u as fp16,
//      output row stride Nd/2.
// ---------------------------------------------------------------------------
__device__ __forceinline__ void mma_f16(float c[4], const uint32_t a[4], const uint32_t b[2]) {
    asm volatile(
        "mma.sync.aligned.m16n8k16.row.col.f32.f16.f16.f32 "
        "{%0,%1,%2,%3}, {%4,%5,%6,%7}, {%8,%9}, {%0,%1,%2,%3};\n"
        : "+f"(c[0]), "+f"(c[1]), "+f"(c[2]), "+f"(c[3])
        : "r"(a[0]), "r"(a[1]), "r"(a[2]), "r"(a[3]), "r"(b[0]), "r"(b[1]));
}
__device__ __forceinline__ void ldsm_x4(uint32_t f[4], uint32_t addr) {
    asm volatile(
        "ldmatrix.sync.aligned.m8n8.x4.shared.b16 {%0,%1,%2,%3}, [%4];\n"
        : "=r"(f[0]), "=r"(f[1]), "=r"(f[2]), "=r"(f[3]) : "r"(addr));
}
__device__ __forceinline__ void ldsm_x4_t(uint32_t f[4], uint32_t addr) {
    asm volatile(
        "ldmatrix.sync.aligned.m8n8.x4.trans.shared.b16 {%0,%1,%2,%3}, [%4];\n"
        : "=r"(f[0]), "=r"(f[1]), "=r"(f[2]), "=r"(f[3]) : "r"(addr));
}

#define BKH 64
#define APH 72
#define BPH 136
#define ASTGH (128*APH)
#define BSTGH (BKH*BPH)
#define STGH  (ASTGH+BSTGH)
#define GEMMH_SMEM (3 * STGH * 2)

__device__ __forceinline__ void cp16(void* dst, const void* src) {
    uint32_t d = (uint32_t)__cvta_generic_to_shared(dst);
    asm volatile("cp.async.cg.shared.global [%0], [%1], 16;\n" :: "r"(d), "l"(src));
}

__global__ void __launch_bounds__(256, 2) gemm_f16(
    const __half* __restrict__ A, const __half* __restrict__ Bm, void* __restrict__ Cout,
    int Nd, int Kd, int mode)
{
    extern __shared__ __half smh[];
    #define ASH_(s,m,k)  smh[(s)*STGH + (m)*APH + (k)]
    #define BSH_(s,kr,n) smh[(s)*STGH + ASTGH + (kr)*BPH + (n)]

    const int t = threadIdx.x;
    const int w = t >> 5, lane = t & 31;
    const int r = lane >> 2, c = lane & 3;
    const int mb = (w >> 2) * 64;
    const int nb = (w & 3) * 32;
    const int bm = blockIdx.y * 128, bn = blockIdx.x * 128;

    const int offm = (lane & 7) + ((lane >> 3) & 1) * 8;
    const int offk = (lane >> 4) * 8;
    const int bfr = lane & 15;
    const int bfc = (lane >> 4) * 8;

    const int ar = t >> 1, ac0 = (t & 1) * 32;
    const int br = t >> 2, bc0 = (t & 3) * 32;
    const __half* Ag = A  + (size_t)(bm + ar) * Kd + ac0;
    const __half* Bg = Bm + (size_t)br * Nd + bn + bc0;

    float acc[16][4];
    #pragma unroll
    for (int i = 0; i < 16; i++)
        #pragma unroll
        for (int j = 0; j < 4; j++) acc[i][j] = 0.f;

    const int niter = Kd / BKH;

    #pragma unroll
    for (int p = 0; p < 2; p++) {
        const int kt = p * BKH;
        #pragma unroll
        for (int i = 0; i < 4; i++)
            cp16(&ASH_(p, ar, ac0 + i * 8), Ag + kt + i * 8);
        #pragma unroll
        for (int i = 0; i < 4; i++)
            cp16(&BSH_(p, br, bc0 + i * 8), Bg + (size_t)kt * Nd + i * 8);
        asm volatile("cp.async.commit_group;\n");
    }

    int st = 0;
    for (int it = 0; it < niter; it++) {
        asm volatile("cp.async.wait_group 1;\n");
        __syncthreads();

        if (it + 2 < niter) {
            const int ps = (st + 2) % 3;
            const int kt = (it + 2) * BKH;
            #pragma unroll
            for (int i = 0; i < 4; i++)
                cp16(&ASH_(ps, ar, ac0 + i * 8), Ag + kt + i * 8);
            #pragma unroll
            for (int i = 0; i < 4; i++)
                cp16(&BSH_(ps, br, bc0 + i * 8), Bg + (size_t)kt * Nd + i * 8);
        }
        asm volatile("cp.async.commit_group;\n");

        const uint32_t sbase = (uint32_t)__cvta_generic_to_shared(&smh[st * STGH]);

        #pragma unroll
        for (int ks = 0; ks < 4; ks++) {
            const int kb = ks * 16;
            uint32_t af[4][4], bf[2][4];
            #pragma unroll
            for (int mt = 0; mt < 4; mt++) {
                const uint32_t aaddr = sbase +
                    (uint32_t)(((mb + mt * 16 + offm) * APH + kb + offk) * 2);
                ldsm_x4(af[mt], aaddr);
            }
            #pragma unroll
            for (int nt2 = 0; nt2 < 2; nt2++) {
                const uint32_t baddr = sbase + (uint32_t)(ASTGH * 2) +
                    (uint32_t)(((kb + bfr) * BPH + nb + nt2 * 16 + bfc) * 2);
                ldsm_x4_t(bf[nt2], baddr);
            }
            #pragma unroll
            for (int mt = 0; mt < 4; mt++)
                #pragma unroll
                for (int nt = 0; nt < 4; nt++)
                    mma_f16(acc[mt * 4 + nt], af[mt], &bf[nt >> 1][(nt & 1) * 2]);
        }

        st = (st + 1) % 3;
    }

    // Epilogue
    if (mode == 3) {
        // swiglu: cols interleaved (gate,up). Thread pair (c0,c1)/(c2,c3).
        __half* po = (__half*)Cout;
        const int No = Nd >> 1;
        #pragma unroll
        for (int mt = 0; mt < 4; mt++) {
            const int row0 = bm + mb + mt * 16 + r;
            #pragma unroll
            for (int nt = 0; nt < 4; nt++) {
                const float* a4 = acc[mt * 4 + nt];
                const int nout = ((bn + nb + nt * 8) >> 1) + c;
                const float s0 = a4[0] / (1.f + expf(-a4[0]));
                const float s1 = a4[2] / (1.f + expf(-a4[2]));
                po[(size_t)row0 * No + nout]       = __float2half_rn(s0 * a4[1]);
                po[(size_t)(row0 + 8) * No + nout] = __float2half_rn(s1 * a4[3]);
            }
        }
    } else if (mode == 2) {
        __half* po = (__half*)Cout;
        #pragma unroll
        for (int mt = 0; mt < 4; mt++) {
            #pragma unroll
            for (int nt = 0; nt < 4; nt++) {
                const float* a4 = acc[mt * 4 + nt];
                const size_t base = (size_t)(bm + mb + mt * 16 + r) * Nd + bn + nb + nt * 8 + c * 2;
                *(__half2*)(po + base)                 = __floats2half2_rn(a4[0], a4[1]);
                *(__half2*)(po + base + 8 * (size_t)Nd) = __floats2half2_rn(a4[2], a4[3]);
            }
        }
    } else {
        float* po = (float*)Cout;
        #pragma unroll
        for (int mt = 0; mt < 4; mt++) {
            #pragma unroll
            for (int nt = 0; nt < 4; nt++) {
                const float* a4 = acc[mt * 4 + nt];
                float* p0 = po + (size_t)(bm + mb + mt * 16 + r) * Nd + bn + nb + nt * 8 + c * 2;
                float* p1 = p0 + 8 * (size_t)Nd;
                if (mode == 1) {
                    float2 v0 = *(float2*)p0;
                    float2 v1 = *(float2*)p1;
                    v0.x += a4[0]; v0.y += a4[1];
                    v1.x += a4[2]; v1.y += a4[3];
                    *(float2*)p0 = v0;
                    *(float2*)p1 = v1;
                } else {
                    *(float2*)p0 = make_float2(a4[0], a4[1]);
                    *(float2*)p1 = make_float2(a4[2], a4[3]);
                }
            }
        }
    }
    #undef ASH_
    #undef BSH_
}

// ---------------------------------------------------------------------------
// Sliding-window attention (fp16 qkv in, fp16 out; fp32 math inside)
// ---------------------------------------------------------------------------
#define ATT_SP 324
#define ATT_SMEM ((2*64*65 + 64*ATT_SP) * 4)

__device__ __forceinline__ void ld8h(float* dst, const __half* src) {
    const uint4 u = *(const uint4*)src;
    const __half2* hp = (const __half2*)&u;
    #pragma unroll
    for (int i = 0; i < 4; i++) {
        const float2 f = __half22float2(hp[i]);
        dst[2 * i]     = f.x;
        dst[2 * i + 1] = f.y;
    }
}

__global__ __launch_bounds__(256) void attn_kernel(
    const __half* __restrict__ qkv, __half* __restrict__ o)
{
    extern __shared__ float sm[];
    float* Qs = sm;
    float* KV = sm + 64 * 65;
    float* S  = sm + 2 * 64 * 65;

    const int q0 = blockIdx.x * 64;
    const int h  = blockIdx.y;
    const int b  = blockIdx.z;
    const int t  = threadIdx.x;
    const int tx = t & 15, ty = t >> 4;
    const int r0 = ty * 4, c0 = tx * 4;
    const float scale = 0.125f;

    for (int e = t; e < 64 * 8; e += 256) {
        const int q = e >> 3, dg = (e & 7) * 8;
        float v[8];
        ld8h(v, qkv + ((size_t)(b * T_ + q0 + q)) * (3 * C_) + h * D_ + dg);
        #pragma unroll
        for (int i = 0; i < 8; i++) Qs[q * 65 + dg + i] = v[i];
    }

    for (int it = 0; it < 5; it++) {
        const int kb = q0 + (it - 4) * 64;
        if (kb < 0) {
            #pragma unroll
            for (int i = 0; i < 4; i++)
                #pragma unroll
                for (int j = 0; j < 4; j++)
                    S[(r0 + i) * ATT_SP + it * 64 + c0 + j] = -1e30f;
            continue;
        }
        __syncthreads();
        for (int e = t; e < 64 * 8; e += 256) {
            const int r = e >> 3, dg = (e & 7) * 8;
            float v[8];
            ld8h(v, qkv + ((size_t)(b * T_ + kb + r)) * (3 * C_) + C_ + h * D_ + dg);
            #pragma unroll
            for (int i = 0; i < 8; i++) KV[r * 65 + dg + i] = v[i];
        }
        __syncthreads();
        float acc[4][4];
        #pragma unroll
        for (int i = 0; i < 4; i++)
            #pragma unroll
            for (int j = 0; j < 4; j++) acc[i][j] = 0.f;
        #pragma unroll 4
        for (int kk = 0; kk < 64; kk++) {
            float a[4], bb[4];
            #pragma unroll
            for (int i = 0; i < 4; i++) a[i]  = Qs[(r0 + i) * 65 + kk];
            #pragma unroll
            for (int j = 0; j < 4; j++) bb[j] = KV[(c0 + j) * 65 + kk];
            #pragma unroll
            for (int i = 0; i < 4; i++)
                #pragma unroll
                for (int j = 0; j < 4; j++) acc[i][j] = fmaf(a[i], bb[j], acc[i][j]);
        }
        #pragma unroll
        for (int i = 0; i < 4; i++) {
            const int ig = q0 + r0 + i;
            #pragma unroll
            for (int j = 0; j < 4; j++) {
                const int jg = kb + c0 + j;
                const bool ok = (jg <= ig) && (jg >= ig - (WIN_ - 1));
                S[(r0 + i) * ATT_SP + it * 64 + c0 + j] = ok ? acc[i][j] * scale : -1e30f;
            }
        }
    }
    __syncthreads();

    {
        const int wid = t >> 5, lane = t & 31;
        for (int rr = 0; rr < 8; rr++) {
            const int r = wid * 8 + rr;
            float m = -1e30f;
            for (int c = lane; c < 320; c += 32) m = fmaxf(m, S[r * ATT_SP + c]);
            #pragma unroll
            for (int off = 16; off; off >>= 1) m = fmaxf(m, __shfl_xor_sync(0xffffffffu, m, off));
            float sum = 0.f;
            for (int c = lane; c < 320; c += 32) {
                const float p = expf(S[r * ATT_SP + c] - m);
                S[r * ATT_SP + c] = p;
                sum += p;
            }
            #pragma unroll
            for (int off = 16; off; off >>= 1) sum += __shfl_xor_sync(0xffffffffu, sum, off);
            const float inv = 1.f / sum;
            for (int c = lane; c < 320; c += 32) S[r * ATT_SP + c] *= inv;
        }
    }

    float oacc[4][4];
    #pragma unroll
    for (int i = 0; i < 4; i++)
        #pragma unroll
        for (int j = 0; j < 4; j++) oacc[i][j] = 0.f;

    for (int it = 0; it < 5; it++) {
        const int kb = q0 + (it - 4) * 64;
        if (kb < 0) continue;
        __syncthreads();
        for (int e = t; e < 64 * 8; e += 256) {
            const int r = e >> 3, dg = (e & 7) * 8;
            float v[8];
            ld8h(v, qkv + ((size_t)(b * T_ + kb + r)) * (3 * C_) + 2 * C_ + h * D_ + dg);
            #pragma unroll
            for (int i = 0; i < 8; i++) KV[r * 65 + dg + i] = v[i];
        }
        __syncthreads();
        #pragma unroll 4
        for (int kk = 0; kk < 64; kk++) {
            float a[4], bb[4];
            #pragma unroll
            for (int i = 0; i < 4; i++) a[i]  = S[(r0 + i) * ATT_SP + it * 64 + kk];
            #pragma unroll
            for (int j = 0; j < 4; j++) bb[j] = KV[kk * 65 + c0 + j];
            #pragma unroll
            for (int i = 0; i < 4; i++)
                #pragma unroll
                for (int j = 0; j < 4; j++) oacc[i][j] = fmaf(a[i], bb[j], oacc[i][j]);
        }
    }
    #pragma unroll
    for (int i = 0; i < 4; i++)
        #pragma unroll
        for (int j = 0; j < 4; j++)
            o[((size_t)(b * T_ + q0 + r0 + i)) * C_ + h * D_ + c0 + j] = __float2half_rn(oacc[i][j]);
}

// ---------------------------------------------------------------------------
// Retrieval projection (fp32, tiny)
// ---------------------------------------------------------------------------
__global__ __launch_bounds__(256) void ret_kernel(
    const float* __restrict__ rc, const float* __restrict__ retW, float* __restrict__ ret)
{
    const int c = blockIdx.x * 256 + threadIdx.x;
    const int b = blockIdx.y;
    float acc = 0.f;
    for (int k = 0; k < C_; k++) acc = fmaf(rc[b * C_ + k], retW[(size_t)k * C_ + c], acc);
    ret[b * C_ + c] = acc;
}

// ---------------------------------------------------------------------------
// Gate + mix (h fp16)
// ---------------------------------------------------------------------------
__global__ __launch_bounds__(128) void gate_mix_kernel(
    const __half* __restrict__ hmat, const float* __restrict__ gW, const float* __restrict__ gb,
    const float* __restrict__ attn, const float* __restrict__ ret, float* __restrict__ x)
{
    __shared__ float red0[128], red2[128];
    __shared__ float gg0, gg2;
    const int tkn = blockIdx.x, tid = threadIdx.x;
    const __half* hrow = hmat + (size_t)tkn * C_;
    float p0 = 0.f, p2 = 0.f;
    for (int c = tid; c < C_; c += 128) {
        const float hv = __half2float(hrow[c]);
        p0 = fmaf(hv, gW[c * 3 + 0], p0);
        p2 = fmaf(hv, gW[c * 3 + 2], p2);
    }
    red0[tid] = p0; red2[tid] = p2; __syncthreads();
    for (int s = 64; s; s >>= 1) {
        if (tid < s) { red0[tid] += red0[tid + s]; red2[tid] += red2[tid + s]; }
        __syncthreads();
    }
    if (tid == 0) {
        const float l0 = red0[0] + gb[0];
        const float l2 = red2[0] + gb[2];
        const float m  = fmaxf(l0, l2);
        const float e0 = expf(l0 - m);
        const float e1 = expf(NEG_ - m);
        const float e2 = expf(l2 - m);
        const float inv = 1.f / (e0 + e1 + e2);
        gg0 = e0 * inv; gg2 = e2 * inv;
    }
    __syncthreads();
    const float a0 = gg0, a2 = gg2;
    const int b = tkn / T_;
    float* xrow = x + (size_t)tkn * C_;
    const float* arow = attn + (size_t)tkn * C_;
    for (int c = tid; c < C_; c += 128)
        xrow[c] += a0 * arow[c] + a2 * ret[b * C_ + c];
}

// ---------------------------------------------------------------------------
// Launcher
// ---------------------------------------------------------------------------
extern "C" void kernel_launch(void* const* d_in, const int* in_sizes, int n_in,
                              void* d_out, int out_size)
{
    (void)in_sizes; (void)n_in; (void)out_size;
    const float* x    = (const float*)d_in[0];
    const float* rc   = (const float*)d_in[1];
    const float* n1g  = (const float*)d_in[2];
    const float* Wqkv = (const float*)d_in[3];
    const float* Wpro = (const float*)d_in[4];
    const float* gW   = (const float*)d_in[5];
    const float* gb   = (const float*)d_in[6];
    const float* retW = (const float*)d_in[7];
    const float* n2g  = (const float*)d_in[8];
    const float* fgW  = (const float*)d_in[9];
    const float* fuW  = (const float*)d_in[10];
    const float* fdW  = (const float*)d_in[11];
    float* xo = (float*)d_out;

    __half *pH, *pH2, *pQKV, *pO, *pF1h, *pWH;
    float *pA, *pR;
    cudaGetSymbolAddress((void**)&pH,   g_h);
    cudaGetSymbolAddress((void**)&pH2,  g_h2);
    cudaGetSymbolAddress((void**)&pQKV, g_qkv);
    cudaGetSymbolAddress((void**)&pO,   g_o);
    cudaGetSymbolAddress((void**)&pA,   g_attn);
    cudaGetSymbolAddress((void**)&pF1h, g_f1h);
    cudaGetSymbolAddress((void**)&pR,   g_ret);
    cudaGetSymbolAddress((void**)&pWH,  g_wh);

    cudaFuncSetAttribute(attn_kernel, cudaFuncAttributeMaxDynamicSharedMemorySize, ATT_SMEM);
    cudaFuncSetAttribute(gemm_f16, cudaFuncAttributeMaxDynamicSharedMemorySize, GEMMH_SMEM);

    // Weight conversion / packing
    for (int l = 0; l < L_; l++) {
        __half* base = pWH + (size_t)l * WH_L;
        cvt_half_copy<<<1184, 256>>>(Wqkv + (size_t)l * 3 * C_ * C_, base + WH_QKV, 3 * C_ * C_ / 4);
        cvt_half_copy<<<1184, 256>>>(Wpro + (size_t)l * C_ * C_,     base + WH_PROJ, C_ * C_ / 4);
        cvt_gateup<<<1184, 256>>>(fgW + (size_t)l * C_ * F_, fuW + (size_t)l * C_ * F_,
                                  (__half2*)(base + WH_GU), C_ * F_);
        cvt_half_copy<<<1184, 256>>>(fdW  + (size_t)l * F_ * C_,     base + WH_DOWN, F_ * C_ / 4);
    }

    cudaMemcpyAsync(xo, x, sizeof(float) * (size_t)M_ * C_, cudaMemcpyDeviceToDevice);

    for (int l = 0; l < L_; l++) {
        __half* base = pWH + (size_t)l * WH_L;

        rmsnorm_kernel<<<M_, 128>>>(xo, n1g + l * C_, pH);

        gemm_f16<<<dim3(3 * C_ / 128, M_ / 128), 256, GEMMH_SMEM>>>(
            pH, base + WH_QKV, pQKV, 3 * C_, C_, 2 /*fp16 store*/);

        attn_kernel<<<dim3(T_ / 64, H_, B_), 256, ATT_SMEM>>>(pQKV, pO);

        gemm_f16<<<dim3(C_ / 128, M_ / 128), 256, GEMMH_SMEM>>>(
            pO, base + WH_PROJ, pA, C_, C_, 0 /*fp32 store*/);

        ret_kernel<<<dim3(C_ / 256, B_), 256>>>(rc, retW + (size_t)l * C_ * C_, pR);

        gate_mix_kernel<<<M_, 128>>>(pH, gW + (size_t)l * C_ * 3, gb + l * 3, pA, pR, xo);

        rmsnorm_kernel<<<M_, 128>>>(xo, n2g + l * C_, pH2);

        // fused gate+up+swiglu: N = 2F interleaved, out fp16 [M, F]
        gemm_f16<<<dim3(2 * F_ / 128, M_ / 128), 256, GEMMH_SMEM>>>(
            pH2, base + WH_GU, pF1h, 2 * F_, C_, 3 /*swiglu*/);

        gemm_f16<<<dim3(C_ / 128, M_ / 128), 256, GEMMH_SMEM>>>(
            pF1h, base + WH_DOWN, xo, C_, F_, 1 /*fp32 accumulate*/);
    }
}

// round 11
// speedup vs baseline: 4.5567x; 1.1485x over previous
#include <cuda_runtime.h>
#include <cuda_fp16.h>
#include <math.h>
#include <stdint.h>

// Problem constants
#define L_ 2
#define B_ 2
#define T_ 2048
#define C_ 1024
#define H_ 16
#define D_ 64
#define F_ 4096
#define WIN_ 256
#define M_ (B_*T_)   // 4096 tokens
#define NEG_ (-1e9f)

// ---------------------------------------------------------------------------
// Scratch
// ---------------------------------------------------------------------------
__device__ __align__(16) __half g_h  [M_*C_];    // rmsnorm1 out (fp16)
__device__ __align__(16) __half g_h2 [M_*C_];    // rmsnorm2 out (fp16)
__device__ __align__(16) __half g_qkv[M_*3*C_];  // qkv (fp16)
__device__ __align__(16) __half g_o  [M_*C_];    // attn out (fp16)
__device__ __align__(16) float  g_attn[M_*C_];
__device__ __align__(16) __half g_f1h[M_*F_];    // swiglu out (fp16)
__device__ __align__(16) float  g_ret[B_*C_];
// fp16 weights per layer: qkv | proj | gateup(interleaved, 2F cols) | down
#define WH_L    16777216
#define WH_QKV  0
#define WH_PROJ 3145728
#define WH_GU   4194304
#define WH_DOWN 12582912
__device__ __align__(16) __half g_wh[L_ * WH_L];

// ---------------------------------------------------------------------------
// Weight conversion kernels
// ---------------------------------------------------------------------------
__global__ __launch_bounds__(256) void cvt_half_copy(
    const float* __restrict__ src, __half* __restrict__ dst, int n4)
{
    int i = blockIdx.x * 256 + threadIdx.x;
    const int stride = gridDim.x * 256;
    for (; i < n4; i += stride) {
        const float4 v = *(const float4*)(src + 4 * (size_t)i);
        *(__half2*)(dst + 4 * (size_t)i)     = __floats2half2_rn(v.x, v.y);
        *(__half2*)(dst + 4 * (size_t)i + 2) = __floats2half2_rn(v.z, v.w);
    }
}

__global__ __launch_bounds__(256) void cvt_gateup(
    const float* __restrict__ gate, const float* __restrict__ up,
    __half2* __restrict__ dst2, int n)
{
    int i = blockIdx.x * 256 + threadIdx.x;
    const int stride = gridDim.x * 256;
    for (; i < n; i += stride)
        dst2[i] = __floats2half2_rn(gate[i], up[i]);
}

// ---------------------------------------------------------------------------
// RMSNorm (fp32 in, fp16 out)
// ---------------------------------------------------------------------------
__global__ __launch_bounds__(128) void rmsnorm_kernel(
    const float* __restrict__ x, const float* __restrict__ g, __half* __restrict__ out)
{
    __shared__ float red[128];
    __shared__ float rinv;
    const int tkn = blockIdx.x, tid = threadIdx.x;
    const float* row = x + (size_t)tkn * C_;
    float ss = 0.f;
    #pragma unroll
    for (int c = tid; c < C_; c += 128) { float v = row[c]; ss += v * v; }
    red[tid] = ss; __syncthreads();
    for (int s = 64; s; s >>= 1) { if (tid < s) red[tid] += red[tid + s]; __syncthreads(); }
    if (tid == 0) rinv = rsqrtf(red[0] * (1.0f / C_) + 1e-6f);
    __syncthreads();
    const float r = rinv;
    __half* orow = out + (size_t)tkn * C_;
    #pragma unroll
    for (int c = tid; c < C_; c += 128) orow[c] = __float2half_rn(row[c] * r * g[c]);
}

// ---------------------------------------------------------------------------
// mma / ldmatrix helpers
// ---------------------------------------------------------------------------
__device__ __forceinline__ void mma_f16(float c[4], const uint32_t a[4], const uint32_t b[2]) {
    asm volatile(
        "mma.sync.aligned.m16n8k16.row.col.f32.f16.f16.f32 "
        "{%0,%1,%2,%3}, {%4,%5,%6,%7}, {%8,%9}, {%0,%1,%2,%3};\n"
        : "+f"(c[0]), "+f"(c[1]), "+f"(c[2]), "+f"(c[3])
        : "r"(a[0]), "r"(a[1]), "r"(a[2]), "r"(a[3]), "r"(b[0]), "r"(b[1]));
}
__device__ __forceinline__ void ldsm_x4(uint32_t f[4], uint32_t addr) {
    asm volatile(
        "ldmatrix.sync.aligned.m8n8.x4.shared.b16 {%0,%1,%2,%3}, [%4];\n"
        : "=r"(f[0]), "=r"(f[1]), "=r"(f[2]), "=r"(f[3]) : "r"(addr));
}
__device__ __forceinline__ void ldsm_x4_t(uint32_t f[4], uint32_t addr) {
    asm volatile(
        "ldmatrix.sync.aligned.m8n8.x4.trans.shared.b16 {%0,%1,%2,%3}, [%4];\n"
        : "=r"(f[0]), "=r"(f[1]), "=r"(f[2]), "=r"(f[3]) : "r"(addr));
}
__device__ __forceinline__ uint32_t smem_u32(const void* p) {
    uint32_t a;
    asm("{ .reg .u64 t; cvta.to.shared.u64 t, %1; cvt.u32.u64 %0, t; }" : "=r"(a) : "l"(p));
    return a;
}

// ---------------------------------------------------------------------------
// FP16 tensor-core GEMM (unchanged from R9). Modes:
//   0: fp32 store  1: fp32 accumulate  2: fp16 store  3: swiglu fused
// ---------------------------------------------------------------------------
#define BKH 64
#define APH 72
#define BPH 136
#define ASTGH (128*APH)
#define BSTGH (BKH*BPH)
#define STGH  (ASTGH+BSTGH)
#define GEMMH_SMEM (3 * STGH * 2)

__device__ __forceinline__ void cp16(void* dst, const void* src) {
    uint32_t d = (uint32_t)__cvta_generic_to_shared(dst);
    asm volatile("cp.async.cg.shared.global [%0], [%1], 16;\n" :: "r"(d), "l"(src));
}

__global__ void __launch_bounds__(256, 2) gemm_f16(
    const __half* __restrict__ A, const __half* __restrict__ Bm, void* __restrict__ Cout,
    int Nd, int Kd, int mode)
{
    extern __shared__ __half smh[];
    #define ASH_(s,m,k)  smh[(s)*STGH + (m)*APH + (k)]
    #define BSH_(s,kr,n) smh[(s)*STGH + ASTGH + (kr)*BPH + (n)]

    const int t = threadIdx.x;
    const int w = t >> 5, lane = t & 31;
    const int r = lane >> 2, c = lane & 3;
    const int mb = (w >> 2) * 64;
    const int nb = (w & 3) * 32;
    const int bm = blockIdx.y * 128, bn = blockIdx.x * 128;

    const int offm = (lane & 7) + ((lane >> 3) & 1) * 8;
    const int offk = (lane >> 4) * 8;
    const int bfr = lane & 15;
    const int bfc = (lane >> 4) * 8;

    const int ar = t >> 1, ac0 = (t & 1) * 32;
    const int br = t >> 2, bc0 = (t & 3) * 32;
    const __half* Ag = A  + (size_t)(bm + ar) * Kd + ac0;
    const __half* Bg = Bm + (size_t)br * Nd + bn + bc0;

    float acc[16][4];
    #pragma unroll
    for (int i = 0; i < 16; i++)
        #pragma unroll
        for (int j = 0; j < 4; j++) acc[i][j] = 0.f;

    const int niter = Kd / BKH;

    #pragma unroll
    for (int p = 0; p < 2; p++) {
        const int kt = p * BKH;
        #pragma unroll
        for (int i = 0; i < 4; i++)
            cp16(&ASH_(p, ar, ac0 + i * 8), Ag + kt + i * 8);
        #pragma unroll
        for (int i = 0; i < 4; i++)
            cp16(&BSH_(p, br, bc0 + i * 8), Bg + (size_t)kt * Nd + i * 8);
        asm volatile("cp.async.commit_group;\n");
    }

    int st = 0;
    for (int it = 0; it < niter; it++) {
        asm volatile("cp.async.wait_group 1;\n");
        __syncthreads();

        if (it + 2 < niter) {
            const int ps = (st + 2) % 3;
            const int kt = (it + 2) * BKH;
            #pragma unroll
            for (int i = 0; i < 4; i++)
                cp16(&ASH_(ps, ar, ac0 + i * 8), Ag + kt + i * 8);
            #pragma unroll
            for (int i = 0; i < 4; i++)
                cp16(&BSH_(ps, br, bc0 + i * 8), Bg + (size_t)kt * Nd + i * 8);
        }
        asm volatile("cp.async.commit_group;\n");

        const uint32_t sbase = (uint32_t)__cvta_generic_to_shared(&smh[st * STGH]);

        #pragma unroll
        for (int ks = 0; ks < 4; ks++) {
            const int kb = ks * 16;
            uint32_t af[4][4], bf[2][4];
            #pragma unroll
            for (int mt = 0; mt < 4; mt++) {
                const uint32_t aaddr = sbase +
                    (uint32_t)(((mb + mt * 16 + offm) * APH + kb + offk) * 2);
                ldsm_x4(af[mt], aaddr);
            }
            #pragma unroll
            for (int nt2 = 0; nt2 < 2; nt2++) {
                const uint32_t baddr = sbase + (uint32_t)(ASTGH * 2) +
                    (uint32_t)(((kb + bfr) * BPH + nb + nt2 * 16 + bfc) * 2);
                ldsm_x4_t(bf[nt2], baddr);
            }
            #pragma unroll
            for (int mt = 0; mt < 4; mt++)
                #pragma unroll
                for (int nt = 0; nt < 4; nt++)
                    mma_f16(acc[mt * 4 + nt], af[mt], &bf[nt >> 1][(nt & 1) * 2]);
        }

        st = (st + 1) % 3;
    }

    if (mode == 3) {
        __half* po = (__half*)Cout;
        const int No = Nd >> 1;
        #pragma unroll
        for (int mt = 0; mt < 4; mt++) {
            const int row0 = bm + mb + mt * 16 + r;
            #pragma unroll
            for (int nt = 0; nt < 4; nt++) {
                const float* a4 = acc[mt * 4 + nt];
                const int nout = ((bn + nb + nt * 8) >> 1) + c;
                const float s0 = a4[0] / (1.f + expf(-a4[0]));
                const float s1 = a4[2] / (1.f + expf(-a4[2]));
                po[(size_t)row0 * No + nout]       = __float2half_rn(s0 * a4[1]);
                po[(size_t)(row0 + 8) * No + nout] = __float2half_rn(s1 * a4[3]);
            }
        }
    } else if (mode == 2) {
        __half* po = (__half*)Cout;
        #pragma unroll
        for (int mt = 0; mt < 4; mt++) {
            #pragma unroll
            for (int nt = 0; nt < 4; nt++) {
                const float* a4 = acc[mt * 4 + nt];
                const size_t base = (size_t)(bm + mb + mt * 16 + r) * Nd + bn + nb + nt * 8 + c * 2;
                *(__half2*)(po + base)                  = __floats2half2_rn(a4[0], a4[1]);
                *(__half2*)(po + base + 8 * (size_t)Nd) = __floats2half2_rn(a4[2], a4[3]);
            }
        }
    } else {
        float* po = (float*)Cout;
        #pragma unroll
        for (int mt = 0; mt < 4; mt++) {
            #pragma unroll
            for (int nt = 0; nt < 4; nt++) {
                const float* a4 = acc[mt * 4 + nt];
                float* p0 = po + (size_t)(bm + mb + mt * 16 + r) * Nd + bn + nb + nt * 8 + c * 2;
                float* p1 = p0 + 8 * (size_t)Nd;
                if (mode == 1) {
                    float2 v0 = *(float2*)p0;
                    float2 v1 = *(float2*)p1;
                    v0.x += a4[0]; v0.y += a4[1];
                    v1.x += a4[2]; v1.y += a4[3];
                    *(float2*)p0 = v0;
                    *(float2*)p1 = v1;
                } else {
                    *(float2*)p0 = make_float2(a4[0], a4[1]);
                    *(float2*)p1 = make_float2(a4[2], a4[3]);
                }
            }
        }
    }
    #undef ASH_
    #undef BSH_
}

// ---------------------------------------------------------------------------
// Tensor-core sliding-window attention.
// Per block: (b, h, 64-query tile), 256 threads (8 warps: 4 row x 2 col).
// QK^T and P@V on mma.m16n8k16; fp32 score slab + softmax; P slab fp16.
// ---------------------------------------------------------------------------
#define AQP 72    // Q/K/V smem pitch (halfs)
#define ASP 324   // score slab pitch (floats)
#define APP 328   // P slab pitch (halfs)
// bytes: Q 9216 | KV 9216 | S 82944 | P 41984
#define ATT_SMEM (9216 + 9216 + 82944 + 41984)

__global__ __launch_bounds__(256) void attn_kernel(
    const __half* __restrict__ qkv, __half* __restrict__ o)
{
    extern __shared__ char attsm[];
    __half* Qs = (__half*)attsm;
    __half* KV = (__half*)(attsm + 9216);
    float*  Sf = (float*)(attsm + 18432);
    __half* Ph = (__half*)(attsm + 101376);

    const int q0 = blockIdx.x * 64;
    const int h  = blockIdx.y;
    const int b  = blockIdx.z;
    const int t  = threadIdx.x;
    const int w  = t >> 5, lane = t & 31;
    const int wr = (w & 3) * 16;    // warp row offset (q)
    const int wc = (w >> 2) * 32;   // warp col offset (key / headdim)
    const int offm = (lane & 7) + ((lane >> 3) & 1) * 8;
    const int offk = (lane >> 4) * 8;
    const int bfr = lane & 15, bfc = (lane >> 4) * 8;
    const int r = lane >> 2, cq = lane & 3;
    const float scale = 0.125f;

    const uint32_t qs_b = smem_u32(Qs);
    const uint32_t kv_b = smem_u32(KV);
    const uint32_t ph_b = smem_u32(Ph);

    // Load Q tile (64 x 64 fp16)
    for (int e = t; e < 512; e += 256) {
        const int row = e >> 3, ch = (e & 7) * 8;
        *(uint4*)&Qs[row * AQP + ch] =
            *(const uint4*)(qkv + ((size_t)(b * T_ + q0 + row)) * (3 * C_) + h * D_ + ch);
    }

    // Phase 1: scores
    for (int it = 0; it < 5; it++) {
        const int kb = q0 + (it - 4) * 64;
        if (kb < 0) {
            for (int e = t; e < 64 * 64; e += 256)
                Sf[(e >> 6) * ASP + it * 64 + (e & 63)] = -1e30f;
            continue;
        }
        __syncthreads();
        for (int e = t; e < 512; e += 256) {
            const int row = e >> 3, ch = (e & 7) * 8;
            *(uint4*)&KV[row * AQP + ch] =
                *(const uint4*)(qkv + ((size_t)(b * T_ + kb + row)) * (3 * C_) + C_ + h * D_ + ch);
        }
        __syncthreads();

        float acc[4][4];
        #pragma unroll
        for (int i = 0; i < 4; i++)
            #pragma unroll
            for (int j = 0; j < 4; j++) acc[i][j] = 0.f;

        #pragma unroll
        for (int ks = 0; ks < 4; ks++) {
            uint32_t af[4], kfA[4], kfB[4];
            ldsm_x4(af,  qs_b + (uint32_t)(((wr + offm) * AQP + ks * 16 + offk) * 2));
            ldsm_x4(kfA, kv_b + (uint32_t)(((wc + offm) * AQP + ks * 16 + offk) * 2));
            ldsm_x4(kfB, kv_b + (uint32_t)(((wc + 16 + offm) * AQP + ks * 16 + offk) * 2));
            uint32_t b0[2] = {kfA[0], kfA[2]};
            uint32_t b1[2] = {kfA[1], kfA[3]};
            uint32_t b2[2] = {kfB[0], kfB[2]};
            uint32_t b3[2] = {kfB[1], kfB[3]};
            mma_f16(acc[0], af, b0);
            mma_f16(acc[1], af, b1);
            mma_f16(acc[2], af, b2);
            mma_f16(acc[3], af, b3);
        }

        // Mask + scale + store to slab
        #pragma unroll
        for (int nt = 0; nt < 4; nt++) {
            const int colg = wc + nt * 8 + cq * 2;
            #pragma unroll
            for (int half_ = 0; half_ < 2; half_++) {
                const int rowl = wr + r + half_ * 8;
                const int ig = q0 + rowl;
                #pragma unroll
                for (int jj = 0; jj < 2; jj++) {
                    const int jg = kb + colg + jj;
                    const bool ok = (jg <= ig) && (jg >= ig - (WIN_ - 1));
                    const float v = acc[nt][half_ * 2 + jj];
                    Sf[rowl * ASP + it * 64 + colg + jj] = ok ? v * scale : -1e30f;
                }
            }
        }
    }
    __syncthreads();

    // Phase 2: softmax (fp32 slab) -> fp16 P slab
    for (int rr = 0; rr < 8; rr++) {
        const int row = w * 8 + rr;
        float m = -1e30f;
        for (int c = lane; c < 320; c += 32) m = fmaxf(m, Sf[row * ASP + c]);
        #pragma unroll
        for (int off = 16; off; off >>= 1) m = fmaxf(m, __shfl_xor_sync(0xffffffffu, m, off));
        float sum = 0.f;
        for (int c = lane; c < 320; c += 32) {
            const float p = expf(Sf[row * ASP + c] - m);
            Sf[row * ASP + c] = p;
            sum += p;
        }
        #pragma unroll
        for (int off = 16; off; off >>= 1) sum += __shfl_xor_sync(0xffffffffu, sum, off);
        const float inv = 1.f / sum;
        for (int c = lane; c < 320; c += 32)
            Ph[row * APP + c] = __float2half_rn(Sf[row * ASP + c] * inv);
    }
    __syncthreads();

    // Phase 3: O = P @ V
    float oacc[4][4];
    #pragma unroll
    for (int i = 0; i < 4; i++)
        #pragma unroll
        for (int j = 0; j < 4; j++) oacc[i][j] = 0.f;

    for (int it = 0; it < 5; it++) {
        const int kb = q0 + (it - 4) * 64;
        if (kb < 0) continue;
        __syncthreads();
        for (int e = t; e < 512; e += 256) {
            const int row = e >> 3, ch = (e & 7) * 8;
            *(uint4*)&KV[row * AQP + ch] =
                *(const uint4*)(qkv + ((size_t)(b * T_ + kb + row)) * (3 * C_) + 2 * C_ + h * D_ + ch);
        }
        __syncthreads();

        #pragma unroll
        for (int ks = 0; ks < 4; ks++) {
            uint32_t af[4], vf[2][4];
            ldsm_x4(af, ph_b + (uint32_t)(((wr + offm) * APP + it * 64 + ks * 16 + offk) * 2));
            #pragma unroll
            for (int nt2 = 0; nt2 < 2; nt2++)
                ldsm_x4_t(vf[nt2],
                    kv_b + (uint32_t)(((ks * 16 + bfr) * AQP + wc + nt2 * 16 + bfc) * 2));
            #pragma unroll
            for (int nt = 0; nt < 4; nt++)
                mma_f16(oacc[nt], af, &vf[nt >> 1][(nt & 1) * 2]);
        }
    }

    // Output (fp16)
    #pragma unroll
    for (int nt = 0; nt < 4; nt++) {
        const int col = wc + nt * 8 + cq * 2;
        const float* a4 = oacc[nt];
        __half* p0 = o + ((size_t)(b * T_ + q0 + wr + r)) * C_ + h * D_ + col;
        *(__half2*)p0 = __floats2half2_rn(a4[0], a4[1]);
        *(__half2*)(p0 + 8 * (size_t)C_) = __floats2half2_rn(a4[2], a4[3]);
    }
}

// ---------------------------------------------------------------------------
// Retrieval projection (fp32, tiny)
// ---------------------------------------------------------------------------
__global__ __launch_bounds__(256) void ret_kernel(
    const float* __restrict__ rc, const float* __restrict__ retW, float* __restrict__ ret)
{
    const int c = blockIdx.x * 256 + threadIdx.x;
    const int b = blockIdx.y;
    float acc = 0.f;
    for (int k = 0; k < C_; k++) acc = fmaf(rc[b * C_ + k], retW[(size_t)k * C_ + c], acc);
    ret[b * C_ + c] = acc;
}

// ---------------------------------------------------------------------------
// Gate + mix (h fp16)
// ---------------------------------------------------------------------------
__global__ __launch_bounds__(128) void gate_mix_kernel(
    const __half* __restrict__ hmat, const float* __restrict__ gW, const float* __restrict__ gb,
    const float* __restrict__ attn, const float* __restrict__ ret, float* __restrict__ x)
{
    __shared__ float red0[128], red2[128];
    __shared__ float gg0, gg2;
    const int tkn = blockIdx.x, tid = threadIdx.x;
    const __half* hrow = hmat + (size_t)tkn * C_;
    float p0 = 0.f, p2 = 0.f;
    for (int c = tid; c < C_; c += 128) {
        const float hv = __half2float(hrow[c]);
        p0 = fmaf(hv, gW[c * 3 + 0], p0);
        p2 = fmaf(hv, gW[c * 3 + 2], p2);
    }
    red0[tid] = p0; red2[tid] = p2; __syncthreads();
    for (int s = 64; s; s >>= 1) {
        if (tid < s) { red0[tid] += red0[tid + s]; red2[tid] += red2[tid + s]; }
        __syncthreads();
    }
    if (tid == 0) {
        const float l0 = red0[0] + gb[0];
        const float l2 = red2[0] + gb[2];
        const float m  = fmaxf(l0, l2);
        const float e0 = expf(l0 - m);
        const float e1 = expf(NEG_ - m);
        const float e2 = expf(l2 - m);
        const float inv = 1.f / (e0 + e1 + e2);
        gg0 = e0 * inv; gg2 = e2 * inv;
    }
    __syncthreads();
    const float a0 = gg0, a2 = gg2;
    const int b = tkn / T_;
    float* xrow = x + (size_t)tkn * C_;
    const float* arow = attn + (size_t)tkn * C_;
    for (int c = tid; c < C_; c += 128)
        xrow[c] += a0 * arow[c] + a2 * ret[b * C_ + c];
}

// ---------------------------------------------------------------------------
// Launcher
// ---------------------------------------------------------------------------
extern "C" void kernel_launch(void* const* d_in, const int* in_sizes, int n_in,
                              void* d_out, int out_size)
{
    (void)in_sizes; (void)n_in; (void)out_size;
    const float* x    = (const float*)d_in[0];
    const float* rc   = (const float*)d_in[1];
    const float* n1g  = (const float*)d_in[2];
    const float* Wqkv = (const float*)d_in[3];
    const float* Wpro = (const float*)d_in[4];
    const float* gW   = (const float*)d_in[5];
    const float* gb   = (const float*)d_in[6];
    const float* retW = (const float*)d_in[7];
    const float* n2g  = (const float*)d_in[8];
    const float* fgW  = (const float*)d_in[9];
    const float* fuW  = (const float*)d_in[10];
    const float* fdW  = (const float*)d_in[11];
    float* xo = (float*)d_out;

    __half *pH, *pH2, *pQKV, *pO, *pF1h, *pWH;
    float *pA, *pR;
    cudaGetSymbolAddress((void**)&pH,   g_h);
    cudaGetSymbolAddress((void**)&pH2,  g_h2);
    cudaGetSymbolAddress((void**)&pQKV, g_qkv);
    cudaGetSymbolAddress((void**)&pO,   g_o);
    cudaGetSymbolAddress((void**)&pA,   g_attn);
    cudaGetSymbolAddress((void**)&pF1h, g_f1h);
    cudaGetSymbolAddress((void**)&pR,   g_ret);
    cudaGetSymbolAddress((void**)&pWH,  g_wh);

    cudaFuncSetAttribute(attn_kernel, cudaFuncAttributeMaxDynamicSharedMemorySize, ATT_SMEM);
    cudaFuncSetAttribute(gemm_f16, cudaFuncAttributeMaxDynamicSharedMemorySize, GEMMH_SMEM);

    // Weight conversion / packing
    for (int l = 0; l < L_; l++) {
        __half* base = pWH + (size_t)l * WH_L;
        cvt_half_copy<<<1184, 256>>>(Wqkv + (size_t)l * 3 * C_ * C_, base + WH_QKV, 3 * C_ * C_ / 4);
        cvt_half_copy<<<1184, 256>>>(Wpro + (size_t)l * C_ * C_,     base + WH_PROJ, C_ * C_ / 4);
        cvt_gateup<<<1184, 256>>>(fgW + (size_t)l * C_ * F_, fuW + (size_t)l * C_ * F_,
                                  (__half2*)(base + WH_GU), C_ * F_);
        cvt_half_copy<<<1184, 256>>>(fdW  + (size_t)l * F_ * C_,     base + WH_DOWN, F_ * C_ / 4);
    }

    cudaMemcpyAsync(xo, x, sizeof(float) * (size_t)M_ * C_, cudaMemcpyDeviceToDevice);

    for (int l = 0; l < L_; l++) {
        __half* base = pWH + (size_t)l * WH_L;

        rmsnorm_kernel<<<M_, 128>>>(xo, n1g + l * C_, pH);

        gemm_f16<<<dim3(3 * C_ / 128, M_ / 128), 256, GEMMH_SMEM>>>(
            pH, base + WH_QKV, pQKV, 3 * C_, C_, 2 /*fp16 store*/);

        attn_kernel<<<dim3(T_ / 64, H_, B_), 256, ATT_SMEM>>>(pQKV, pO);

        gemm_f16<<<dim3(C_ / 128, M_ / 128), 256, GEMMH_SMEM>>>(
            pO, base + WH_PROJ, pA, C_, C_, 0 /*fp32 store*/);

        ret_kernel<<<dim3(C_ / 256, B_), 256>>>(rc, retW + (size_t)l * C_ * C_, pR);

        gate_mix_kernel<<<M_, 128>>>(pH, gW + (size_t)l * C_ * 3, gb + l * 3, pA, pR, xo);

        rmsnorm_kernel<<<M_, 128>>>(xo, n2g + l * C_, pH2);

        gemm_f16<<<dim3(2 * F_ / 128, M_ / 128), 256, GEMMH_SMEM>>>(
            pH2, base + WH_GU, pF1h, 2 * F_, C_, 3 /*swiglu*/);

        gemm_f16<<<dim3(C_ / 128, M_ / 128), 256, GEMMH_SMEM>>>(
            pF1h, base + WH_DOWN, xo, C_, F_, 1 /*fp32 accumulate*/);
    }
}

// round 12
// speedup vs baseline: 4.6031x; 1.0102x over previous
#include <cuda_runtime.h>
#include <cuda_fp16.h>
#include <math.h>
#include <stdint.h>

// Problem constants
#define L_ 2
#define B_ 2
#define T_ 2048
#define C_ 1024
#define H_ 16
#define D_ 64
#define F_ 4096
#define WIN_ 256
#define M_ (B_*T_)   // 4096 tokens
#define NEG_ (-1e9f)

// ---------------------------------------------------------------------------
// Scratch
// ---------------------------------------------------------------------------
__device__ __align__(16) __half g_h  [M_*C_];    // rmsnorm1 out (fp16)
__device__ __align__(16) __half g_h2 [M_*C_];    // rmsnorm2 out (fp16)
__device__ __align__(16) __half g_qkv[M_*3*C_];  // qkv (fp16)
__device__ __align__(16) __half g_o  [M_*C_];    // attn out (fp16)
__device__ __align__(16) __half g_f1h[M_*F_];    // swiglu out (fp16)
__device__ __align__(16) float  g_ret[B_*C_];
__device__ __align__(16) float2 g_gates[M_];     // (g0, g2) per token
// fp16 weights per layer: qkv | proj | gateup(interleaved, 2F cols) | down
#define WH_L    16777216
#define WH_QKV  0
#define WH_PROJ 3145728
#define WH_GU   4194304
#define WH_DOWN 12582912
__device__ __align__(16) __half g_wh[L_ * WH_L];

// ---------------------------------------------------------------------------
// Weight conversion kernels
// ---------------------------------------------------------------------------
__global__ __launch_bounds__(256) void cvt_half_copy(
    const float* __restrict__ src, __half* __restrict__ dst, int n4)
{
    int i = blockIdx.x * 256 + threadIdx.x;
    const int stride = gridDim.x * 256;
    for (; i < n4; i += stride) {
        const float4 v = *(const float4*)(src + 4 * (size_t)i);
        *(__half2*)(dst + 4 * (size_t)i)     = __floats2half2_rn(v.x, v.y);
        *(__half2*)(dst + 4 * (size_t)i + 2) = __floats2half2_rn(v.z, v.w);
    }
}

__global__ __launch_bounds__(256) void cvt_gateup(
    const float* __restrict__ gate, const float* __restrict__ up,
    __half2* __restrict__ dst2, int n)
{
    int i = blockIdx.x * 256 + threadIdx.x;
    const int stride = gridDim.x * 256;
    for (; i < n; i += stride)
        dst2[i] = __floats2half2_rn(gate[i], up[i]);
}

// ---------------------------------------------------------------------------
// RMSNorm (fp32 in, fp16 out)
// ---------------------------------------------------------------------------
__global__ __launch_bounds__(128) void rmsnorm_kernel(
    const float* __restrict__ x, const float* __restrict__ g, __half* __restrict__ out)
{
    __shared__ float red[128];
    __shared__ float rinv;
    const int tkn = blockIdx.x, tid = threadIdx.x;
    const float* row = x + (size_t)tkn * C_;
    float ss = 0.f;
    #pragma unroll
    for (int c = tid; c < C_; c += 128) { float v = row[c]; ss += v * v; }
    red[tid] = ss; __syncthreads();
    for (int s = 64; s; s >>= 1) { if (tid < s) red[tid] += red[tid + s]; __syncthreads(); }
    if (tid == 0) rinv = rsqrtf(red[0] * (1.0f / C_) + 1e-6f);
    __syncthreads();
    const float r = rinv;
    __half* orow = out + (size_t)tkn * C_;
    #pragma unroll
    for (int c = tid; c < C_; c += 128) orow[c] = __float2half_rn(row[c] * r * g[c]);
}

// ---------------------------------------------------------------------------
// Per-token gate softmax: gates[t] = (softmax(l0, -1e9, l2)[0], [2])
// One warp per token.
// ---------------------------------------------------------------------------
__global__ __launch_bounds__(256) void gates_kernel(
    const __half* __restrict__ h, const float* __restrict__ gW, const float* __restrict__ gb,
    float2* __restrict__ gates)
{
    const int wid = threadIdx.x >> 5, lane = threadIdx.x & 31;
    const int tkn = blockIdx.x * 8 + wid;
    const __half* hrow = h + (size_t)tkn * C_;
    float p0 = 0.f, p2 = 0.f;
    #pragma unroll 4
    for (int c = lane; c < C_; c += 32) {
        const float hv = __half2float(hrow[c]);
        p0 = fmaf(hv, gW[c * 3 + 0], p0);
        p2 = fmaf(hv, gW[c * 3 + 2], p2);
    }
    #pragma unroll
    for (int off = 16; off; off >>= 1) {
        p0 += __shfl_xor_sync(0xffffffffu, p0, off);
        p2 += __shfl_xor_sync(0xffffffffu, p2, off);
    }
    if (lane == 0) {
        const float l0 = p0 + gb[0];
        const float l2 = p2 + gb[2];
        const float m  = fmaxf(l0, l2);
        const float e0 = expf(l0 - m);
        const float e1 = expf(NEG_ - m);
        const float e2 = expf(l2 - m);
        const float inv = 1.f / (e0 + e1 + e2);
        gates[tkn] = make_float2(e0 * inv, e2 * inv);
    }
}

// ---------------------------------------------------------------------------
// mma / ldmatrix helpers
// ---------------------------------------------------------------------------
__device__ __forceinline__ void mma_f16(float c[4], const uint32_t a[4], const uint32_t b[2]) {
    asm volatile(
        "mma.sync.aligned.m16n8k16.row.col.f32.f16.f16.f32 "
        "{%0,%1,%2,%3}, {%4,%5,%6,%7}, {%8,%9}, {%0,%1,%2,%3};\n"
        : "+f"(c[0]), "+f"(c[1]), "+f"(c[2]), "+f"(c[3])
        : "r"(a[0]), "r"(a[1]), "r"(a[2]), "r"(a[3]), "r"(b[0]), "r"(b[1]));
}
__device__ __forceinline__ void ldsm_x4(uint32_t f[4], uint32_t addr) {
    asm volatile(
        "ldmatrix.sync.aligned.m8n8.x4.shared.b16 {%0,%1,%2,%3}, [%4];\n"
        : "=r"(f[0]), "=r"(f[1]), "=r"(f[2]), "=r"(f[3]) : "r"(addr));
}
__device__ __forceinline__ void ldsm_x4_t(uint32_t f[4], uint32_t addr) {
    asm volatile(
        "ldmatrix.sync.aligned.m8n8.x4.trans.shared.b16 {%0,%1,%2,%3}, [%4];\n"
        : "=r"(f[0]), "=r"(f[1]), "=r"(f[2]), "=r"(f[3]) : "r"(addr));
}
__device__ __forceinline__ uint32_t smem_u32(const void* p) {
    uint32_t a;
    asm("{ .reg .u64 t; cvta.to.shared.u64 t, %1; cvt.u32.u64 %0, t; }" : "=r"(a) : "l"(p));
    return a;
}

// ---------------------------------------------------------------------------
// FP16 tensor-core GEMM. Modes:
//   0: fp32 store  1: fp32 accumulate  2: fp16 store  3: swiglu fused
//   4: gate-mix    x += g0*acc + g2*ret  (gates per row, ret per (batch,col))
// ---------------------------------------------------------------------------
#define BKH 64
#define APH 72
#define BPH 136
#define ASTGH (128*APH)
#define BSTGH (BKH*BPH)
#define STGH  (ASTGH+BSTGH)
#define GEMMH_SMEM (3 * STGH * 2)

__device__ __forceinline__ void cp16(void* dst, const void* src) {
    uint32_t d = (uint32_t)__cvta_generic_to_shared(dst);
    asm volatile("cp.async.cg.shared.global [%0], [%1], 16;\n" :: "r"(d), "l"(src));
}

__global__ void __launch_bounds__(256, 2) gemm_f16(
    const __half* __restrict__ A, const __half* __restrict__ Bm, void* __restrict__ Cout,
    int Nd, int Kd, int mode,
    const float2* __restrict__ gates, const float* __restrict__ retv)
{
    extern __shared__ __half smh[];
    #define ASH_(s,m,k)  smh[(s)*STGH + (m)*APH + (k)]
    #define BSH_(s,kr,n) smh[(s)*STGH + ASTGH + (kr)*BPH + (n)]

    const int t = threadIdx.x;
    const int w = t >> 5, lane = t & 31;
    const int r = lane >> 2, c = lane & 3;
    const int mb = (w >> 2) * 64;
    const int nb = (w & 3) * 32;
    const int bm = blockIdx.y * 128, bn = blockIdx.x * 128;

    const int offm = (lane & 7) + ((lane >> 3) & 1) * 8;
    const int offk = (lane >> 4) * 8;
    const int bfr = lane & 15;
    const int bfc = (lane >> 4) * 8;

    const int ar = t >> 1, ac0 = (t & 1) * 32;
    const int br = t >> 2, bc0 = (t & 3) * 32;
    const __half* Ag = A  + (size_t)(bm + ar) * Kd + ac0;
    const __half* Bg = Bm + (size_t)br * Nd + bn + bc0;

    float acc[16][4];
    #pragma unroll
    for (int i = 0; i < 16; i++)
        #pragma unroll
        for (int j = 0; j < 4; j++) acc[i][j] = 0.f;

    const int niter = Kd / BKH;

    #pragma unroll
    for (int p = 0; p < 2; p++) {
        const int kt = p * BKH;
        #pragma unroll
        for (int i = 0; i < 4; i++)
            cp16(&ASH_(p, ar, ac0 + i * 8), Ag + kt + i * 8);
        #pragma unroll
        for (int i = 0; i < 4; i++)
            cp16(&BSH_(p, br, bc0 + i * 8), Bg + (size_t)kt * Nd + i * 8);
        asm volatile("cp.async.commit_group;\n");
    }

    int st = 0;
    for (int it = 0; it < niter; it++) {
        asm volatile("cp.async.wait_group 1;\n");
        __syncthreads();

        if (it + 2 < niter) {
            const int ps = (st + 2) % 3;
            const int kt = (it + 2) * BKH;
            #pragma unroll
            for (int i = 0; i < 4; i++)
                cp16(&ASH_(ps, ar, ac0 + i * 8), Ag + kt + i * 8);
            #pragma unroll
            for (int i = 0; i < 4; i++)
                cp16(&BSH_(ps, br, bc0 + i * 8), Bg + (size_t)kt * Nd + i * 8);
        }
        asm volatile("cp.async.commit_group;\n");

        const uint32_t sbase = (uint32_t)__cvta_generic_to_shared(&smh[st * STGH]);

        #pragma unroll
        for (int ks = 0; ks < 4; ks++) {
            const int kb = ks * 16;
            uint32_t af[4][4], bf[2][4];
            #pragma unroll
            for (int mt = 0; mt < 4; mt++) {
                const uint32_t aaddr = sbase +
                    (uint32_t)(((mb + mt * 16 + offm) * APH + kb + offk) * 2);
                ldsm_x4(af[mt], aaddr);
            }
            #pragma unroll
            for (int nt2 = 0; nt2 < 2; nt2++) {
                const uint32_t baddr = sbase + (uint32_t)(ASTGH * 2) +
                    (uint32_t)(((kb + bfr) * BPH + nb + nt2 * 16 + bfc) * 2);
                ldsm_x4_t(bf[nt2], baddr);
            }
            #pragma unroll
            for (int mt = 0; mt < 4; mt++)
                #pragma unroll
                for (int nt = 0; nt < 4; nt++)
                    mma_f16(acc[mt * 4 + nt], af[mt], &bf[nt >> 1][(nt & 1) * 2]);
        }

        st = (st + 1) % 3;
    }

    if (mode == 4) {
        // x += g0*acc + g2*ret ; one batch per tile (128 | T_)
        float* xo = (float*)Cout;
        const float* retb = retv + (size_t)(bm / T_) * C_;
        #pragma unroll
        for (int mt = 0; mt < 4; mt++) {
            const int row0 = bm + mb + mt * 16 + r;
            const float2 gA = gates[row0];
            const float2 gB = gates[row0 + 8];
            #pragma unroll
            for (int nt = 0; nt < 4; nt++) {
                const float* a4 = acc[mt * 4 + nt];
                const int col = bn + nb + nt * 8 + c * 2;
                const float2 rv = *(const float2*)(retb + col);
                float* p0 = xo + (size_t)row0 * Nd + col;
                float* p1 = p0 + 8 * (size_t)Nd;
                float2 v0 = *(float2*)p0;
                float2 v1 = *(float2*)p1;
                v0.x += gA.x * a4[0] + gA.y * rv.x;
                v0.y += gA.x * a4[1] + gA.y * rv.y;
                v1.x += gB.x * a4[2] + gB.y * rv.x;
                v1.y += gB.x * a4[3] + gB.y * rv.y;
                *(float2*)p0 = v0;
                *(float2*)p1 = v1;
            }
        }
    } else if (mode == 3) {
        __half* po = (__half*)Cout;
        const int No = Nd >> 1;
        #pragma unroll
        for (int mt = 0; mt < 4; mt++) {
            const int row0 = bm + mb + mt * 16 + r;
            #pragma unroll
            for (int nt = 0; nt < 4; nt++) {
                const float* a4 = acc[mt * 4 + nt];
                const int nout = ((bn + nb + nt * 8) >> 1) + c;
                const float s0 = a4[0] / (1.f + expf(-a4[0]));
                const float s1 = a4[2] / (1.f + expf(-a4[2]));
                po[(size_t)row0 * No + nout]       = __float2half_rn(s0 * a4[1]);
                po[(size_t)(row0 + 8) * No + nout] = __float2half_rn(s1 * a4[3]);
            }
        }
    } else if (mode == 2) {
        __half* po = (__half*)Cout;
        #pragma unroll
        for (int mt = 0; mt < 4; mt++) {
            #pragma unroll
            for (int nt = 0; nt < 4; nt++) {
                const float* a4 = acc[mt * 4 + nt];
                const size_t base = (size_t)(bm + mb + mt * 16 + r) * Nd + bn + nb + nt * 8 + c * 2;
                *(__half2*)(po + base)                  = __floats2half2_rn(a4[0], a4[1]);
                *(__half2*)(po + base + 8 * (size_t)Nd) = __floats2half2_rn(a4[2], a4[3]);
            }
        }
    } else {
        float* po = (float*)Cout;
        #pragma unroll
        for (int mt = 0; mt < 4; mt++) {
            #pragma unroll
            for (int nt = 0; nt < 4; nt++) {
                const float* a4 = acc[mt * 4 + nt];
                float* p0 = po + (size_t)(bm + mb + mt * 16 + r) * Nd + bn + nb + nt * 8 + c * 2;
                float* p1 = p0 + 8 * (size_t)Nd;
                if (mode == 1) {
                    float2 v0 = *(float2*)p0;
                    float2 v1 = *(float2*)p1;
                    v0.x += a4[0]; v0.y += a4[1];
                    v1.x += a4[2]; v1.y += a4[3];
                    *(float2*)p0 = v0;
                    *(float2*)p1 = v1;
                } else {
                    *(float2*)p0 = make_float2(a4[0], a4[1]);
                    *(float2*)p1 = make_float2(a4[2], a4[3]);
                }
            }
        }
    }
    #undef ASH_
    #undef BSH_
}

// ---------------------------------------------------------------------------
// Tensor-core sliding-window attention (unchanged from R11)
// ---------------------------------------------------------------------------
#define AQP 72
#define ASP 324
#define APP 328
#define ATT_SMEM (9216 + 9216 + 82944 + 41984)

__global__ __launch_bounds__(256) void attn_kernel(
    const __half* __restrict__ qkv, __half* __restrict__ o)
{
    extern __shared__ char attsm[];
    __half* Qs = (__half*)attsm;
    __half* KV = (__half*)(attsm + 9216);
    float*  Sf = (float*)(attsm + 18432);
    __half* Ph = (__half*)(attsm + 101376);

    const int q0 = blockIdx.x * 64;
    const int h  = blockIdx.y;
    const int b  = blockIdx.z;
    const int t  = threadIdx.x;
    const int w  = t >> 5, lane = t & 31;
    const int wr = (w & 3) * 16;
    const int wc = (w >> 2) * 32;
    const int offm = (lane & 7) + ((lane >> 3) & 1) * 8;
    const int offk = (lane >> 4) * 8;
    const int bfr = lane & 15, bfc = (lane >> 4) * 8;
    const int r = lane >> 2, cq = lane & 3;
    const float scale = 0.125f;

    const uint32_t qs_b = smem_u32(Qs);
    const uint32_t kv_b = smem_u32(KV);
    const uint32_t ph_b = smem_u32(Ph);

    for (int e = t; e < 512; e += 256) {
        const int row = e >> 3, ch = (e & 7) * 8;
        *(uint4*)&Qs[row * AQP + ch] =
            *(const uint4*)(qkv + ((size_t)(b * T_ + q0 + row)) * (3 * C_) + h * D_ + ch);
    }

    for (int it = 0; it < 5; it++) {
        const int kb = q0 + (it - 4) * 64;
        if (kb < 0) {
            for (int e = t; e < 64 * 64; e += 256)
                Sf[(e >> 6) * ASP + it * 64 + (e & 63)] = -1e30f;
            continue;
        }
        __syncthreads();
        for (int e = t; e < 512; e += 256) {
            const int row = e >> 3, ch = (e & 7) * 8;
            *(uint4*)&KV[row * AQP + ch] =
                *(const uint4*)(qkv + ((size_t)(b * T_ + kb + row)) * (3 * C_) + C_ + h * D_ + ch);
        }
        __syncthreads();

        float acc[4][4];
        #pragma unroll
        for (int i = 0; i < 4; i++)
            #pragma unroll
            for (int j = 0; j < 4; j++) acc[i][j] = 0.f;

        #pragma unroll
        for (int ks = 0; ks < 4; ks++) {
            uint32_t af[4], kfA[4], kfB[4];
            ldsm_x4(af,  qs_b + (uint32_t)(((wr + offm) * AQP + ks * 16 + offk) * 2));
            ldsm_x4(kfA, kv_b + (uint32_t)(((wc + offm) * AQP + ks * 16 + offk) * 2));
            ldsm_x4(kfB, kv_b + (uint32_t)(((wc + 16 + offm) * AQP + ks * 16 + offk) * 2));
            uint32_t b0[2] = {kfA[0], kfA[2]};
            uint32_t b1[2] = {kfA[1], kfA[3]};
            uint32_t b2[2] = {kfB[0], kfB[2]};
            uint32_t b3[2] = {kfB[1], kfB[3]};
            mma_f16(acc[0], af, b0);
            mma_f16(acc[1], af, b1);
            mma_f16(acc[2], af, b2);
            mma_f16(acc[3], af, b3);
        }

        #pragma unroll
        for (int nt = 0; nt < 4; nt++) {
            const int colg = wc + nt * 8 + cq * 2;
            #pragma unroll
            for (int half_ = 0; half_ < 2; half_++) {
                const int rowl = wr + r + half_ * 8;
                const int ig = q0 + rowl;
                #pragma unroll
                for (int jj = 0; jj < 2; jj++) {
                    const int jg = kb + colg + jj;
                    const bool ok = (jg <= ig) && (jg >= ig - (WIN_ - 1));
                    const float v = acc[nt][half_ * 2 + jj];
                    Sf[rowl * ASP + it * 64 + colg + jj] = ok ? v * scale : -1e30f;
                }
            }
        }
    }
    __syncthreads();

    for (int rr = 0; rr < 8; rr++) {
        const int row = w * 8 + rr;
        float m = -1e30f;
        for (int c = lane; c < 320; c += 32) m = fmaxf(m, Sf[row * ASP + c]);
        #pragma unroll
        for (int off = 16; off; off >>= 1) m = fmaxf(m, __shfl_xor_sync(0xffffffffu, m, off));
        float sum = 0.f;
        for (int c = lane; c < 320; c += 32) {
            const float p = expf(Sf[row * ASP + c] - m);
            Sf[row * ASP + c] = p;
            sum += p;
        }
        #pragma unroll
        for (int off = 16; off; off >>= 1) sum += __shfl_xor_sync(0xffffffffu, sum, off);
        const float inv = 1.f / sum;
        for (int c = lane; c < 320; c += 32)
            Ph[row * APP + c] = __float2half_rn(Sf[row * ASP + c] * inv);
    }
    __syncthreads();

    float oacc[4][4];
    #pragma unroll
    for (int i = 0; i < 4; i++)
        #pragma unroll
        for (int j = 0; j < 4; j++) oacc[i][j] = 0.f;

    for (int it = 0; it < 5; it++) {
        const int kb = q0 + (it - 4) * 64;
        if (kb < 0) continue;
        __syncthreads();
        for (int e = t; e < 512; e += 256) {
            const int row = e >> 3, ch = (e & 7) * 8;
            *(uint4*)&KV[row * AQP + ch] =
                *(const uint4*)(qkv + ((size_t)(b * T_ + kb + row)) * (3 * C_) + 2 * C_ + h * D_ + ch);
        }
        __syncthreads();

        #pragma unroll
        for (int ks = 0; ks < 4; ks++) {
            uint32_t af[4], vf[2][4];
            ldsm_x4(af, ph_b + (uint32_t)(((wr + offm) * APP + it * 64 + ks * 16 + offk) * 2));
            #pragma unroll
            for (int nt2 = 0; nt2 < 2; nt2++)
                ldsm_x4_t(vf[nt2],
                    kv_b + (uint32_t)(((ks * 16 + bfr) * AQP + wc + nt2 * 16 + bfc) * 2));
            #pragma unroll
            for (int nt = 0; nt < 4; nt++)
                mma_f16(oacc[nt], af, &vf[nt >> 1][(nt & 1) * 2]);
        }
    }

    #pragma unroll
    for (int nt = 0; nt < 4; nt++) {
        const int col = wc + nt * 8 + cq * 2;
        const float* a4 = oacc[nt];
        __half* p0 = o + ((size_t)(b * T_ + q0 + wr + r)) * C_ + h * D_ + col;
        *(__half2*)p0 = __floats2half2_rn(a4[0], a4[1]);
        *(__half2*)(p0 + 8 * (size_t)C_) = __floats2half2_rn(a4[2], a4[3]);
    }
}

// ---------------------------------------------------------------------------
// Retrieval projection (fp32, tiny)
// ---------------------------------------------------------------------------
__global__ __launch_bounds__(256) void ret_kernel(
    const float* __restrict__ rc, const float* __restrict__ retW, float* __restrict__ ret)
{
    const int c = blockIdx.x * 256 + threadIdx.x;
    const int b = blockIdx.y;
    float acc = 0.f;
    for (int k = 0; k < C_; k++) acc = fmaf(rc[b * C_ + k], retW[(size_t)k * C_ + c], acc);
    ret[b * C_ + c] = acc;
}

// ---------------------------------------------------------------------------
// Launcher
// ---------------------------------------------------------------------------
extern "C" void kernel_launch(void* const* d_in, const int* in_sizes, int n_in,
                              void* d_out, int out_size)
{
    (void)in_sizes; (void)n_in; (void)out_size;
    const float* x    = (const float*)d_in[0];
    const float* rc   = (const float*)d_in[1];
    const float* n1g  = (const float*)d_in[2];
    const float* Wqkv = (const float*)d_in[3];
    const float* Wpro = (const float*)d_in[4];
    const float* gW   = (const float*)d_in[5];
    const float* gb   = (const float*)d_in[6];
    const float* retW = (const float*)d_in[7];
    const float* n2g  = (const float*)d_in[8];
    const float* fgW  = (const float*)d_in[9];
    const float* fuW  = (const float*)d_in[10];
    const float* fdW  = (const float*)d_in[11];
    float* xo = (float*)d_out;

    __half *pH, *pH2, *pQKV, *pO, *pF1h, *pWH;
    float *pR;
    float2 *pG;
    cudaGetSymbolAddress((void**)&pH,   g_h);
    cudaGetSymbolAddress((void**)&pH2,  g_h2);
    cudaGetSymbolAddress((void**)&pQKV, g_qkv);
    cudaGetSymbolAddress((void**)&pO,   g_o);
    cudaGetSymbolAddress((void**)&pF1h, g_f1h);
    cudaGetSymbolAddress((void**)&pR,   g_ret);
    cudaGetSymbolAddress((void**)&pG,   g_gates);
    cudaGetSymbolAddress((void**)&pWH,  g_wh);

    cudaFuncSetAttribute(attn_kernel, cudaFuncAttributeMaxDynamicSharedMemorySize, ATT_SMEM);
    cudaFuncSetAttribute(gemm_f16, cudaFuncAttributeMaxDynamicSharedMemorySize, GEMMH_SMEM);

    // Weight conversion / packing
    for (int l = 0; l < L_; l++) {
        __half* base = pWH + (size_t)l * WH_L;
        cvt_half_copy<<<1184, 256>>>(Wqkv + (size_t)l * 3 * C_ * C_, base + WH_QKV, 3 * C_ * C_ / 4);
        cvt_half_copy<<<1184, 256>>>(Wpro + (size_t)l * C_ * C_,     base + WH_PROJ, C_ * C_ / 4);
        cvt_gateup<<<1184, 256>>>(fgW + (size_t)l * C_ * F_, fuW + (size_t)l * C_ * F_,
                                  (__half2*)(base + WH_GU), C_ * F_);
        cvt_half_copy<<<1184, 256>>>(fdW  + (size_t)l * F_ * C_,     base + WH_DOWN, F_ * C_ / 4);
    }

    cudaMemcpyAsync(xo, x, sizeof(float) * (size_t)M_ * C_, cudaMemcpyDeviceToDevice);

    for (int l = 0; l < L_; l++) {
        __half* base = pWH + (size_t)l * WH_L;

        rmsnorm_kernel<<<M_, 128>>>(xo, n1g + l * C_, pH);

        gemm_f16<<<dim3(3 * C_ / 128, M_ / 128), 256, GEMMH_SMEM>>>(
            pH, base + WH_QKV, pQKV, 3 * C_, C_, 2, nullptr, nullptr);

        attn_kernel<<<dim3(T_ / 64, H_, B_), 256, ATT_SMEM>>>(pQKV, pO);

        ret_kernel<<<dim3(C_ / 256, B_), 256>>>(rc, retW + (size_t)l * C_ * C_, pR);
        gates_kernel<<<M_ / 8, 256>>>(pH, gW + (size_t)l * C_ * 3, gb + l * 3, pG);

        // proj GEMM with fused gate-mix epilogue: x += g0*(o@Wproj) + g2*ret
        gemm_f16<<<dim3(C_ / 128, M_ / 128), 256, GEMMH_SMEM>>>(
            pO, base + WH_PROJ, xo, C_, C_, 4, pG, pR);

        rmsnorm_kernel<<<M_, 128>>>(xo, n2g + l * C_, pH2);

        gemm_f16<<<dim3(2 * F_ / 128, M_ / 128), 256, GEMMH_SMEM>>>(
            pH2, base + WH_GU, pF1h, 2 * F_, C_, 3, nullptr, nullptr);

        gemm_f16<<<dim3(C_ / 128, M_ / 128), 256, GEMMH_SMEM>>>(
            pF1h, base + WH_DOWN, xo, C_, F_, 1, nullptr, nullptr);
    }
}

// round 13
// speedup vs baseline: 4.6513x; 1.0105x over previous
#include <cuda_runtime.h>
#include <cuda_fp16.h>
#include <math.h>
#include <stdint.h>

// Problem constants
#define L_ 2
#define B_ 2
#define T_ 2048
#define C_ 1024
#define H_ 16
#define D_ 64
#define F_ 4096
#define WIN_ 256
#define M_ (B_*T_)   // 4096 tokens
#define NEG_ (-1e9f)

// ---------------------------------------------------------------------------
// Scratch
// ---------------------------------------------------------------------------
__device__ __align__(16) __half g_h  [M_*C_];    // rmsnorm1 out (fp16)
__device__ __align__(16) __half g_h2 [M_*C_];    // rmsnorm2 out (fp16)
__device__ __align__(16) __half g_qkv[M_*3*C_];  // qkv (fp16)
__device__ __align__(16) __half g_o  [M_*C_];    // attn out (fp16)
__device__ __align__(16) __half g_f1h[M_*F_];    // swiglu out (fp16)
__device__ __align__(16) float  g_ret[B_*C_];
__device__ __align__(16) float2 g_gates[M_];     // (g0, g2) per token
// fp16 weights per layer: qkv | proj | gateup(interleaved, 2F cols) | down
#define WH_L    16777216
#define WH_QKV  0
#define WH_PROJ 3145728
#define WH_GU   4194304
#define WH_DOWN 12582912
__device__ __align__(16) __half g_wh[L_ * WH_L];

// ---------------------------------------------------------------------------
// Fused weight prep: one launch converts/packs ALL weights for both layers.
// Work units (per layer): qkv 3CC/4 float4 | proj CC/4 | gu CF half2-pairs/2
// (processed as 2 pairs per unit) | down FC/4.
// ---------------------------------------------------------------------------
#define PW_QKV4  (3*C_*C_/4)          // 786432
#define PW_PROJ4 (C_*C_/4)            // 262144
#define PW_GU2   (C_*F_/2)            // 2097152 (each does 2 interleaved pairs)
#define PW_DOWN4 (F_*C_/4)            // 1048576
#define PW_PER_L (PW_QKV4 + PW_PROJ4 + PW_GU2 + PW_DOWN4)

__global__ __launch_bounds__(256) void prep_weights(
    const float* __restrict__ Wqkv, const float* __restrict__ Wpro,
    const float* __restrict__ fgW,  const float* __restrict__ fuW,
    const float* __restrict__ fdW,  __half* __restrict__ wh)
{
    const int total = L_ * PW_PER_L;
    const int stride = gridDim.x * 256;
    for (int i = blockIdx.x * 256 + threadIdx.x; i < total; i += stride) {
        const int l = i / PW_PER_L;
        int j = i - l * PW_PER_L;
        __half* base = wh + (size_t)l * WH_L;
        if (j < PW_QKV4) {
            const float4 v = *(const float4*)(Wqkv + (size_t)l * 3 * C_ * C_ + 4 * (size_t)j);
            __half2* d = (__half2*)(base + WH_QKV + 4 * (size_t)j);
            d[0] = __floats2half2_rn(v.x, v.y);
            d[1] = __floats2half2_rn(v.z, v.w);
            continue;
        }
        j -= PW_QKV4;
        if (j < PW_PROJ4) {
            const float4 v = *(const float4*)(Wpro + (size_t)l * C_ * C_ + 4 * (size_t)j);
            __half2* d = (__half2*)(base + WH_PROJ + 4 * (size_t)j);
            d[0] = __floats2half2_rn(v.x, v.y);
            d[1] = __floats2half2_rn(v.z, v.w);
            continue;
        }
        j -= PW_PROJ4;
        if (j < PW_GU2) {
            // two adjacent (gate,up) pairs
            const size_t e = 2 * (size_t)j;
            const float2 gv = *(const float2*)(fgW + (size_t)l * C_ * F_ + e);
            const float2 uv = *(const float2*)(fuW + (size_t)l * C_ * F_ + e);
            __half2* d = (__half2*)(base + WH_GU + 2 * e);
            d[0] = __floats2half2_rn(gv.x, uv.x);
            d[1] = __floats2half2_rn(gv.y, uv.y);
            continue;
        }
        j -= PW_GU2;
        {
            const float4 v = *(const float4*)(fdW + (size_t)l * F_ * C_ + 4 * (size_t)j);
            __half2* d = (__half2*)(base + WH_DOWN + 4 * (size_t)j);
            d[0] = __floats2half2_rn(v.x, v.y);
            d[1] = __floats2half2_rn(v.z, v.w);
        }
    }
}

// ---------------------------------------------------------------------------
// RMSNorm (fp32 in, fp16 out), vectorized: 256 threads, 1 float4/thread.
// ---------------------------------------------------------------------------
__global__ __launch_bounds__(256) void rmsnorm_kernel(
    const float* __restrict__ x, const float* __restrict__ g, __half* __restrict__ out)
{
    __shared__ float red[8];
    __shared__ float rinv;
    const int tkn = blockIdx.x, tid = threadIdx.x;
    const int lane = tid & 31, w = tid >> 5;
    const float4 v = *(const float4*)(x + (size_t)tkn * C_ + tid * 4);
    float ss = v.x * v.x + v.y * v.y + v.z * v.z + v.w * v.w;
    #pragma unroll
    for (int off = 16; off; off >>= 1) ss += __shfl_xor_sync(0xffffffffu, ss, off);
    if (lane == 0) red[w] = ss;
    __syncthreads();
    if (tid == 0) {
        float s = 0.f;
        #pragma unroll
        for (int i = 0; i < 8; i++) s += red[i];
        rinv = rsqrtf(s * (1.0f / C_) + 1e-6f);
    }
    __syncthreads();
    const float r = rinv;
    const float4 gv = *(const float4*)(g + tid * 4);
    __half2* orow = (__half2*)(out + (size_t)tkn * C_ + tid * 4);
    orow[0] = __floats2half2_rn(v.x * r * gv.x, v.y * r * gv.y);
    orow[1] = __floats2half2_rn(v.z * r * gv.z, v.w * r * gv.w);
}

// ---------------------------------------------------------------------------
// Per-token gate softmax: one warp per token.
// ---------------------------------------------------------------------------
__global__ __launch_bounds__(256) void gates_kernel(
    const __half* __restrict__ h, const float* __restrict__ gW, const float* __restrict__ gb,
    float2* __restrict__ gates)
{
    const int wid = threadIdx.x >> 5, lane = threadIdx.x & 31;
    const int tkn = blockIdx.x * 8 + wid;
    const __half* hrow = h + (size_t)tkn * C_;
    float p0 = 0.f, p2 = 0.f;
    #pragma unroll 4
    for (int c = lane; c < C_; c += 32) {
        const float hv = __half2float(hrow[c]);
        p0 = fmaf(hv, gW[c * 3 + 0], p0);
        p2 = fmaf(hv, gW[c * 3 + 2], p2);
    }
    #pragma unroll
    for (int off = 16; off; off >>= 1) {
        p0 += __shfl_xor_sync(0xffffffffu, p0, off);
        p2 += __shfl_xor_sync(0xffffffffu, p2, off);
    }
    if (lane == 0) {
        const float l0 = p0 + gb[0];
        const float l2 = p2 + gb[2];
        const float m  = fmaxf(l0, l2);
        const float e0 = expf(l0 - m);
        const float e1 = expf(NEG_ - m);
        const float e2 = expf(l2 - m);
        const float inv = 1.f / (e0 + e1 + e2);
        gates[tkn] = make_float2(e0 * inv, e2 * inv);
    }
}

// ---------------------------------------------------------------------------
// mma / ldmatrix helpers
// ---------------------------------------------------------------------------
__device__ __forceinline__ void mma_f16(float c[4], const uint32_t a[4], const uint32_t b[2]) {
    asm volatile(
        "mma.sync.aligned.m16n8k16.row.col.f32.f16.f16.f32 "
        "{%0,%1,%2,%3}, {%4,%5,%6,%7}, {%8,%9}, {%0,%1,%2,%3};\n"
        : "+f"(c[0]), "+f"(c[1]), "+f"(c[2]), "+f"(c[3])
        : "r"(a[0]), "r"(a[1]), "r"(a[2]), "r"(a[3]), "r"(b[0]), "r"(b[1]));
}
__device__ __forceinline__ void ldsm_x4(uint32_t f[4], uint32_t addr) {
    asm volatile(
        "ldmatrix.sync.aligned.m8n8.x4.shared.b16 {%0,%1,%2,%3}, [%4];\n"
        : "=r"(f[0]), "=r"(f[1]), "=r"(f[2]), "=r"(f[3]) : "r"(addr));
}
__device__ __forceinline__ void ldsm_x4_t(uint32_t f[4], uint32_t addr) {
    asm volatile(
        "ldmatrix.sync.aligned.m8n8.x4.trans.shared.b16 {%0,%1,%2,%3}, [%4];\n"
        : "=r"(f[0]), "=r"(f[1]), "=r"(f[2]), "=r"(f[3]) : "r"(addr));
}
__device__ __forceinline__ uint32_t smem_u32(const void* p) {
    uint32_t a;
    asm("{ .reg .u64 t; cvta.to.shared.u64 t, %1; cvt.u32.u64 %0, t; }" : "=r"(a) : "l"(p));
    return a;
}

// ---------------------------------------------------------------------------
// FP16 tensor-core GEMM (unchanged). Modes:
//   0: fp32 store  1: fp32 accumulate  2: fp16 store  3: swiglu  4: gate-mix
// ---------------------------------------------------------------------------
#define BKH 64
#define APH 72
#define BPH 136
#define ASTGH (128*APH)
#define BSTGH (BKH*BPH)
#define STGH  (ASTGH+BSTGH)
#define GEMMH_SMEM (3 * STGH * 2)

__device__ __forceinline__ void cp16(void* dst, const void* src) {
    uint32_t d = (uint32_t)__cvta_generic_to_shared(dst);
    asm volatile("cp.async.cg.shared.global [%0], [%1], 16;\n" :: "r"(d), "l"(src));
}

__global__ void __launch_bounds__(256, 2) gemm_f16(
    const __half* __restrict__ A, const __half* __restrict__ Bm, void* __restrict__ Cout,
    int Nd, int Kd, int mode,
    const float2* __restrict__ gates, const float* __restrict__ retv)
{
    extern __shared__ __half smh[];
    #define ASH_(s,m,k)  smh[(s)*STGH + (m)*APH + (k)]
    #define BSH_(s,kr,n) smh[(s)*STGH + ASTGH + (kr)*BPH + (n)]

    const int t = threadIdx.x;
    const int w = t >> 5, lane = t & 31;
    const int r = lane >> 2, c = lane & 3;
    const int mb = (w >> 2) * 64;
    const int nb = (w & 3) * 32;
    const int bm = blockIdx.y * 128, bn = blockIdx.x * 128;

    const int offm = (lane & 7) + ((lane >> 3) & 1) * 8;
    const int offk = (lane >> 4) * 8;
    const int bfr = lane & 15;
    const int bfc = (lane >> 4) * 8;

    const int ar = t >> 1, ac0 = (t & 1) * 32;
    const int br = t >> 2, bc0 = (t & 3) * 32;
    const __half* Ag = A  + (size_t)(bm + ar) * Kd + ac0;
    const __half* Bg = Bm + (size_t)br * Nd + bn + bc0;

    float acc[16][4];
    #pragma unroll
    for (int i = 0; i < 16; i++)
        #pragma unroll
        for (int j = 0; j < 4; j++) acc[i][j] = 0.f;

    const int niter = Kd / BKH;

    #pragma unroll
    for (int p = 0; p < 2; p++) {
        const int kt = p * BKH;
        #pragma unroll
        for (int i = 0; i < 4; i++)
            cp16(&ASH_(p, ar, ac0 + i * 8), Ag + kt + i * 8);
        #pragma unroll
        for (int i = 0; i < 4; i++)
            cp16(&BSH_(p, br, bc0 + i * 8), Bg + (size_t)kt * Nd + i * 8);
        asm volatile("cp.async.commit_group;\n");
    }

    int st = 0;
    for (int it = 0; it < niter; it++) {
        asm volatile("cp.async.wait_group 1;\n");
        __syncthreads();

        if (it + 2 < niter) {
            const int ps = (st + 2) % 3;
            const int kt = (it + 2) * BKH;
            #pragma unroll
            for (int i = 0; i < 4; i++)
                cp16(&ASH_(ps, ar, ac0 + i * 8), Ag + kt + i * 8);
            #pragma unroll
            for (int i = 0; i < 4; i++)
                cp16(&BSH_(ps, br, bc0 + i * 8), Bg + (size_t)kt * Nd + i * 8);
        }
        asm volatile("cp.async.commit_group;\n");

        const uint32_t sbase = (uint32_t)__cvta_generic_to_shared(&smh[st * STGH]);

        #pragma unroll
        for (int ks = 0; ks < 4; ks++) {
            const int kb = ks * 16;
            uint32_t af[4][4], bf[2][4];
            #pragma unroll
            for (int mt = 0; mt < 4; mt++) {
                const uint32_t aaddr = sbase +
                    (uint32_t)(((mb + mt * 16 + offm) * APH + kb + offk) * 2);
                ldsm_x4(af[mt], aaddr);
            }
            #pragma unroll
            for (int nt2 = 0; nt2 < 2; nt2++) {
                const uint32_t baddr = sbase + (uint32_t)(ASTGH * 2) +
                    (uint32_t)(((kb + bfr) * BPH + nb + nt2 * 16 + bfc) * 2);
                ldsm_x4_t(bf[nt2], baddr);
            }
            #pragma unroll
            for (int mt = 0; mt < 4; mt++)
                #pragma unroll
                for (int nt = 0; nt < 4; nt++)
                    mma_f16(acc[mt * 4 + nt], af[mt], &bf[nt >> 1][(nt & 1) * 2]);
        }

        st = (st + 1) % 3;
    }

    if (mode == 4) {
        float* xo = (float*)Cout;
        const float* retb = retv + (size_t)(bm / T_) * C_;
        #pragma unroll
        for (int mt = 0; mt < 4; mt++) {
            const int row0 = bm + mb + mt * 16 + r;
            const float2 gA = gates[row0];
            const float2 gB = gates[row0 + 8];
            #pragma unroll
            for (int nt = 0; nt < 4; nt++) {
                const float* a4 = acc[mt * 4 + nt];
                const int col = bn + nb + nt * 8 + c * 2;
                const float2 rv = *(const float2*)(retb + col);
                float* p0 = xo + (size_t)row0 * Nd + col;
                float* p1 = p0 + 8 * (size_t)Nd;
                float2 v0 = *(float2*)p0;
                float2 v1 = *(float2*)p1;
                v0.x += gA.x * a4[0] + gA.y * rv.x;
                v0.y += gA.x * a4[1] + gA.y * rv.y;
                v1.x += gB.x * a4[2] + gB.y * rv.x;
                v1.y += gB.x * a4[3] + gB.y * rv.y;
                *(float2*)p0 = v0;
                *(float2*)p1 = v1;
            }
        }
    } else if (mode == 3) {
        __half* po = (__half*)Cout;
        const int No = Nd >> 1;
        #pragma unroll
        for (int mt = 0; mt < 4; mt++) {
            const int row0 = bm + mb + mt * 16 + r;
            #pragma unroll
            for (int nt = 0; nt < 4; nt++) {
                const float* a4 = acc[mt * 4 + nt];
                const int nout = ((bn + nb + nt * 8) >> 1) + c;
                const float s0 = a4[0] / (1.f + expf(-a4[0]));
                const float s1 = a4[2] / (1.f + expf(-a4[2]));
                po[(size_t)row0 * No + nout]       = __float2half_rn(s0 * a4[1]);
                po[(size_t)(row0 + 8) * No + nout] = __float2half_rn(s1 * a4[3]);
            }
        }
    } else if (mode == 2) {
        __half* po = (__half*)Cout;
        #pragma unroll
        for (int mt = 0; mt < 4; mt++) {
            #pragma unroll
            for (int nt = 0; nt < 4; nt++) {
                const float* a4 = acc[mt * 4 + nt];
                const size_t base = (size_t)(bm + mb + mt * 16 + r) * Nd + bn + nb + nt * 8 + c * 2;
                *(__half2*)(po + base)                  = __floats2half2_rn(a4[0], a4[1]);
                *(__half2*)(po + base + 8 * (size_t)Nd) = __floats2half2_rn(a4[2], a4[3]);
            }
        }
    } else {
        float* po = (float*)Cout;
        #pragma unroll
        for (int mt = 0; mt < 4; mt++) {
            #pragma unroll
            for (int nt = 0; nt < 4; nt++) {
                const float* a4 = acc[mt * 4 + nt];
                float* p0 = po + (size_t)(bm + mb + mt * 16 + r) * Nd + bn + nb + nt * 8 + c * 2;
                float* p1 = p0 + 8 * (size_t)Nd;
                if (mode == 1) {
                    float2 v0 = *(float2*)p0;
                    float2 v1 = *(float2*)p1;
                    v0.x += a4[0]; v0.y += a4[1];
                    v1.x += a4[2]; v1.y += a4[3];
                    *(float2*)p0 = v0;
                    *(float2*)p1 = v1;
                } else {
                    *(float2*)p0 = make_float2(a4[0], a4[1]);
                    *(float2*)p1 = make_float2(a4[2], a4[3]);
                }
            }
        }
    }
    #undef ASH_
    #undef BSH_
}

// ---------------------------------------------------------------------------
// Tensor-core sliding-window attention (unchanged from R11/R12)
// ---------------------------------------------------------------------------
#define AQP 72
#define ASP 324
#define APP 328
#define ATT_SMEM (9216 + 9216 + 82944 + 41984)

__global__ __launch_bounds__(256) void attn_kernel(
    const __half* __restrict__ qkv, __half* __restrict__ o)
{
    extern __shared__ char attsm[];
    __half* Qs = (__half*)attsm;
    __half* KV = (__half*)(attsm + 9216);
    float*  Sf = (float*)(attsm + 18432);
    __half* Ph = (__half*)(attsm + 101376);

    const int q0 = blockIdx.x * 64;
    const int h  = blockIdx.y;
    const int b  = blockIdx.z;
    const int t  = threadIdx.x;
    const int w  = t >> 5, lane = t & 31;
    const int wr = (w & 3) * 16;
    const int wc = (w >> 2) * 32;
    const int offm = (lane & 7) + ((lane >> 3) & 1) * 8;
    const int offk = (lane >> 4) * 8;
    const int bfr = lane & 15, bfc = (lane >> 4) * 8;
    const int r = lane >> 2, cq = lane & 3;
    const float scale = 0.125f;

    const uint32_t qs_b = smem_u32(Qs);
    const uint32_t kv_b = smem_u32(KV);
    const uint32_t ph_b = smem_u32(Ph);

    for (int e = t; e < 512; e += 256) {
        const int row = e >> 3, ch = (e & 7) * 8;
        *(uint4*)&Qs[row * AQP + ch] =
            *(const uint4*)(qkv + ((size_t)(b * T_ + q0 + row)) * (3 * C_) + h * D_ + ch);
    }

    for (int it = 0; it < 5; it++) {
        const int kb = q0 + (it - 4) * 64;
        if (kb < 0) {
            for (int e = t; e < 64 * 64; e += 256)
                Sf[(e >> 6) * ASP + it * 64 + (e & 63)] = -1e30f;
            continue;
        }
        __syncthreads();
        for (int e = t; e < 512; e += 256) {
            const int row = e >> 3, ch = (e & 7) * 8;
            *(uint4*)&KV[row * AQP + ch] =
                *(const uint4*)(qkv + ((size_t)(b * T_ + kb + row)) * (3 * C_) + C_ + h * D_ + ch);
        }
        __syncthreads();

        float acc[4][4];
        #pragma unroll
        for (int i = 0; i < 4; i++)
            #pragma unroll
            for (int j = 0; j < 4; j++) acc[i][j] = 0.f;

        #pragma unroll
        for (int ks = 0; ks < 4; ks++) {
            uint32_t af[4], kfA[4], kfB[4];
            ldsm_x4(af,  qs_b + (uint32_t)(((wr + offm) * AQP + ks * 16 + offk) * 2));
            ldsm_x4(kfA, kv_b + (uint32_t)(((wc + offm) * AQP + ks * 16 + offk) * 2));
            ldsm_x4(kfB, kv_b + (uint32_t)(((wc + 16 + offm) * AQP + ks * 16 + offk) * 2));
            uint32_t b0[2] = {kfA[0], kfA[2]};
            uint32_t b1[2] = {kfA[1], kfA[3]};
            uint32_t b2[2] = {kfB[0], kfB[2]};
            uint32_t b3[2] = {kfB[1], kfB[3]};
            mma_f16(acc[0], af, b0);
            mma_f16(acc[1], af, b1);
            mma_f16(acc[2], af, b2);
            mma_f16(acc[3], af, b3);
        }

        #pragma unroll
        for (int nt = 0; nt < 4; nt++) {
            const int colg = wc + nt * 8 + cq * 2;
            #pragma unroll
            for (int half_ = 0; half_ < 2; half_++) {
                const int rowl = wr + r + half_ * 8;
                const int ig = q0 + rowl;
                #pragma unroll
                for (int jj = 0; jj < 2; jj++) {
                    const int jg = kb + colg + jj;
                    const bool ok = (jg <= ig) && (jg >= ig - (WIN_ - 1));
                    const float v = acc[nt][half_ * 2 + jj];
                    Sf[rowl * ASP + it * 64 + colg + jj] = ok ? v * scale : -1e30f;
                }
            }
        }
    }
    __syncthreads();

    for (int rr = 0; rr < 8; rr++) {
        const int row = w * 8 + rr;
        float m = -1e30f;
        for (int c = lane; c < 320; c += 32) m = fmaxf(m, Sf[row * ASP + c]);
        #pragma unroll
        for (int off = 16; off; off >>= 1) m = fmaxf(m, __shfl_xor_sync(0xffffffffu, m, off));
        float sum = 0.f;
        for (int c = lane; c < 320; c += 32) {
            const float p = expf(Sf[row * ASP + c] - m);
            Sf[row * ASP + c] = p;
            sum += p;
        }
        #pragma unroll
        for (int off = 16; off; off >>= 1) sum += __shfl_xor_sync(0xffffffffu, sum, off);
        const float inv = 1.f / sum;
        for (int c = lane; c < 320; c += 32)
            Ph[row * APP + c] = __float2half_rn(Sf[row * ASP + c] * inv);
    }
    __syncthreads();

    float oacc[4][4];
    #pragma unroll
    for (int i = 0; i < 4; i++)
        #pragma unroll
        for (int j = 0; j < 4; j++) oacc[i][j] = 0.f;

    for (int it = 0; it < 5; it++) {
        const int kb = q0 + (it - 4) * 64;
        if (kb < 0) continue;
        __syncthreads();
        for (int e = t; e < 512; e += 256) {
            const int row = e >> 3, ch = (e & 7) * 8;
            *(uint4*)&KV[row * AQP + ch] =
                *(const uint4*)(qkv + ((size_t)(b * T_ + kb + row)) * (3 * C_) + 2 * C_ + h * D_ + ch);
        }
        __syncthreads();

        #pragma unroll
        for (int ks = 0; ks < 4; ks++) {
            uint32_t af[4], vf[2][4];
            ldsm_x4(af, ph_b + (uint32_t)(((wr + offm) * APP + it * 64 + ks * 16 + offk) * 2));
            #pragma unroll
            for (int nt2 = 0; nt2 < 2; nt2++)
                ldsm_x4_t(vf[nt2],
                    kv_b + (uint32_t)(((ks * 16 + bfr) * AQP + wc + nt2 * 16 + bfc) * 2));
            #pragma unroll
            for (int nt = 0; nt < 4; nt++)
                mma_f16(oacc[nt], af, &vf[nt >> 1][(nt & 1) * 2]);
        }
    }

    #pragma unroll
    for (int nt = 0; nt < 4; nt++) {
        const int col = wc + nt * 8 + cq * 2;
        const float* a4 = oacc[nt];
        __half* p0 = o + ((size_t)(b * T_ + q0 + wr + r)) * C_ + h * D_ + col;
        *(__half2*)p0 = __floats2half2_rn(a4[0], a4[1]);
        *(__half2*)(p0 + 8 * (size_t)C_) = __floats2half2_rn(a4[2], a4[3]);
    }
}

// ---------------------------------------------------------------------------
// Retrieval projection (fp32, tiny)
// ---------------------------------------------------------------------------
__global__ __launch_bounds__(256) void ret_kernel(
    const float* __restrict__ rc, const float* __restrict__ retW, float* __restrict__ ret)
{
    const int c = blockIdx.x * 256 + threadIdx.x;
    const int b = blockIdx.y;
    float acc = 0.f;
    for (int k = 0; k < C_; k++) acc = fmaf(rc[b * C_ + k], retW[(size_t)k * C_ + c], acc);
    ret[b * C_ + c] = acc;
}

// ---------------------------------------------------------------------------
// Launcher
// ---------------------------------------------------------------------------
extern "C" void kernel_launch(void* const* d_in, const int* in_sizes, int n_in,
                              void* d_out, int out_size)
{
    (void)in_sizes; (void)n_in; (void)out_size;
    const float* x    = (const float*)d_in[0];
    const float* rc   = (const float*)d_in[1];
    const float* n1g  = (const float*)d_in[2];
    const float* Wqkv = (const float*)d_in[3];
    const float* Wpro = (const float*)d_in[4];
    const float* gW   = (const float*)d_in[5];
    const float* gb   = (const float*)d_in[6];
    const float* retW = (const float*)d_in[7];
    const float* n2g  = (const float*)d_in[8];
    const float* fgW  = (const float*)d_in[9];
    const float* fuW  = (const float*)d_in[10];
    const float* fdW  = (const float*)d_in[11];
    float* xo = (float*)d_out;

    __half *pH, *pH2, *pQKV, *pO, *pF1h, *pWH;
    float *pR;
    float2 *pG;
    cudaGetSymbolAddress((void**)&pH,   g_h);
    cudaGetSymbolAddress((void**)&pH2,  g_h2);
    cudaGetSymbolAddress((void**)&pQKV, g_qkv);
    cudaGetSymbolAddress((void**)&pO,   g_o);
    cudaGetSymbolAddress((void**)&pF1h, g_f1h);
    cudaGetSymbolAddress((void**)&pR,   g_ret);
    cudaGetSymbolAddress((void**)&pG,   g_gates);
    cudaGetSymbolAddress((void**)&pWH,  g_wh);

    cudaFuncSetAttribute(attn_kernel, cudaFuncAttributeMaxDynamicSharedMemorySize, ATT_SMEM);
    cudaFuncSetAttribute(gemm_f16, cudaFuncAttributeMaxDynamicSharedMemorySize, GEMMH_SMEM);

    // Single fused weight-prep launch (both layers, all matrices)
    prep_weights<<<1184, 256>>>(Wqkv, Wpro, fgW, fuW, fdW, pWH);

    cudaMemcpyAsync(xo, x, sizeof(float) * (size_t)M_ * C_, cudaMemcpyDeviceToDevice);

    for (int l = 0; l < L_; l++) {
        __half* base = pWH + (size_t)l * WH_L;

        rmsnorm_kernel<<<M_, 256>>>(xo, n1g + l * C_, pH);

        gemm_f16<<<dim3(3 * C_ / 128, M_ / 128), 256, GEMMH_SMEM>>>(
            pH, base + WH_QKV, pQKV, 3 * C_, C_, 2, nullptr, nullptr);

        attn_kernel<<<dim3(T_ / 64, H_, B_), 256, ATT_SMEM>>>(pQKV, pO);

        ret_kernel<<<dim3(C_ / 256, B_), 256>>>(rc, retW + (size_t)l * C_ * C_, pR);
        gates_kernel<<<M_ / 8, 256>>>(pH, gW + (size_t)l * C_ * 3, gb + l * 3, pG);

        gemm_f16<<<dim3(C_ / 128, M_ / 128), 256, GEMMH_SMEM>>>(
            pO, base + WH_PROJ, xo, C_, C_, 4, pG, pR);

        rmsnorm_kernel<<<M_, 256>>>(xo, n2g + l * C_, pH2);

        gemm_f16<<<dim3(2 * F_ / 128, M_ / 128), 256, GEMMH_SMEM>>>(
            pH2, base + WH_GU, pF1h, 2 * F_, C_, 3, nullptr, nullptr);

        gemm_f16<<<dim3(C_ / 128, M_ / 128), 256, GEMMH_SMEM>>>(
            pF1h, base + WH_DOWN, xo, C_, F_, 1, nullptr, nullptr);
    }
}